// round 5
// baseline (speedup 1.0000x reference)
#include <cuda_runtime.h>
#include <math.h>

#define BB   128
#define TT   25
#define VV   10000
#define EE   512
#define NFE  2048
#define HH   512
#define MAPS 512
#define IN0  1024   // EE + MAPS
#define NBLK 128    // persistent recurrence grid (must be <= 148 for co-residency)

// ---------------- scratch (device globals; no allocation allowed) ----------------
__device__ float g_p[BB * MAPS];                 // input-layer output
__device__ float g_X0[TT * BB * 1536];           // precomputed x@W (u|r|c) + biases
__device__ float g_h0[2][BB * HH];               // double-buffered layer-0 hidden
__device__ float g_h1[2][BB * HH];               // double-buffered layer-1 hidden
__device__ float g_ur0[BB * 1024];               // layer-0 gates u|r
__device__ float g_ur1[BB * 1024];               // layer-1 gates u|r
__device__ float g_H1[TT * BB * HH];             // all h1_t for logits GEMM
__device__ float g_bur1[1024];                   // packed [bu1 | br1]

// transposed recurrent weights, [n][k] layout for coalesced staging
__device__ float g_WAT[1024 * 512];              // [Wu0_h | Wr0_h]^T   n<1024, k<512
__device__ float g_WBT[512 * 512];               // Wc0 h-part ^T       n<512,  k<512
__device__ float g_WCT[1024 * 1024];             // [Wu1 | Wr1]^T       n<1024, k<1024
__device__ float g_WDT[512 * 1024];              // Wc1 ^T              n<512,  k<1024

// device-wide barrier state: pure store/load, NO atomic RMW (L2 atomic ALU
// serializes per address; 128 spinning RMWs cost ~us each -> 2ms total in R4).
__device__ volatile int g_flags[NBLK];           // per-block arrival epoch
__device__ volatile int g_epoch;                 // released epoch

__device__ __forceinline__ float sigmoidf(float x) { return 1.f / (1.f + expf(-x)); }
__device__ __forceinline__ float4 ldcg4(const float* p) {
    return __ldcg(reinterpret_cast<const float4*>(p));
}

__device__ __forceinline__ void gbar(int e) {
    __syncthreads();
    if (blockIdx.x == 0) {
        // threads 1..127 each watch exactly one peer block's flag (pure loads)
        if (threadIdx.x > 0 && threadIdx.x < NBLK) {
            while (g_flags[threadIdx.x] < e) { }
        }
        __syncthreads();
        if (threadIdx.x == 0) {
            __threadfence();
            g_epoch = e;                          // release
        }
    } else {
        if (threadIdx.x == 0) {
            __threadfence();                      // publish this block's writes
            g_flags[blockIdx.x] = e;              // arrive (single STG)
            while (g_epoch < e) { }               // wait (pure loads, L2 broadcast)
            __threadfence();
        }
    }
    __syncthreads();
}

// ---------------- pack: transpose recurrent weights + bias pack + barrier reset ----------------
__global__ void k_pack(const float* __restrict__ Wu0, const float* __restrict__ Wr0,
                       const float* __restrict__ Wc0,
                       const float* __restrict__ Wu1, const float* __restrict__ Wr1,
                       const float* __restrict__ Wc1,
                       const float* __restrict__ bu1, const float* __restrict__ br1) {
    long long i = (long long)blockIdx.x * blockDim.x + threadIdx.x;
    if (i < NBLK) g_flags[i] = 0;
    if (i == 0) g_epoch = 0;
    // WAT: 1024x512  (h-part of Wu0|Wr0: rows IN0..IN0+511 of W[(H+IN0) x H])
    if (i < 1024LL * 512) {
        int n = (int)(i >> 9), k = (int)(i & 511);
        g_WAT[i] = (n < 512) ? Wu0[(IN0 + k) * HH + n] : Wr0[(IN0 + k) * HH + (n - 512)];
        return;
    }
    i -= 1024LL * 512;
    // WBT: 512x512 (Wc0 rows 0..511 = r*h part)
    if (i < 512LL * 512) {
        int n = (int)(i >> 9), k = (int)(i & 511);
        g_WBT[i] = Wc0[k * HH + n];
        return;
    }
    i -= 512LL * 512;
    // WCT: 1024x1024 ([Wu1|Wr1], K=1024)
    if (i < 1024LL * 1024) {
        int n = (int)(i >> 10), k = (int)(i & 1023);
        g_WCT[i] = (n < 512) ? Wu1[k * HH + n] : Wr1[k * HH + (n - 512)];
        return;
    }
    i -= 1024LL * 1024;
    // WDT: 512x1024 (Wc1, K=1024)
    if (i < 512LL * 1024) {
        int n = (int)(i >> 10), k = (int)(i & 1023);
        g_WDT[i] = Wc1[k * HH + n];
        return;
    }
    i -= 512LL * 1024;
    if (i < 1024) g_bur1[i] = (i < 512) ? bu1[i] : br1[i - 512];
}

// ---------------- input layer GEMM ----------------
template <int K, typename Op>
__global__ void __launch_bounds__(256) small_gemm(Op op) {
    __shared__ float As[32][33];
    __shared__ float Bs[32][33];
    const int tid = threadIdx.x;
    const int r0 = tid >> 4;
    const int c0 = tid & 15;
    const int mBase = blockIdx.y * 32;
    const int nBase = blockIdx.x * 32;

    float a00 = 0.f, a01 = 0.f, a10 = 0.f, a11 = 0.f;

    for (int k0 = 0; k0 < K; k0 += 32) {
#pragma unroll
        for (int i = 0; i < 4; i++) {
            int e = tid + i * 256;
            int r = e >> 5, kk = e & 31;
            As[r][kk] = op.loadA(mBase + r, k0 + kk);
        }
#pragma unroll
        for (int i = 0; i < 4; i++) {
            int e = tid + i * 256;
            int kk = e >> 5, n = e & 31;
            Bs[kk][n] = op.loadB(k0 + kk, nBase + n);
        }
        __syncthreads();
#pragma unroll
        for (int kk = 0; kk < 32; kk++) {
            float x0 = As[r0][kk],      x1 = As[r0 + 16][kk];
            float y0 = Bs[kk][c0],      y1 = Bs[kk][c0 + 16];
            a00 += x0 * y0; a01 += x0 * y1;
            a10 += x1 * y0; a11 += x1 * y1;
        }
        __syncthreads();
    }
    op.store(mBase + r0,      nBase + c0,      a00);
    op.store(mBase + r0,      nBase + c0 + 16, a01);
    op.store(mBase + r0 + 16, nBase + c0,      a10);
    op.store(mBase + r0 + 16, nBase + c0 + 16, a11);
}

struct OpP {  // p = leaky_relu(cnn @ Win + bin)
    const float* A; const float* Bw; const float* bias;
    __device__ float loadA(int r, int k) const { return A[r * NFE + k]; }
    __device__ float loadB(int k, int n) const { return Bw[k * MAPS + n]; }
    __device__ void store(int r, int n, float acc) const {
        float v = acc + bias[n];
        g_p[r * MAPS + n] = v > 0.f ? v : 0.01f * v;
    }
};

// ---------------- persistent recurrence ----------------
template <int PH, int COLS, int KTOT>
__device__ __forceinline__ void run_phase(
    float As[32][129], float Bs[8][36], int t,
    const float* h0c, float* h0n, const float* h1c, float* h1n,
    const float* __restrict__ bc1)
{
    const int tid = threadIdx.x, blk = blockIdx.x;
    const int w = tid >> 5, lane = tid & 31;
    const int row = ((w & 3) << 5) + lane;
    constexpr int CW = COLS / 2;
    const int cb = blk * COLS;
    const int cwl = CW * (w >> 2);          // local col base within block
    const int cg = cb + cwl;                // global col base for this warp

    const int rA = tid >> 1;                // staging row 0..127
    const int kg = (tid & 1) * 16;          // staging k offset within chunk

    const float* WT = (PH == 0) ? g_WAT : (PH == 1) ? g_WBT : (PH == 2) ? g_WCT : g_WDT;

    float acc[CW];
#pragma unroll
    for (int j = 0; j < CW; j++) acc[j] = 0.f;

    float4 va[4];
    float4 vb;

    auto loadA = [&](int ka) -> float4 {
        if (PH == 0) {
            return ldcg4(h0c + rA * HH + ka);
        } else if (PH == 1) {
            float4 u = ldcg4(g_ur0 + rA * 1024 + 512 + ka);
            float4 h = ldcg4(h0c + rA * HH + ka);
            return make_float4(u.x * h.x, u.y * h.y, u.z * h.z, u.w * h.w);
        } else if (PH == 2) {
            return (ka < 512) ? ldcg4(h0n + rA * HH + ka)
                              : ldcg4(h1c + rA * HH + (ka - 512));
        } else {
            if (ka < 512) {
                float4 u = ldcg4(g_ur1 + rA * 1024 + 512 + ka);
                float4 h = ldcg4(h1c + rA * HH + ka);
                return make_float4(u.x * h.x, u.y * h.y, u.z * h.z, u.w * h.w);
            }
            return ldcg4(h0n + rA * HH + (ka - 512));
        }
    };

    // prefetch chunk 0
#pragma unroll
    for (int j2 = 0; j2 < 4; j2++) va[j2] = loadA(kg + j2 * 4);
    if (tid < COLS * 8) {
        int c = tid >> 3, kk4 = (tid & 7) * 4;
        vb = *reinterpret_cast<const float4*>(WT + (cb + c) * KTOT + kk4);
    }

    for (int k0 = 0; k0 < KTOT; k0 += 32) {
#pragma unroll
        for (int j2 = 0; j2 < 4; j2++) {
            int kk = kg + j2 * 4;
            As[kk][rA]     = va[j2].x;
            As[kk + 1][rA] = va[j2].y;
            As[kk + 2][rA] = va[j2].z;
            As[kk + 3][rA] = va[j2].w;
        }
        if (tid < COLS * 8) {
            int c = tid >> 3, kk4 = (tid & 7) * 4;
            *reinterpret_cast<float4*>(&Bs[c][kk4]) = vb;
        }
        __syncthreads();

        if (k0 + 32 < KTOT) {
#pragma unroll
            for (int j2 = 0; j2 < 4; j2++) va[j2] = loadA(k0 + 32 + kg + j2 * 4);
            if (tid < COLS * 8) {
                int c = tid >> 3, kk4 = (tid & 7) * 4;
                vb = *reinterpret_cast<const float4*>(WT + (cb + c) * KTOT + k0 + 32 + kk4);
            }
        }

#pragma unroll
        for (int kk = 0; kk < 32; kk += 2) {
            float a0 = As[kk][row];
            float a1 = As[kk + 1][row];
#pragma unroll
            for (int j = 0; j < CW; j++) {
                float2 b = *reinterpret_cast<const float2*>(&Bs[cwl + j][kk]);
                acc[j] = fmaf(a0, b.x, fmaf(a1, b.y, acc[j]));
            }
        }
        __syncthreads();
    }

    // ---- epilogues ----
    if (PH == 0) {        // ur0 = sigmoid(acc + X0[u|r])
        const float* x = g_X0 + (t * BB + row) * 1536 + cg;
        float4 o;
        o.x = sigmoidf(acc[0] + x[0]);
        o.y = sigmoidf(acc[1] + x[1]);
        o.z = sigmoidf(acc[2] + x[2]);
        o.w = sigmoidf(acc[3] + x[3]);
        *reinterpret_cast<float4*>(g_ur0 + row * 1024 + cg) = o;
    } else if (PH == 1) { // h0' = u*h0 + (1-u)*tanh(acc + X0[c])
        const float* x = g_X0 + (t * BB + row) * 1536 + 1024 + cg;
        float u0 = __ldcg(g_ur0 + row * 1024 + cg);
        float u1 = __ldcg(g_ur0 + row * 1024 + cg + 1);
        float p0 = __ldcg(h0c + row * HH + cg);
        float p1 = __ldcg(h0c + row * HH + cg + 1);
        float hh0 = tanhf(acc[0] + x[0]);
        float hh1 = tanhf(acc[1] + x[1]);
        float2 o;
        o.x = u0 * p0 + (1.f - u0) * hh0;
        o.y = u1 * p1 + (1.f - u1) * hh1;
        *reinterpret_cast<float2*>(h0n + row * HH + cg) = o;
    } else if (PH == 2) { // ur1 = sigmoid(acc + bur1)
        float4 o;
        o.x = sigmoidf(acc[0] + g_bur1[cg]);
        o.y = sigmoidf(acc[1] + g_bur1[cg + 1]);
        o.z = sigmoidf(acc[2] + g_bur1[cg + 2]);
        o.w = sigmoidf(acc[3] + g_bur1[cg + 3]);
        *reinterpret_cast<float4*>(g_ur1 + row * 1024 + cg) = o;
    } else {              // h1' = u*h1 + (1-u)*tanh(acc + bc1); also H1[t]
        float u0 = __ldcg(g_ur1 + row * 1024 + cg);
        float u1 = __ldcg(g_ur1 + row * 1024 + cg + 1);
        float p0 = __ldcg(h1c + row * HH + cg);
        float p1 = __ldcg(h1c + row * HH + cg + 1);
        float hh0 = tanhf(acc[0] + bc1[cg]);
        float hh1 = tanhf(acc[1] + bc1[cg + 1]);
        float2 o;
        o.x = u0 * p0 + (1.f - u0) * hh0;
        o.y = u1 * p1 + (1.f - u1) * hh1;
        *reinterpret_cast<float2*>(h1n + row * HH + cg) = o;
        *reinterpret_cast<float2*>(g_H1 + (t * BB + row) * HH + cg) = o;
    }
}

__global__ void __launch_bounds__(256, 1) k_recurrence(const float* __restrict__ bc1) {
    __shared__ float As[32][129];
    __shared__ float Bs[8][36];
    const int tid = threadIdx.x, blk = blockIdx.x;
    int ep = 0;

    // zero initial states (buffer 0)
    {
        int idx = blk * 256 + tid;            // 0..32767
        g_h0[0][idx] = 0.f; g_h0[0][idx + 32768] = 0.f;
        g_h1[0][idx] = 0.f; g_h1[0][idx + 32768] = 0.f;
    }
    gbar(++ep);

    for (int t = 0; t < TT; t++) {
        const int cur = t & 1;
        const float* h0c = g_h0[cur];
        float*       h0n = g_h0[cur ^ 1];
        const float* h1c = g_h1[cur];
        float*       h1n = g_h1[cur ^ 1];

        run_phase<0, 8,  512>(As, Bs, t, h0c, h0n, h1c, h1n, bc1);  // ur0
        gbar(++ep);
        run_phase<1, 4,  512>(As, Bs, t, h0c, h0n, h1c, h1n, bc1);  // h0'
        gbar(++ep);
        run_phase<2, 8, 1024>(As, Bs, t, h0c, h0n, h1c, h1n, bc1);  // ur1
        gbar(++ep);
        run_phase<3, 4, 1024>(As, Bs, t, h0c, h0n, h1c, h1n, bc1);  // h1'
        if (t != TT - 1) gbar(++ep);          // stream order covers the final step
    }
}

// ---------------- precompute X0 = [x@Wu0_x | x@Wr0_x | x@Wc0_x] + biases ----------------
__global__ void __launch_bounds__(256) k_precompute(
    const int* __restrict__ tokens, const float* __restrict__ emb,
    const float* __restrict__ Wu0, const float* __restrict__ Wr0, const float* __restrict__ Wc0,
    const float* __restrict__ bu0, const float* __restrict__ br0, const float* __restrict__ bc0)
{
    __shared__ float As[64][17];
    __shared__ float Bs[16][64];
    const int tid = threadIdx.x;
    const int mBase = blockIdx.y * 64;
    const int nBase = blockIdx.x * 64;
    const int region = nBase >> 9;                   // 0:u, 1:r, 2:c
    const float* Bw   = (region == 0) ? Wu0 : (region == 1) ? Wr0 : Wc0;
    const float* bias = (region == 0) ? bu0 : (region == 1) ? br0 : bc0;
    const int row0 = (region == 2) ? 512 : 0;        // x-part of Wc0 = rows 512..1535
    const int nOff = nBase - region * 512;

    const int r0 = tid >> 4, c0 = tid & 15;
    const int rl = tid >> 4, kl = tid & 15;
    int tok[4]; int bidx[4];
#pragma unroll
    for (int i = 0; i < 4; i++) {
        int m = mBase + rl + 16 * i;
        bidx[i] = m & 127;
        tok[i] = tokens[bidx[i] * TT + (m >> 7)];
    }

    float acc[4][4];
#pragma unroll
    for (int i = 0; i < 4; i++)
#pragma unroll
        for (int j = 0; j < 4; j++) acc[i][j] = 0.f;

    for (int k0 = 0; k0 < IN0; k0 += 16) {
        int kabs = k0 + kl;
#pragma unroll
        for (int i = 0; i < 4; i++) {
            float v = (kabs < 512) ? emb[(size_t)tok[i] * EE + kabs]
                                   : g_p[bidx[i] * MAPS + (kabs - 512)];
            As[rl + 16 * i][kl] = v;
        }
#pragma unroll
        for (int i = 0; i < 4; i++) {
            int e = tid + i * 256;
            int kk = e >> 6, n = e & 63;
            Bs[kk][n] = Bw[(row0 + k0 + kk) * HH + nOff + n];
        }
        __syncthreads();
#pragma unroll
        for (int kk = 0; kk < 16; kk++) {
            float a0 = As[r0][kk], a1 = As[r0 + 16][kk], a2 = As[r0 + 32][kk], a3 = As[r0 + 48][kk];
            float b0 = Bs[kk][c0], b1 = Bs[kk][c0 + 16], b2 = Bs[kk][c0 + 32], b3 = Bs[kk][c0 + 48];
            acc[0][0] += a0 * b0; acc[0][1] += a0 * b1; acc[0][2] += a0 * b2; acc[0][3] += a0 * b3;
            acc[1][0] += a1 * b0; acc[1][1] += a1 * b1; acc[1][2] += a1 * b2; acc[1][3] += a1 * b3;
            acc[2][0] += a2 * b0; acc[2][1] += a2 * b1; acc[2][2] += a2 * b2; acc[2][3] += a2 * b3;
            acc[3][0] += a3 * b0; acc[3][1] += a3 * b1; acc[3][2] += a3 * b2; acc[3][3] += a3 * b3;
        }
        __syncthreads();
    }
#pragma unroll
    for (int i = 0; i < 4; i++) {
        int m = mBase + r0 + 16 * i;
#pragma unroll
        for (int j = 0; j < 4; j++) {
            int nl = nOff + c0 + 16 * j;
            g_X0[m * 1536 + nBase + c0 + 16 * j] = acc[i][j] + bias[nl];
        }
    }
}

// ---------------- logits = H1_all @ Wout + bout ; out[b][t][v] ----------------
__global__ void __launch_bounds__(256) k_logits(const float* __restrict__ Wout,
                                                const float* __restrict__ bout,
                                                float* __restrict__ out)
{
    __shared__ float As[64][17];
    __shared__ float Bs[16][64];
    const int tid = threadIdx.x;
    const int mBase = blockIdx.y * 64;
    const int nBase = blockIdx.x * 64;
    const int r0 = tid >> 4, c0 = tid & 15;
    const int rl = tid >> 4, kl = tid & 15;

    float acc[4][4];
#pragma unroll
    for (int i = 0; i < 4; i++)
#pragma unroll
        for (int j = 0; j < 4; j++) acc[i][j] = 0.f;

    for (int k0 = 0; k0 < HH; k0 += 16) {
#pragma unroll
        for (int i = 0; i < 4; i++)
            As[rl + 16 * i][kl] = g_H1[(mBase + rl + 16 * i) * HH + k0 + kl];
#pragma unroll
        for (int i = 0; i < 4; i++) {
            int e = tid + i * 256;
            int kk = e >> 6, n = e & 63;
            int col = nBase + n;
            Bs[kk][n] = (col < VV) ? Wout[(k0 + kk) * VV + col] : 0.f;
        }
        __syncthreads();
#pragma unroll
        for (int kk = 0; kk < 16; kk++) {
            float a0 = As[r0][kk], a1 = As[r0 + 16][kk], a2 = As[r0 + 32][kk], a3 = As[r0 + 48][kk];
            float b0 = Bs[kk][c0], b1 = Bs[kk][c0 + 16], b2 = Bs[kk][c0 + 32], b3 = Bs[kk][c0 + 48];
            acc[0][0] += a0 * b0; acc[0][1] += a0 * b1; acc[0][2] += a0 * b2; acc[0][3] += a0 * b3;
            acc[1][0] += a1 * b0; acc[1][1] += a1 * b1; acc[1][2] += a1 * b2; acc[1][3] += a1 * b3;
            acc[2][0] += a2 * b0; acc[2][1] += a2 * b1; acc[2][2] += a2 * b2; acc[2][3] += a2 * b3;
            acc[3][0] += a3 * b0; acc[3][1] += a3 * b1; acc[3][2] += a3 * b2; acc[3][3] += a3 * b3;
        }
        __syncthreads();
    }
#pragma unroll
    for (int i = 0; i < 4; i++) {
        int m = mBase + r0 + 16 * i;
        int tIdx = m >> 7, b = m & 127;
        size_t rowOff = ((size_t)b * TT + tIdx) * VV;
#pragma unroll
        for (int j = 0; j < 4; j++) {
            int col = nBase + c0 + 16 * j;
            if (col < VV) out[rowOff + col] = acc[i][j] + bout[col];
        }
    }
}

__global__ void k_hidden(float* __restrict__ outh) {
    int i = blockIdx.x * blockDim.x + threadIdx.x;
    if (i < BB * HH) {
        outh[i]           = g_h0[1][i];   // after 25 steps final state is buffer 1
        outh[BB * HH + i] = g_h1[1][i];
    }
}

// ---------------- launch ----------------
extern "C" void kernel_launch(void* const* d_in, const int* in_sizes, int n_in,
                              void* d_out, int out_size) {
    const int*   tokens = (const int*)d_in[0];     // int32 (JAX x64 disabled)
    const float* cnn  = (const float*)d_in[1];
    const float* emb  = (const float*)d_in[2];
    const float* Win  = (const float*)d_in[3];
    const float* bin  = (const float*)d_in[4];
    const float* Wout = (const float*)d_in[5];
    const float* bout = (const float*)d_in[6];
    const float* Wu0  = (const float*)d_in[7];
    const float* bu0  = (const float*)d_in[8];
    const float* Wr0  = (const float*)d_in[9];
    const float* br0  = (const float*)d_in[10];
    const float* Wc0  = (const float*)d_in[11];
    const float* bc0  = (const float*)d_in[12];
    const float* Wu1  = (const float*)d_in[13];
    const float* bu1  = (const float*)d_in[14];
    const float* Wr1  = (const float*)d_in[15];
    const float* br1  = (const float*)d_in[16];
    const float* Wc1  = (const float*)d_in[17];
    const float* bc1  = (const float*)d_in[18];
    float* out = (float*)d_out;

    long long packN = 1024LL*512 + 512LL*512 + 1024LL*1024 + 512LL*1024 + 1024;
    k_pack<<<(int)((packN + 255) / 256), 256>>>(Wu0, Wr0, Wc0, Wu1, Wr1, Wc1, bu1, br1);

    // input layer: p = leaky_relu(cnn @ Win + bin)
    small_gemm<NFE, OpP><<<dim3(MAPS / 32, BB / 32), 256>>>(OpP{cnn, Win, bin});

    // precompute x-dependent GRU0 terms for all timesteps
    k_precompute<<<dim3(1536 / 64, (TT * BB) / 64), 256>>>(tokens, emb, Wu0, Wr0, Wc0, bu0, br0, bc0);

    // whole 25-step recurrence in ONE persistent kernel
    k_recurrence<<<NBLK, 256>>>(bc1);

    // logits: [3200,512] x [512,10000] + bias -> [B,T,V]
    k_logits<<<dim3((VV + 63) / 64, (TT * BB) / 64), 256>>>(Wout, bout, out);

    // hidden [2,B,H]
    k_hidden<<<(BB * HH + 255) / 256, 256>>>(out + (size_t)BB * TT * VV);
}

// round 6
// speedup vs baseline: 1.1563x; 1.1563x over previous
#include <cuda_runtime.h>
#include <math.h>

#define BB   128
#define TT   25
#define VV   10000
#define EE   512
#define NFE  2048
#define HH   512
#define MAPS 512
#define IN0  1024   // EE + MAPS
#define NBLK 128    // persistent recurrence grid (<=148 for co-residency)

// ---------------- scratch (device globals; no allocation allowed) ----------------
__device__ float g_p[BB * MAPS];
__device__ float g_X0[TT * BB * 1536];
__device__ float g_h0[2][BB * HH];
__device__ float g_h1[2][BB * HH];
__device__ float g_ur0[BB * 1024];
__device__ float g_ur1[BB * 1024];
__device__ float g_H1[TT * BB * HH];
__device__ float g_bur1[1024];

// transposed recurrent weights, [n][k] layout
__device__ float g_WAT[1024 * 512];
__device__ float g_WBT[512 * 512];
__device__ float g_WCT[1024 * 1024];
__device__ float g_WDT[512 * 1024];

// store/load flag barrier (no atomic RMW)
__device__ volatile int g_flags[NBLK];
__device__ volatile int g_epoch;

__device__ __forceinline__ float sigmoidf(float x) { return 1.f / (1.f + expf(-x)); }
__device__ __forceinline__ float4 ldcg4(const float* p) {
    return __ldcg(reinterpret_cast<const float4*>(p));
}

__device__ __forceinline__ void gbar(int e) {
    __syncthreads();
    if (blockIdx.x == 0) {
        if (threadIdx.x > 0 && threadIdx.x < NBLK) {
            while (g_flags[threadIdx.x] < e) { }
        }
        __syncthreads();
        if (threadIdx.x == 0) {
            __threadfence();
            g_epoch = e;
        }
    } else {
        if (threadIdx.x == 0) {
            __threadfence();
            g_flags[blockIdx.x] = e;
            while (g_epoch < e) { }
            __threadfence();
        }
    }
    __syncthreads();
}

// ---------------- pack ----------------
__global__ void k_pack(const float* __restrict__ Wu0, const float* __restrict__ Wr0,
                       const float* __restrict__ Wc0,
                       const float* __restrict__ Wu1, const float* __restrict__ Wr1,
                       const float* __restrict__ Wc1,
                       const float* __restrict__ bu1, const float* __restrict__ br1) {
    long long i = (long long)blockIdx.x * blockDim.x + threadIdx.x;
    if (i < NBLK) g_flags[i] = 0;
    if (i == 0) g_epoch = 0;
    if (i < 1024LL * 512) {
        int n = (int)(i >> 9), k = (int)(i & 511);
        g_WAT[i] = (n < 512) ? Wu0[(IN0 + k) * HH + n] : Wr0[(IN0 + k) * HH + (n - 512)];
        return;
    }
    i -= 1024LL * 512;
    if (i < 512LL * 512) {
        int n = (int)(i >> 9), k = (int)(i & 511);
        g_WBT[i] = Wc0[k * HH + n];
        return;
    }
    i -= 512LL * 512;
    if (i < 1024LL * 1024) {
        int n = (int)(i >> 10), k = (int)(i & 1023);
        g_WCT[i] = (n < 512) ? Wu1[k * HH + n] : Wr1[k * HH + (n - 512)];
        return;
    }
    i -= 1024LL * 1024;
    if (i < 512LL * 1024) {
        int n = (int)(i >> 10), k = (int)(i & 1023);
        g_WDT[i] = Wc1[k * HH + n];
        return;
    }
    i -= 512LL * 1024;
    if (i < 1024) g_bur1[i] = (i < 512) ? bu1[i] : br1[i - 512];
}

// ---------------- input layer GEMM ----------------
template <int K, typename Op>
__global__ void __launch_bounds__(256) small_gemm(Op op) {
    __shared__ float As[32][33];
    __shared__ float Bs[32][33];
    const int tid = threadIdx.x;
    const int r0 = tid >> 4;
    const int c0 = tid & 15;
    const int mBase = blockIdx.y * 32;
    const int nBase = blockIdx.x * 32;

    float a00 = 0.f, a01 = 0.f, a10 = 0.f, a11 = 0.f;

    for (int k0 = 0; k0 < K; k0 += 32) {
#pragma unroll
        for (int i = 0; i < 4; i++) {
            int e = tid + i * 256;
            int r = e >> 5, kk = e & 31;
            As[r][kk] = op.loadA(mBase + r, k0 + kk);
        }
#pragma unroll
        for (int i = 0; i < 4; i++) {
            int e = tid + i * 256;
            int kk = e >> 5, n = e & 31;
            Bs[kk][n] = op.loadB(k0 + kk, nBase + n);
        }
        __syncthreads();
#pragma unroll
        for (int kk = 0; kk < 32; kk++) {
            float x0 = As[r0][kk],      x1 = As[r0 + 16][kk];
            float y0 = Bs[kk][c0],      y1 = Bs[kk][c0 + 16];
            a00 += x0 * y0; a01 += x0 * y1;
            a10 += x1 * y0; a11 += x1 * y1;
        }
        __syncthreads();
    }
    op.store(mBase + r0,      nBase + c0,      a00);
    op.store(mBase + r0,      nBase + c0 + 16, a01);
    op.store(mBase + r0 + 16, nBase + c0,      a10);
    op.store(mBase + r0 + 16, nBase + c0 + 16, a11);
}

struct OpP {
    const float* A; const float* Bw; const float* bias;
    __device__ float loadA(int r, int k) const { return A[r * NFE + k]; }
    __device__ float loadB(int k, int n) const { return Bw[k * MAPS + n]; }
    __device__ void store(int r, int n, float acc) const {
        float v = acc + bias[n];
        g_p[r * MAPS + n] = v > 0.f ? v : 0.01f * v;
    }
};

// ---------------- persistent recurrence ----------------
// COALESCED staging: thread loads linear elem L = tid + i*256 of the 128x32 chunk,
// row = L>>3, col4 = (L&7)*4 -> warp = 4 dense rows x 128B. Commit to As[col][row]
// stays conflict-free with the 129 pad (bank = col + row mod 32, distinct per warp).
template <int PH, int COLS, int KTOT>
__device__ __forceinline__ void run_phase(
    float As[32][129], float Bs[8][36], int t,
    const float* h0c, float* h0n, const float* h1c, float* h1n,
    const float* __restrict__ bc1)
{
    const int tid = threadIdx.x, blk = blockIdx.x;
    const int w = tid >> 5, lane = tid & 31;
    const int crow = ((w & 3) << 5) + lane;      // compute row
    constexpr int CW = COLS / 2;
    const int cb = blk * COLS;
    const int cwl = CW * (w >> 2);
    const int cg = cb + cwl;

    const float* WT = (PH == 0) ? g_WAT : (PH == 1) ? g_WBT : (PH == 2) ? g_WCT : g_WDT;

    float acc[CW];
#pragma unroll
    for (int j = 0; j < CW; j++) acc[j] = 0.f;

    float4 va[4];
    float4 vb;

    auto loadA4 = [&](int r, int ka) -> float4 {
        if (PH == 0) {
            return ldcg4(h0c + r * HH + ka);
        } else if (PH == 1) {
            float4 u = ldcg4(g_ur0 + r * 1024 + 512 + ka);
            float4 h = ldcg4(h0c + r * HH + ka);
            return make_float4(u.x * h.x, u.y * h.y, u.z * h.z, u.w * h.w);
        } else if (PH == 2) {
            return (ka < 512) ? ldcg4(h0n + r * HH + ka)
                              : ldcg4(h1c + r * HH + (ka - 512));
        } else {
            if (ka < 512) {
                float4 u = ldcg4(g_ur1 + r * 1024 + 512 + ka);
                float4 h = ldcg4(h1c + r * HH + ka);
                return make_float4(u.x * h.x, u.y * h.y, u.z * h.z, u.w * h.w);
            }
            return ldcg4(h0n + r * HH + (ka - 512));
        }
    };

    // prefetch chunk 0
#pragma unroll
    for (int i = 0; i < 4; i++) {
        int L = tid + i * 256;
        va[i] = loadA4(L >> 3, (L & 7) << 2);
    }
    if (tid < COLS * 8) {
        int c = tid >> 3, kk4 = (tid & 7) * 4;
        vb = *reinterpret_cast<const float4*>(WT + (cb + c) * KTOT + kk4);
    }

    for (int k0 = 0; k0 < KTOT; k0 += 32) {
        // commit prefetched regs to smem (conflict-free scatter)
#pragma unroll
        for (int i = 0; i < 4; i++) {
            int L = tid + i * 256;
            int r = L >> 3, c4 = (L & 7) << 2;
            As[c4][r]     = va[i].x;
            As[c4 + 1][r] = va[i].y;
            As[c4 + 2][r] = va[i].z;
            As[c4 + 3][r] = va[i].w;
        }
        if (tid < COLS * 8) {
            int c = tid >> 3, kk4 = (tid & 7) * 4;
            *reinterpret_cast<float4*>(&Bs[c][kk4]) = vb;
        }
        __syncthreads();

        // prefetch next chunk while computing
        if (k0 + 32 < KTOT) {
#pragma unroll
            for (int i = 0; i < 4; i++) {
                int L = tid + i * 256;
                va[i] = loadA4(L >> 3, k0 + 32 + ((L & 7) << 2));
            }
            if (tid < COLS * 8) {
                int c = tid >> 3, kk4 = (tid & 7) * 4;
                vb = *reinterpret_cast<const float4*>(WT + (cb + c) * KTOT + k0 + 32 + kk4);
            }
        }

#pragma unroll
        for (int kk = 0; kk < 32; kk += 2) {
            float a0 = As[kk][crow];
            float a1 = As[kk + 1][crow];
#pragma unroll
            for (int j = 0; j < CW; j++) {
                float2 b = *reinterpret_cast<const float2*>(&Bs[cwl + j][kk]);
                acc[j] = fmaf(a0, b.x, fmaf(a1, b.y, acc[j]));
            }
        }
        __syncthreads();
    }

    // ---- epilogues ----
    if (PH == 0) {
        const float* x = g_X0 + (t * BB + crow) * 1536 + cg;
        float4 o;
        o.x = sigmoidf(acc[0] + x[0]);
        o.y = sigmoidf(acc[1] + x[1]);
        o.z = sigmoidf(acc[2] + x[2]);
        o.w = sigmoidf(acc[3] + x[3]);
        *reinterpret_cast<float4*>(g_ur0 + crow * 1024 + cg) = o;
    } else if (PH == 1) {
        const float* x = g_X0 + (t * BB + crow) * 1536 + 1024 + cg;
        float u0 = __ldcg(g_ur0 + crow * 1024 + cg);
        float u1 = __ldcg(g_ur0 + crow * 1024 + cg + 1);
        float p0 = __ldcg(h0c + crow * HH + cg);
        float p1 = __ldcg(h0c + crow * HH + cg + 1);
        float hh0 = tanhf(acc[0] + x[0]);
        float hh1 = tanhf(acc[1] + x[1]);
        float2 o;
        o.x = u0 * p0 + (1.f - u0) * hh0;
        o.y = u1 * p1 + (1.f - u1) * hh1;
        *reinterpret_cast<float2*>(h0n + crow * HH + cg) = o;
    } else if (PH == 2) {
        float4 o;
        o.x = sigmoidf(acc[0] + g_bur1[cg]);
        o.y = sigmoidf(acc[1] + g_bur1[cg + 1]);
        o.z = sigmoidf(acc[2] + g_bur1[cg + 2]);
        o.w = sigmoidf(acc[3] + g_bur1[cg + 3]);
        *reinterpret_cast<float4*>(g_ur1 + crow * 1024 + cg) = o;
    } else {
        float u0 = __ldcg(g_ur1 + crow * 1024 + cg);
        float u1 = __ldcg(g_ur1 + crow * 1024 + cg + 1);
        float p0 = __ldcg(h1c + crow * HH + cg);
        float p1 = __ldcg(h1c + crow * HH + cg + 1);
        float hh0 = tanhf(acc[0] + bc1[cg]);
        float hh1 = tanhf(acc[1] + bc1[cg + 1]);
        float2 o;
        o.x = u0 * p0 + (1.f - u0) * hh0;
        o.y = u1 * p1 + (1.f - u1) * hh1;
        *reinterpret_cast<float2*>(h1n + crow * HH + cg) = o;
        *reinterpret_cast<float2*>(g_H1 + (t * BB + crow) * HH + cg) = o;
    }
}

__global__ void __launch_bounds__(256, 1) k_recurrence(const float* __restrict__ bc1) {
    __shared__ float As[32][129];
    __shared__ float Bs[8][36];
    const int tid = threadIdx.x, blk = blockIdx.x;
    int ep = 0;

    {
        int idx = blk * 256 + tid;
        g_h0[0][idx] = 0.f; g_h0[0][idx + 32768] = 0.f;
        g_h1[0][idx] = 0.f; g_h1[0][idx + 32768] = 0.f;
    }
    gbar(++ep);

    for (int t = 0; t < TT; t++) {
        const int cur = t & 1;
        const float* h0c = g_h0[cur];
        float*       h0n = g_h0[cur ^ 1];
        const float* h1c = g_h1[cur];
        float*       h1n = g_h1[cur ^ 1];

        run_phase<0, 8,  512>(As, Bs, t, h0c, h0n, h1c, h1n, bc1);  // ur0
        gbar(++ep);
        run_phase<1, 4,  512>(As, Bs, t, h0c, h0n, h1c, h1n, bc1);  // h0'
        gbar(++ep);
        run_phase<2, 8, 1024>(As, Bs, t, h0c, h0n, h1c, h1n, bc1);  // ur1
        gbar(++ep);
        run_phase<3, 4, 1024>(As, Bs, t, h0c, h0n, h1c, h1n, bc1);  // h1'
        if (t != TT - 1) gbar(++ep);
    }
}

// ---------------- precompute X0 ----------------
__global__ void __launch_bounds__(256) k_precompute(
    const int* __restrict__ tokens, const float* __restrict__ emb,
    const float* __restrict__ Wu0, const float* __restrict__ Wr0, const float* __restrict__ Wc0,
    const float* __restrict__ bu0, const float* __restrict__ br0, const float* __restrict__ bc0)
{
    __shared__ float As[64][17];
    __shared__ float Bs[16][64];
    const int tid = threadIdx.x;
    const int mBase = blockIdx.y * 64;
    const int nBase = blockIdx.x * 64;
    const int region = nBase >> 9;
    const float* Bw   = (region == 0) ? Wu0 : (region == 1) ? Wr0 : Wc0;
    const float* bias = (region == 0) ? bu0 : (region == 1) ? br0 : bc0;
    const int row0 = (region == 2) ? 512 : 0;
    const int nOff = nBase - region * 512;

    const int r0 = tid >> 4, c0 = tid & 15;
    const int rl = tid >> 4, kl = tid & 15;
    int tok[4]; int bidx[4];
#pragma unroll
    for (int i = 0; i < 4; i++) {
        int m = mBase + rl + 16 * i;
        bidx[i] = m & 127;
        tok[i] = tokens[bidx[i] * TT + (m >> 7)];
    }

    float acc[4][4];
#pragma unroll
    for (int i = 0; i < 4; i++)
#pragma unroll
        for (int j = 0; j < 4; j++) acc[i][j] = 0.f;

    for (int k0 = 0; k0 < IN0; k0 += 16) {
        int kabs = k0 + kl;
#pragma unroll
        for (int i = 0; i < 4; i++) {
            float v = (kabs < 512) ? emb[(size_t)tok[i] * EE + kabs]
                                   : g_p[bidx[i] * MAPS + (kabs - 512)];
            As[rl + 16 * i][kl] = v;
        }
#pragma unroll
        for (int i = 0; i < 4; i++) {
            int e = tid + i * 256;
            int kk = e >> 6, n = e & 63;
            Bs[kk][n] = Bw[(row0 + k0 + kk) * HH + nOff + n];
        }
        __syncthreads();
#pragma unroll
        for (int kk = 0; kk < 16; kk++) {
            float a0 = As[r0][kk], a1 = As[r0 + 16][kk], a2 = As[r0 + 32][kk], a3 = As[r0 + 48][kk];
            float b0 = Bs[kk][c0], b1 = Bs[kk][c0 + 16], b2 = Bs[kk][c0 + 32], b3 = Bs[kk][c0 + 48];
            acc[0][0] += a0 * b0; acc[0][1] += a0 * b1; acc[0][2] += a0 * b2; acc[0][3] += a0 * b3;
            acc[1][0] += a1 * b0; acc[1][1] += a1 * b1; acc[1][2] += a1 * b2; acc[1][3] += a1 * b3;
            acc[2][0] += a2 * b0; acc[2][1] += a2 * b1; acc[2][2] += a2 * b2; acc[2][3] += a2 * b3;
            acc[3][0] += a3 * b0; acc[3][1] += a3 * b1; acc[3][2] += a3 * b2; acc[3][3] += a3 * b3;
        }
        __syncthreads();
    }
#pragma unroll
    for (int i = 0; i < 4; i++) {
        int m = mBase + r0 + 16 * i;
#pragma unroll
        for (int j = 0; j < 4; j++) {
            int nl = nOff + c0 + 16 * j;
            g_X0[m * 1536 + nBase + c0 + 16 * j] = acc[i][j] + bias[nl];
        }
    }
}

// ---------------- logits ----------------
__global__ void __launch_bounds__(256) k_logits(const float* __restrict__ Wout,
                                                const float* __restrict__ bout,
                                                float* __restrict__ out)
{
    __shared__ float As[64][17];
    __shared__ float Bs[16][64];
    const int tid = threadIdx.x;
    const int mBase = blockIdx.y * 64;
    const int nBase = blockIdx.x * 64;
    const int r0 = tid >> 4, c0 = tid & 15;
    const int rl = tid >> 4, kl = tid & 15;

    float acc[4][4];
#pragma unroll
    for (int i = 0; i < 4; i++)
#pragma unroll
        for (int j = 0; j < 4; j++) acc[i][j] = 0.f;

    for (int k0 = 0; k0 < HH; k0 += 16) {
#pragma unroll
        for (int i = 0; i < 4; i++)
            As[rl + 16 * i][kl] = g_H1[(mBase + rl + 16 * i) * HH + k0 + kl];
#pragma unroll
        for (int i = 0; i < 4; i++) {
            int e = tid + i * 256;
            int kk = e >> 6, n = e & 63;
            int col = nBase + n;
            Bs[kk][n] = (col < VV) ? Wout[(k0 + kk) * VV + col] : 0.f;
        }
        __syncthreads();
#pragma unroll
        for (int kk = 0; kk < 16; kk++) {
            float a0 = As[r0][kk], a1 = As[r0 + 16][kk], a2 = As[r0 + 32][kk], a3 = As[r0 + 48][kk];
            float b0 = Bs[kk][c0], b1 = Bs[kk][c0 + 16], b2 = Bs[kk][c0 + 32], b3 = Bs[kk][c0 + 48];
            acc[0][0] += a0 * b0; acc[0][1] += a0 * b1; acc[0][2] += a0 * b2; acc[0][3] += a0 * b3;
            acc[1][0] += a1 * b0; acc[1][1] += a1 * b1; acc[1][2] += a1 * b2; acc[1][3] += a1 * b3;
            acc[2][0] += a2 * b0; acc[2][1] += a2 * b1; acc[2][2] += a2 * b2; acc[2][3] += a2 * b3;
            acc[3][0] += a3 * b0; acc[3][1] += a3 * b1; acc[3][2] += a3 * b2; acc[3][3] += a3 * b3;
        }
        __syncthreads();
    }
#pragma unroll
    for (int i = 0; i < 4; i++) {
        int m = mBase + r0 + 16 * i;
        int tIdx = m >> 7, b = m & 127;
        size_t rowOff = ((size_t)b * TT + tIdx) * VV;
#pragma unroll
        for (int j = 0; j < 4; j++) {
            int col = nBase + c0 + 16 * j;
            if (col < VV) out[rowOff + col] = acc[i][j] + bout[col];
        }
    }
}

__global__ void k_hidden(float* __restrict__ outh) {
    int i = blockIdx.x * blockDim.x + threadIdx.x;
    if (i < BB * HH) {
        outh[i]           = g_h0[1][i];
        outh[BB * HH + i] = g_h1[1][i];
    }
}

// ---------------- launch ----------------
extern "C" void kernel_launch(void* const* d_in, const int* in_sizes, int n_in,
                              void* d_out, int out_size) {
    const int*   tokens = (const int*)d_in[0];     // int32 (JAX x64 disabled)
    const float* cnn  = (const float*)d_in[1];
    const float* emb  = (const float*)d_in[2];
    const float* Win  = (const float*)d_in[3];
    const float* bin  = (const float*)d_in[4];
    const float* Wout = (const float*)d_in[5];
    const float* bout = (const float*)d_in[6];
    const float* Wu0  = (const float*)d_in[7];
    const float* bu0  = (const float*)d_in[8];
    const float* Wr0  = (const float*)d_in[9];
    const float* br0  = (const float*)d_in[10];
    const float* Wc0  = (const float*)d_in[11];
    const float* bc0  = (const float*)d_in[12];
    const float* Wu1  = (const float*)d_in[13];
    const float* bu1  = (const float*)d_in[14];
    const float* Wr1  = (const float*)d_in[15];
    const float* br1  = (const float*)d_in[16];
    const float* Wc1  = (const float*)d_in[17];
    const float* bc1  = (const float*)d_in[18];
    float* out = (float*)d_out;

    long long packN = 1024LL*512 + 512LL*512 + 1024LL*1024 + 512LL*1024 + 1024;
    k_pack<<<(int)((packN + 255) / 256), 256>>>(Wu0, Wr0, Wc0, Wu1, Wr1, Wc1, bu1, br1);

    small_gemm<NFE, OpP><<<dim3(MAPS / 32, BB / 32), 256>>>(OpP{cnn, Win, bin});

    k_precompute<<<dim3(1536 / 64, (TT * BB) / 64), 256>>>(tokens, emb, Wu0, Wr0, Wc0, bu0, br0, bc0);

    k_recurrence<<<NBLK, 256>>>(bc1);

    k_logits<<<dim3((VV + 63) / 64, (TT * BB) / 64), 256>>>(Wout, bout, out);

    k_hidden<<<(BB * HH + 255) / 256, 256>>>(out + (size_t)BB * TT * VV);
}

// round 7
// speedup vs baseline: 1.2036x; 1.0409x over previous
#include <cuda_runtime.h>
#include <math.h>

#define BB   128
#define TT   25
#define VV   10000
#define EE   512
#define NFE  2048
#define HH   512
#define MAPS 512
#define IN0  1024   // EE + MAPS
#define NBLK 128    // 4 row-groups x 32 col-tiles

// ---------------- scratch ----------------
__device__ float g_p[BB * MAPS];
__device__ float g_X0[TT * BB * 1536];
__device__ float g_h0[2][BB * HH];
__device__ float g_h1[2][BB * HH];
__device__ float g_ur0[BB * 1024];
__device__ float g_ur1[BB * 1024];
__device__ float g_H1[TT * BB * HH];
__device__ float g_bur1[1024];

// transposed recurrent weights, [n][k]
__device__ float g_WAT[1024 * 512];
__device__ float g_WBT[512 * 512];
__device__ float g_WCT[1024 * 1024];
__device__ float g_WDT[512 * 1024];

// group-local store/load barriers (4 groups x 32 blocks)
__device__ volatile int g_gflags[4][32];
__device__ volatile int g_gepoch[4];

__device__ __forceinline__ float sigmoidf(float x) { return 1.f / (1.f + expf(-x)); }
__device__ __forceinline__ float4 ldcg4(const float* p) {
    return __ldcg(reinterpret_cast<const float4*>(p));
}

__device__ __forceinline__ void gbarg(int grp, int ct, int e) {
    __syncthreads();
    if (ct == 0) {
        if (threadIdx.x > 0 && threadIdx.x < 32) {
            while (g_gflags[grp][threadIdx.x] < e) { }
        }
        __syncthreads();
        if (threadIdx.x == 0) {
            __threadfence();
            g_gepoch[grp] = e;
        }
    } else {
        if (threadIdx.x == 0) {
            __threadfence();
            g_gflags[grp][ct] = e;
            while (g_gepoch[grp] < e) { }
            __threadfence();
        }
    }
    __syncthreads();
}

// ---------------- pack ----------------
__global__ void k_pack(const float* __restrict__ Wu0, const float* __restrict__ Wr0,
                       const float* __restrict__ Wc0,
                       const float* __restrict__ Wu1, const float* __restrict__ Wr1,
                       const float* __restrict__ Wc1,
                       const float* __restrict__ bu1, const float* __restrict__ br1) {
    long long i = (long long)blockIdx.x * blockDim.x + threadIdx.x;
    if (i < 128) { g_gflags[i >> 5][i & 31] = 0; if ((i & 31) == 0) g_gepoch[i >> 5] = 0; }
    if (i < 1024LL * 512) {
        int n = (int)(i >> 9), k = (int)(i & 511);
        g_WAT[i] = (n < 512) ? Wu0[(IN0 + k) * HH + n] : Wr0[(IN0 + k) * HH + (n - 512)];
        return;
    }
    i -= 1024LL * 512;
    if (i < 512LL * 512) {
        int n = (int)(i >> 9), k = (int)(i & 511);
        g_WBT[i] = Wc0[k * HH + n];
        return;
    }
    i -= 512LL * 512;
    if (i < 1024LL * 1024) {
        int n = (int)(i >> 10), k = (int)(i & 1023);
        g_WCT[i] = (n < 512) ? Wu1[k * HH + n] : Wr1[k * HH + (n - 512)];
        return;
    }
    i -= 1024LL * 1024;
    if (i < 512LL * 1024) {
        int n = (int)(i >> 10), k = (int)(i & 1023);
        g_WDT[i] = Wc1[k * HH + n];
        return;
    }
    i -= 512LL * 1024;
    if (i < 1024) g_bur1[i] = (i < 512) ? bu1[i] : br1[i - 512];
}

// ---------------- input layer GEMM ----------------
template <int K, typename Op>
__global__ void __launch_bounds__(256) small_gemm(Op op) {
    __shared__ float As[32][33];
    __shared__ float Bs[32][33];
    const int tid = threadIdx.x;
    const int r0 = tid >> 4;
    const int c0 = tid & 15;
    const int mBase = blockIdx.y * 32;
    const int nBase = blockIdx.x * 32;

    float a00 = 0.f, a01 = 0.f, a10 = 0.f, a11 = 0.f;

    for (int k0 = 0; k0 < K; k0 += 32) {
#pragma unroll
        for (int i = 0; i < 4; i++) {
            int e = tid + i * 256;
            int r = e >> 5, kk = e & 31;
            As[r][kk] = op.loadA(mBase + r, k0 + kk);
        }
#pragma unroll
        for (int i = 0; i < 4; i++) {
            int e = tid + i * 256;
            int kk = e >> 5, n = e & 31;
            Bs[kk][n] = op.loadB(k0 + kk, nBase + n);
        }
        __syncthreads();
#pragma unroll
        for (int kk = 0; kk < 32; kk++) {
            float x0 = As[r0][kk],      x1 = As[r0 + 16][kk];
            float y0 = Bs[kk][c0],      y1 = Bs[kk][c0 + 16];
            a00 += x0 * y0; a01 += x0 * y1;
            a10 += x1 * y0; a11 += x1 * y1;
        }
        __syncthreads();
    }
    op.store(mBase + r0,      nBase + c0,      a00);
    op.store(mBase + r0,      nBase + c0 + 16, a01);
    op.store(mBase + r0 + 16, nBase + c0,      a10);
    op.store(mBase + r0 + 16, nBase + c0 + 16, a11);
}

struct OpP {
    const float* A; const float* Bw; const float* bias;
    __device__ float loadA(int r, int k) const { return A[r * NFE + k]; }
    __device__ float loadB(int k, int n) const { return Bw[k * MAPS + n]; }
    __device__ void store(int r, int n, float acc) const {
        float v = acc + bias[n];
        g_p[r * MAPS + n] = v > 0.f ? v : 0.01f * v;
    }
};

// ---------------- persistent recurrence: 4 row-groups x 32 col-tiles ----------------
// Block (grp, ct): rows grp*32..+31, cols ct*COLS..+COLS-1 of the phase output.
// As row-major [row][k] (direct float4 stage); compute: row = lane, cols = w*CWT+j.
template <int PH, int COLS, int KTOT>
__device__ __forceinline__ void run_phase(
    float As[32][36], float Bs[32][36], int t, int grp, int ct,
    const float* h0c, float* h0n, const float* h1c, float* h1n,
    const float* __restrict__ bc1)
{
    const int tid = threadIdx.x;
    const int w = tid >> 5, lane = tid & 31;
    constexpr int CWT = COLS / 8;                 // cols per thread (4 or 2)
    const int cb = ct * COLS;
    const int cw = w * CWT;
    const int R0 = grp * 32;

    const float* WT = (PH == 0) ? g_WAT : (PH == 1) ? g_WBT : (PH == 2) ? g_WCT : g_WDT;

    float acc[CWT];
#pragma unroll
    for (int j = 0; j < CWT; j++) acc[j] = 0.f;

    // staging roles: A: thread -> (row=tid>>3, k4=(tid&7)*4); B: (col=tid>>3, k4)
    const int sr = tid >> 3;
    const int sk = (tid & 7) << 2;
    const bool bAct = (COLS == 32) ? true : (tid < 128);

    auto loadA4 = [&](int ka) -> float4 {
        int r = R0 + sr;
        if (PH == 0) {
            return ldcg4(h0c + r * HH + ka);
        } else if (PH == 1) {
            float4 u = ldcg4(g_ur0 + r * 1024 + 512 + ka);
            float4 h = ldcg4(h0c + r * HH + ka);
            return make_float4(u.x * h.x, u.y * h.y, u.z * h.z, u.w * h.w);
        } else if (PH == 2) {
            return (ka < 512) ? ldcg4(h0n + r * HH + ka)
                              : ldcg4(h1c + r * HH + (ka - 512));
        } else {
            if (ka < 512) {
                float4 u = ldcg4(g_ur1 + r * 1024 + 512 + ka);
                float4 h = ldcg4(h1c + r * HH + ka);
                return make_float4(u.x * h.x, u.y * h.y, u.z * h.z, u.w * h.w);
            }
            return ldcg4(h0n + r * HH + (ka - 512));
        }
    };

    float4 va = loadA4(sk);
    float4 vb;
    if (bAct) vb = *reinterpret_cast<const float4*>(WT + (cb + sr) * KTOT + sk);

    for (int k0 = 0; k0 < KTOT; k0 += 32) {
        *reinterpret_cast<float4*>(&As[sr][sk]) = va;
        if (bAct) *reinterpret_cast<float4*>(&Bs[sr][sk]) = vb;
        __syncthreads();

        if (k0 + 32 < KTOT) {
            va = loadA4(k0 + 32 + sk);
            if (bAct) vb = *reinterpret_cast<const float4*>(WT + (cb + sr) * KTOT + k0 + 32 + sk);
        }

#pragma unroll
        for (int kk = 0; kk < 32; kk += 4) {
            float4 a = *reinterpret_cast<const float4*>(&As[lane][kk]);
#pragma unroll
            for (int j = 0; j < CWT; j++) {
                float4 b = *reinterpret_cast<const float4*>(&Bs[cw + j][kk]);
                acc[j] = fmaf(a.x, b.x, acc[j]);
                acc[j] = fmaf(a.y, b.y, acc[j]);
                acc[j] = fmaf(a.z, b.z, acc[j]);
                acc[j] = fmaf(a.w, b.w, acc[j]);
            }
        }
        __syncthreads();
    }

    const int R = R0 + lane;
    const int cgl = cb + cw;                     // global col of acc[0]

    if (PH == 0) {        // ur0 = sigmoid(acc + X0[u|r]),  CWT=4
        const float* x = g_X0 + (t * BB + R) * 1536 + cgl;
        float4 o;
        o.x = sigmoidf(acc[0] + x[0]);
        o.y = sigmoidf(acc[1] + x[1]);
        o.z = sigmoidf(acc[2] + x[2]);
        o.w = sigmoidf(acc[3] + x[3]);
        *reinterpret_cast<float4*>(g_ur0 + R * 1024 + cgl) = o;
    } else if (PH == 1) { // h0' = u*h0 + (1-u)*tanh(acc + X0[c]),  CWT=2
        const float* x = g_X0 + (t * BB + R) * 1536 + 1024 + cgl;
        float u0 = __ldcg(g_ur0 + R * 1024 + cgl);
        float u1 = __ldcg(g_ur0 + R * 1024 + cgl + 1);
        float p0 = __ldcg(h0c + R * HH + cgl);
        float p1 = __ldcg(h0c + R * HH + cgl + 1);
        float hh0 = tanhf(acc[0] + x[0]);
        float hh1 = tanhf(acc[1] + x[1]);
        float2 o;
        o.x = u0 * p0 + (1.f - u0) * hh0;
        o.y = u1 * p1 + (1.f - u1) * hh1;
        *reinterpret_cast<float2*>(h0n + R * HH + cgl) = o;
    } else if (PH == 2) { // ur1 = sigmoid(acc + bur1),  CWT=4
        float4 o;
        o.x = sigmoidf(acc[0] + g_bur1[cgl]);
        o.y = sigmoidf(acc[1] + g_bur1[cgl + 1]);
        o.z = sigmoidf(acc[2] + g_bur1[cgl + 2]);
        o.w = sigmoidf(acc[3] + g_bur1[cgl + 3]);
        *reinterpret_cast<float4*>(g_ur1 + R * 1024 + cgl) = o;
    } else {              // h1' = u*h1 + (1-u)*tanh(acc + bc1); also H1[t],  CWT=2
        float u0 = __ldcg(g_ur1 + R * 1024 + cgl);
        float u1 = __ldcg(g_ur1 + R * 1024 + cgl + 1);
        float p0 = __ldcg(h1c + R * HH + cgl);
        float p1 = __ldcg(h1c + R * HH + cgl + 1);
        float hh0 = tanhf(acc[0] + bc1[cgl]);
        float hh1 = tanhf(acc[1] + bc1[cgl + 1]);
        float2 o;
        o.x = u0 * p0 + (1.f - u0) * hh0;
        o.y = u1 * p1 + (1.f - u1) * hh1;
        *reinterpret_cast<float2*>(h1n + R * HH + cgl) = o;
        *reinterpret_cast<float2*>(g_H1 + (t * BB + R) * HH + cgl) = o;
    }
}

__global__ void __launch_bounds__(256, 1) k_recurrence(const float* __restrict__ bc1) {
    __shared__ float As[32][36];
    __shared__ float Bs[32][36];
    const int tid = threadIdx.x, blk = blockIdx.x;
    const int grp = blk >> 5, ct = blk & 31;
    int ep = 0;

    // zero this group's rows of h0[0], h1[0]  (32 rows x 512 = 16384 floats/group)
    {
        int off = grp * 16384 + ct * 512 + tid * 2;
        *reinterpret_cast<float2*>(&g_h0[0][0] + off) = make_float2(0.f, 0.f);
        *reinterpret_cast<float2*>(&g_h1[0][0] + off) = make_float2(0.f, 0.f);
    }
    gbarg(grp, ct, ++ep);

    for (int t = 0; t < TT; t++) {
        const int cur = t & 1;
        const float* h0c = g_h0[cur];
        float*       h0n = g_h0[cur ^ 1];
        const float* h1c = g_h1[cur];
        float*       h1n = g_h1[cur ^ 1];

        run_phase<0, 32,  512>(As, Bs, t, grp, ct, h0c, h0n, h1c, h1n, bc1);  // ur0
        gbarg(grp, ct, ++ep);
        run_phase<1, 16,  512>(As, Bs, t, grp, ct, h0c, h0n, h1c, h1n, bc1);  // h0'
        gbarg(grp, ct, ++ep);
        run_phase<2, 32, 1024>(As, Bs, t, grp, ct, h0c, h0n, h1c, h1n, bc1);  // ur1
        gbarg(grp, ct, ++ep);
        run_phase<3, 16, 1024>(As, Bs, t, grp, ct, h0c, h0n, h1c, h1n, bc1);  // h1'
        if (t != TT - 1) gbarg(grp, ct, ++ep);
    }
}

// ---------------- precompute X0 ----------------
__global__ void __launch_bounds__(256) k_precompute(
    const int* __restrict__ tokens, const float* __restrict__ emb,
    const float* __restrict__ Wu0, const float* __restrict__ Wr0, const float* __restrict__ Wc0,
    const float* __restrict__ bu0, const float* __restrict__ br0, const float* __restrict__ bc0)
{
    __shared__ float As[64][17];
    __shared__ float Bs[16][64];
    const int tid = threadIdx.x;
    const int mBase = blockIdx.y * 64;
    const int nBase = blockIdx.x * 64;
    const int region = nBase >> 9;
    const float* Bw   = (region == 0) ? Wu0 : (region == 1) ? Wr0 : Wc0;
    const float* bias = (region == 0) ? bu0 : (region == 1) ? br0 : bc0;
    const int row0 = (region == 2) ? 512 : 0;
    const int nOff = nBase - region * 512;

    const int r0 = tid >> 4, c0 = tid & 15;
    const int rl = tid >> 4, kl = tid & 15;
    int tok[4]; int bidx[4];
#pragma unroll
    for (int i = 0; i < 4; i++) {
        int m = mBase + rl + 16 * i;
        bidx[i] = m & 127;
        tok[i] = tokens[bidx[i] * TT + (m >> 7)];
    }

    float acc[4][4];
#pragma unroll
    for (int i = 0; i < 4; i++)
#pragma unroll
        for (int j = 0; j < 4; j++) acc[i][j] = 0.f;

    for (int k0 = 0; k0 < IN0; k0 += 16) {
        int kabs = k0 + kl;
#pragma unroll
        for (int i = 0; i < 4; i++) {
            float v = (kabs < 512) ? emb[(size_t)tok[i] * EE + kabs]
                                   : g_p[bidx[i] * MAPS + (kabs - 512)];
            As[rl + 16 * i][kl] = v;
        }
#pragma unroll
        for (int i = 0; i < 4; i++) {
            int e = tid + i * 256;
            int kk = e >> 6, n = e & 63;
            Bs[kk][n] = Bw[(row0 + k0 + kk) * HH + nOff + n];
        }
        __syncthreads();
#pragma unroll
        for (int kk = 0; kk < 16; kk++) {
            float a0 = As[r0][kk], a1 = As[r0 + 16][kk], a2 = As[r0 + 32][kk], a3 = As[r0 + 48][kk];
            float b0 = Bs[kk][c0], b1 = Bs[kk][c0 + 16], b2 = Bs[kk][c0 + 32], b3 = Bs[kk][c0 + 48];
            acc[0][0] += a0 * b0; acc[0][1] += a0 * b1; acc[0][2] += a0 * b2; acc[0][3] += a0 * b3;
            acc[1][0] += a1 * b0; acc[1][1] += a1 * b1; acc[1][2] += a1 * b2; acc[1][3] += a1 * b3;
            acc[2][0] += a2 * b0; acc[2][1] += a2 * b1; acc[2][2] += a2 * b2; acc[2][3] += a2 * b3;
            acc[3][0] += a3 * b0; acc[3][1] += a3 * b1; acc[3][2] += a3 * b2; acc[3][3] += a3 * b3;
        }
        __syncthreads();
    }
#pragma unroll
    for (int i = 0; i < 4; i++) {
        int m = mBase + r0 + 16 * i;
#pragma unroll
        for (int j = 0; j < 4; j++) {
            int nl = nOff + c0 + 16 * j;
            g_X0[m * 1536 + nBase + c0 + 16 * j] = acc[i][j] + bias[nl];
        }
    }
}

// ---------------- logits ----------------
__global__ void __launch_bounds__(256) k_logits(const float* __restrict__ Wout,
                                                const float* __restrict__ bout,
                                                float* __restrict__ out)
{
    __shared__ float As[64][17];
    __shared__ float Bs[16][64];
    const int tid = threadIdx.x;
    const int mBase = blockIdx.y * 64;
    const int nBase = blockIdx.x * 64;
    const int r0 = tid >> 4, c0 = tid & 15;
    const int rl = tid >> 4, kl = tid & 15;

    float acc[4][4];
#pragma unroll
    for (int i = 0; i < 4; i++)
#pragma unroll
        for (int j = 0; j < 4; j++) acc[i][j] = 0.f;

    for (int k0 = 0; k0 < HH; k0 += 16) {
#pragma unroll
        for (int i = 0; i < 4; i++)
            As[rl + 16 * i][kl] = g_H1[(mBase + rl + 16 * i) * HH + k0 + kl];
#pragma unroll
        for (int i = 0; i < 4; i++) {
            int e = tid + i * 256;
            int kk = e >> 6, n = e & 63;
            int col = nBase + n;
            Bs[kk][n] = (col < VV) ? Wout[(k0 + kk) * VV + col] : 0.f;
        }
        __syncthreads();
#pragma unroll
        for (int kk = 0; kk < 16; kk++) {
            float a0 = As[r0][kk], a1 = As[r0 + 16][kk], a2 = As[r0 + 32][kk], a3 = As[r0 + 48][kk];
            float b0 = Bs[kk][c0], b1 = Bs[kk][c0 + 16], b2 = Bs[kk][c0 + 32], b3 = Bs[kk][c0 + 48];
            acc[0][0] += a0 * b0; acc[0][1] += a0 * b1; acc[0][2] += a0 * b2; acc[0][3] += a0 * b3;
            acc[1][0] += a1 * b0; acc[1][1] += a1 * b1; acc[1][2] += a1 * b2; acc[1][3] += a1 * b3;
            acc[2][0] += a2 * b0; acc[2][1] += a2 * b1; acc[2][2] += a2 * b2; acc[2][3] += a2 * b3;
            acc[3][0] += a3 * b0; acc[3][1] += a3 * b1; acc[3][2] += a3 * b2; acc[3][3] += a3 * b3;
        }
        __syncthreads();
    }
#pragma unroll
    for (int i = 0; i < 4; i++) {
        int m = mBase + r0 + 16 * i;
        int tIdx = m >> 7, b = m & 127;
        size_t rowOff = ((size_t)b * TT + tIdx) * VV;
#pragma unroll
        for (int j = 0; j < 4; j++) {
            int col = nBase + c0 + 16 * j;
            if (col < VV) out[rowOff + col] = acc[i][j] + bout[col];
        }
    }
}

__global__ void k_hidden(float* __restrict__ outh) {
    int i = blockIdx.x * blockDim.x + threadIdx.x;
    if (i < BB * HH) {
        outh[i]           = g_h0[1][i];
        outh[BB * HH + i] = g_h1[1][i];
    }
}

// ---------------- launch ----------------
extern "C" void kernel_launch(void* const* d_in, const int* in_sizes, int n_in,
                              void* d_out, int out_size) {
    const int*   tokens = (const int*)d_in[0];     // int32 (JAX x64 disabled)
    const float* cnn  = (const float*)d_in[1];
    const float* emb  = (const float*)d_in[2];
    const float* Win  = (const float*)d_in[3];
    const float* bin  = (const float*)d_in[4];
    const float* Wout = (const float*)d_in[5];
    const float* bout = (const float*)d_in[6];
    const float* Wu0  = (const float*)d_in[7];
    const float* bu0  = (const float*)d_in[8];
    const float* Wr0  = (const float*)d_in[9];
    const float* br0  = (const float*)d_in[10];
    const float* Wc0  = (const float*)d_in[11];
    const float* bc0  = (const float*)d_in[12];
    const float* Wu1  = (const float*)d_in[13];
    const float* bu1  = (const float*)d_in[14];
    const float* Wr1  = (const float*)d_in[15];
    const float* br1  = (const float*)d_in[16];
    const float* Wc1  = (const float*)d_in[17];
    const float* bc1  = (const float*)d_in[18];
    float* out = (float*)d_out;

    long long packN = 1024LL*512 + 512LL*512 + 1024LL*1024 + 512LL*1024 + 1024;
    k_pack<<<(int)((packN + 255) / 256), 256>>>(Wu0, Wr0, Wc0, Wu1, Wr1, Wc1, bu1, br1);

    small_gemm<NFE, OpP><<<dim3(MAPS / 32, BB / 32), 256>>>(OpP{cnn, Win, bin});

    k_precompute<<<dim3(1536 / 64, (TT * BB) / 64), 256>>>(tokens, emb, Wu0, Wr0, Wc0, bu0, br0, bc0);

    k_recurrence<<<NBLK, 256>>>(bc1);

    k_logits<<<dim3((VV + 63) / 64, (TT * BB) / 64), 256>>>(Wout, bout, out);

    k_hidden<<<(BB * HH + 255) / 256, 256>>>(out + (size_t)BB * TT * VV);
}

// round 8
// speedup vs baseline: 1.2869x; 1.0692x over previous
#include <cuda_runtime.h>
#include <math.h>

#define BB   128
#define TT   25
#define VV   10000
#define EE   512
#define NFE  2048
#define HH   512
#define MAPS 512
#define IN0  1024   // EE + MAPS
#define NBLK 128    // 4 row-groups x 32 col-tiles

// ---------------- scratch ----------------
__device__ float g_p[BB * MAPS];
__device__ float g_X0[TT * BB * 1536];
__device__ float g_h0[2][BB * HH];
__device__ float g_h1[2][BB * HH];
__device__ float g_ur0[BB * 1024];
__device__ float g_ur1[BB * 1024];
__device__ float g_H1[TT * BB * HH];
__device__ float g_bur1[1024];

// packed gate weights, ORIGINAL [k][n] layout (coalesced B staging)
__device__ float g_WA[512 * 1024];     // rows k<512 (h-part), cols [u|r] of layer0
__device__ float g_WC[1024 * 1024];    // rows k<1024 ([h0',h1]), cols [u|r] of layer1

// group-local store/load barriers (4 groups x 32 blocks)
__device__ volatile int g_gflags[4][32];
__device__ volatile int g_gepoch[4];

__device__ __forceinline__ float sigmoidf(float x) { return 1.f / (1.f + expf(-x)); }
__device__ __forceinline__ float4 ldcg4(const float* p) {
    return __ldcg(reinterpret_cast<const float4*>(p));
}
__device__ __forceinline__ float4 ldg4(const float* p) {
    return __ldg(reinterpret_cast<const float4*>(p));
}

__device__ __forceinline__ void gbarg(int grp, int ct, int e) {
    __syncthreads();
    if (ct == 0) {
        if (threadIdx.x > 0 && threadIdx.x < 32) {
            while (g_gflags[grp][threadIdx.x] < e) { }
        }
        __syncthreads();
        if (threadIdx.x == 0) {
            __threadfence();
            g_gepoch[grp] = e;
        }
    } else {
        if (threadIdx.x == 0) {
            __threadfence();
            g_gflags[grp][ct] = e;
            while (g_gepoch[grp] < e) { }
            __threadfence();
        }
    }
    __syncthreads();
}

// ---------------- pack ----------------
__global__ void k_pack(const float* __restrict__ Wu0, const float* __restrict__ Wr0,
                       const float* __restrict__ Wu1, const float* __restrict__ Wr1,
                       const float* __restrict__ bu1, const float* __restrict__ br1) {
    long long i = (long long)blockIdx.x * blockDim.x + threadIdx.x;
    if (i < 128) { g_gflags[i >> 5][i & 31] = 0; if ((i & 31) == 0) g_gepoch[i >> 5] = 0; }
    // WA: [512][1024]: row k = [Wu0[IN0+k][0:512] | Wr0[IN0+k][0:512]]
    if (i < 512LL * 1024) {
        int k = (int)(i >> 10), n = (int)(i & 1023);
        g_WA[i] = (n < 512) ? Wu0[(IN0 + k) * HH + n] : Wr0[(IN0 + k) * HH + (n - 512)];
        return;
    }
    i -= 512LL * 1024;
    // WC: [1024][1024]: row k = [Wu1[k][0:512] | Wr1[k][0:512]]
    if (i < 1024LL * 1024) {
        int k = (int)(i >> 10), n = (int)(i & 1023);
        g_WC[i] = (n < 512) ? Wu1[k * HH + n] : Wr1[k * HH + (n - 512)];
        return;
    }
    i -= 1024LL * 1024;
    if (i < 1024) g_bur1[i] = (i < 512) ? bu1[i] : br1[i - 512];
}

// ---------------- input layer GEMM ----------------
template <int K, typename Op>
__global__ void __launch_bounds__(256) small_gemm(Op op) {
    __shared__ float As[32][33];
    __shared__ float Bs[32][33];
    const int tid = threadIdx.x;
    const int r0 = tid >> 4;
    const int c0 = tid & 15;
    const int mBase = blockIdx.y * 32;
    const int nBase = blockIdx.x * 32;

    float a00 = 0.f, a01 = 0.f, a10 = 0.f, a11 = 0.f;

    for (int k0 = 0; k0 < K; k0 += 32) {
#pragma unroll
        for (int i = 0; i < 4; i++) {
            int e = tid + i * 256;
            int r = e >> 5, kk = e & 31;
            As[r][kk] = op.loadA(mBase + r, k0 + kk);
        }
#pragma unroll
        for (int i = 0; i < 4; i++) {
            int e = tid + i * 256;
            int kk = e >> 5, n = e & 31;
            Bs[kk][n] = op.loadB(k0 + kk, nBase + n);
        }
        __syncthreads();
#pragma unroll
        for (int kk = 0; kk < 32; kk++) {
            float x0 = As[r0][kk],      x1 = As[r0 + 16][kk];
            float y0 = Bs[kk][c0],      y1 = Bs[kk][c0 + 16];
            a00 += x0 * y0; a01 += x0 * y1;
            a10 += x1 * y0; a11 += x1 * y1;
        }
        __syncthreads();
    }
    op.store(mBase + r0,      nBase + c0,      a00);
    op.store(mBase + r0,      nBase + c0 + 16, a01);
    op.store(mBase + r0 + 16, nBase + c0,      a10);
    op.store(mBase + r0 + 16, nBase + c0 + 16, a11);
}

struct OpP {
    const float* A; const float* Bw; const float* bias;
    __device__ float loadA(int r, int k) const { return A[r * NFE + k]; }
    __device__ float loadB(int k, int n) const { return Bw[k * MAPS + n]; }
    __device__ void store(int r, int n, float acc) const {
        float v = acc + bias[n];
        g_p[r * MAPS + n] = v > 0.f ? v : 0.01f * v;
    }
};

// ---------------- persistent recurrence: 512 threads, K-chunk 64 ----------------
// Block (grp, ct): rows grp*32..+31, cols ct*COLS..+COLS-1.
// Thread (r = tid>>4, c2 = tid&15): COLS=32 -> 2 cols (2*c2, 2*c2+1); COLS=16 -> col c2.
template <int PH, int COLS, int KTOT>
__device__ __forceinline__ void run_phase(
    float As[32][68], float Bs[64][36], int t, int grp, int ct,
    const float* h0c, float* h0n, const float* h1c, float* h1n,
    const float* __restrict__ Wg, int Wstride,
    const float* __restrict__ bc1)
{
    const int tid = threadIdx.x;
    const int r = tid >> 4, c2 = tid & 15;
    const int R0 = grp * 32;
    const int cb = ct * COLS;

    // A staging: thread -> (row sr, k-offset sk4) of the 32x64 chunk
    const int sr = tid >> 4;
    const int sk4 = (tid & 15) << 2;
    // B staging
    int bk, bn; bool bAct;
    if (COLS == 32) { bk = tid >> 3; bn = (tid & 7) << 2; bAct = true; }
    else            { bk = tid >> 2; bn = (tid & 3) << 2; bAct = (tid < 256); }

    float acc0 = 0.f, acc1 = 0.f;

    auto loadA4 = [&](int ka) -> float4 {
        int rr = R0 + sr;
        if (PH == 0) {
            return ldcg4(h0c + rr * HH + ka);
        } else if (PH == 1) {
            float4 u = ldcg4(g_ur0 + rr * 1024 + 512 + ka);
            float4 h = ldcg4(h0c + rr * HH + ka);
            return make_float4(u.x * h.x, u.y * h.y, u.z * h.z, u.w * h.w);
        } else if (PH == 2) {
            return (ka < 512) ? ldcg4(h0n + rr * HH + ka)
                              : ldcg4(h1c + rr * HH + (ka - 512));
        } else {
            if (ka < 512) {
                float4 u = ldcg4(g_ur1 + rr * 1024 + 512 + ka);
                float4 h = ldcg4(h1c + rr * HH + ka);
                return make_float4(u.x * h.x, u.y * h.y, u.z * h.z, u.w * h.w);
            }
            return ldcg4(h0n + rr * HH + (ka - 512));
        }
    };

    float4 va = loadA4(sk4);
    float4 vb;
    if (bAct) vb = ldg4(Wg + bk * Wstride + cb + bn);

    for (int k0 = 0; k0 < KTOT; k0 += 64) {
        *reinterpret_cast<float4*>(&As[sr][sk4]) = va;
        if (bAct) *reinterpret_cast<float4*>(&Bs[bk][bn]) = vb;
        __syncthreads();

        if (k0 + 64 < KTOT) {
            va = loadA4(k0 + 64 + sk4);
            if (bAct) vb = ldg4(Wg + (k0 + 64 + bk) * Wstride + cb + bn);
        }

#pragma unroll
        for (int kk = 0; kk < 64; kk += 4) {
            float4 a = *reinterpret_cast<const float4*>(&As[r][kk]);
            if (COLS == 32) {
                float2 b0 = *reinterpret_cast<const float2*>(&Bs[kk][2 * c2]);
                float2 b1 = *reinterpret_cast<const float2*>(&Bs[kk + 1][2 * c2]);
                float2 b2 = *reinterpret_cast<const float2*>(&Bs[kk + 2][2 * c2]);
                float2 b3 = *reinterpret_cast<const float2*>(&Bs[kk + 3][2 * c2]);
                acc0 = fmaf(a.x, b0.x, acc0); acc1 = fmaf(a.x, b0.y, acc1);
                acc0 = fmaf(a.y, b1.x, acc0); acc1 = fmaf(a.y, b1.y, acc1);
                acc0 = fmaf(a.z, b2.x, acc0); acc1 = fmaf(a.z, b2.y, acc1);
                acc0 = fmaf(a.w, b3.x, acc0); acc1 = fmaf(a.w, b3.y, acc1);
            } else {
                acc0 = fmaf(a.x, Bs[kk][c2],     acc0);
                acc1 = fmaf(a.y, Bs[kk + 1][c2], acc1);
                acc0 = fmaf(a.z, Bs[kk + 2][c2], acc0);
                acc1 = fmaf(a.w, Bs[kk + 3][c2], acc1);
            }
        }
        __syncthreads();
    }
    if (COLS == 16) acc0 += acc1;

    const int R = R0 + r;

    if (PH == 0) {        // ur0 = sigmoid(acc + X0[u|r])
        int cgl = cb + 2 * c2;
        const float* x = g_X0 + (t * BB + R) * 1536 + cgl;
        float2 o;
        o.x = sigmoidf(acc0 + x[0]);
        o.y = sigmoidf(acc1 + x[1]);
        *reinterpret_cast<float2*>(g_ur0 + R * 1024 + cgl) = o;
    } else if (PH == 1) { // h0' = u*h0 + (1-u)*tanh(acc + X0[c])
        int cgl = cb + c2;
        float x = g_X0[(t * BB + R) * 1536 + 1024 + cgl];
        float u = __ldcg(g_ur0 + R * 1024 + cgl);
        float p = __ldcg(h0c + R * HH + cgl);
        float hh = tanhf(acc0 + x);
        h0n[R * HH + cgl] = u * p + (1.f - u) * hh;
    } else if (PH == 2) { // ur1 = sigmoid(acc + bur1)
        int cgl = cb + 2 * c2;
        float2 o;
        o.x = sigmoidf(acc0 + g_bur1[cgl]);
        o.y = sigmoidf(acc1 + g_bur1[cgl + 1]);
        *reinterpret_cast<float2*>(g_ur1 + R * 1024 + cgl) = o;
    } else {              // h1' = u*h1 + (1-u)*tanh(acc + bc1); also H1[t]
        int cgl = cb + c2;
        float u = __ldcg(g_ur1 + R * 1024 + cgl);
        float p = __ldcg(h1c + R * HH + cgl);
        float hh = tanhf(acc0 + bc1[cgl]);
        float v = u * p + (1.f - u) * hh;
        h1n[R * HH + cgl] = v;
        g_H1[(t * BB + R) * HH + cgl] = v;
    }
}

__global__ void __launch_bounds__(512, 1) k_recurrence(
    const float* __restrict__ Wc0, const float* __restrict__ Wc1,
    const float* __restrict__ bc1)
{
    __shared__ float As[32][68];
    __shared__ float Bs[64][36];
    const int tid = threadIdx.x, blk = blockIdx.x;
    const int grp = blk >> 5, ct = blk & 31;
    int ep = 0;

    // zero this group's rows of h0[0], h1[0]
    {
        int off = grp * 16384 + ct * 512 + tid;
        g_h0[0][off] = 0.f;
        g_h1[0][off] = 0.f;
    }
    gbarg(grp, ct, ++ep);

    for (int t = 0; t < TT; t++) {
        const int cur = t & 1;
        const float* h0c = g_h0[cur];
        float*       h0n = g_h0[cur ^ 1];
        const float* h1c = g_h1[cur];
        float*       h1n = g_h1[cur ^ 1];

        run_phase<0, 32,  512>(As, Bs, t, grp, ct, h0c, h0n, h1c, h1n, g_WA, 1024, bc1);
        gbarg(grp, ct, ++ep);
        run_phase<1, 16,  512>(As, Bs, t, grp, ct, h0c, h0n, h1c, h1n, Wc0, 512, bc1);
        gbarg(grp, ct, ++ep);
        run_phase<2, 32, 1024>(As, Bs, t, grp, ct, h0c, h0n, h1c, h1n, g_WC, 1024, bc1);
        gbarg(grp, ct, ++ep);
        run_phase<3, 16, 1024>(As, Bs, t, grp, ct, h0c, h0n, h1c, h1n, Wc1, 512, bc1);
        if (t != TT - 1) gbarg(grp, ct, ++ep);
    }
}

// ---------------- precompute X0 ----------------
__global__ void __launch_bounds__(256) k_precompute(
    const int* __restrict__ tokens, const float* __restrict__ emb,
    const float* __restrict__ Wu0, const float* __restrict__ Wr0, const float* __restrict__ Wc0,
    const float* __restrict__ bu0, const float* __restrict__ br0, const float* __restrict__ bc0)
{
    __shared__ float As[64][17];
    __shared__ float Bs[16][64];
    const int tid = threadIdx.x;
    const int mBase = blockIdx.y * 64;
    const int nBase = blockIdx.x * 64;
    const int region = nBase >> 9;
    const float* Bw   = (region == 0) ? Wu0 : (region == 1) ? Wr0 : Wc0;
    const float* bias = (region == 0) ? bu0 : (region == 1) ? br0 : bc0;
    const int row0 = (region == 2) ? 512 : 0;
    const int nOff = nBase - region * 512;

    const int r0 = tid >> 4, c0 = tid & 15;
    const int rl = tid >> 4, kl = tid & 15;
    int tok[4]; int bidx[4];
#pragma unroll
    for (int i = 0; i < 4; i++) {
        int m = mBase + rl + 16 * i;
        bidx[i] = m & 127;
        tok[i] = tokens[bidx[i] * TT + (m >> 7)];
    }

    float acc[4][4];
#pragma unroll
    for (int i = 0; i < 4; i++)
#pragma unroll
        for (int j = 0; j < 4; j++) acc[i][j] = 0.f;

    for (int k0 = 0; k0 < IN0; k0 += 16) {
        int kabs = k0 + kl;
#pragma unroll
        for (int i = 0; i < 4; i++) {
            float v = (kabs < 512) ? emb[(size_t)tok[i] * EE + kabs]
                                   : g_p[bidx[i] * MAPS + (kabs - 512)];
            As[rl + 16 * i][kl] = v;
        }
#pragma unroll
        for (int i = 0; i < 4; i++) {
            int e = tid + i * 256;
            int kk = e >> 6, n = e & 63;
            Bs[kk][n] = Bw[(row0 + k0 + kk) * HH + nOff + n];
        }
        __syncthreads();
#pragma unroll
        for (int kk = 0; kk < 16; kk++) {
            float a0 = As[r0][kk], a1 = As[r0 + 16][kk], a2 = As[r0 + 32][kk], a3 = As[r0 + 48][kk];
            float b0 = Bs[kk][c0], b1 = Bs[kk][c0 + 16], b2 = Bs[kk][c0 + 32], b3 = Bs[kk][c0 + 48];
            acc[0][0] += a0 * b0; acc[0][1] += a0 * b1; acc[0][2] += a0 * b2; acc[0][3] += a0 * b3;
            acc[1][0] += a1 * b0; acc[1][1] += a1 * b1; acc[1][2] += a1 * b2; acc[1][3] += a1 * b3;
            acc[2][0] += a2 * b0; acc[2][1] += a2 * b1; acc[2][2] += a2 * b2; acc[2][3] += a2 * b3;
            acc[3][0] += a3 * b0; acc[3][1] += a3 * b1; acc[3][2] += a3 * b2; acc[3][3] += a3 * b3;
        }
        __syncthreads();
    }
#pragma unroll
    for (int i = 0; i < 4; i++) {
        int m = mBase + r0 + 16 * i;
#pragma unroll
        for (int j = 0; j < 4; j++) {
            int nl = nOff + c0 + 16 * j;
            g_X0[m * 1536 + nBase + c0 + 16 * j] = acc[i][j] + bias[nl];
        }
    }
}

// ---------------- logits ----------------
__global__ void __launch_bounds__(256) k_logits(const float* __restrict__ Wout,
                                                const float* __restrict__ bout,
                                                float* __restrict__ out)
{
    __shared__ float As[64][17];
    __shared__ float Bs[16][64];
    const int tid = threadIdx.x;
    const int mBase = blockIdx.y * 64;
    const int nBase = blockIdx.x * 64;
    const int r0 = tid >> 4, c0 = tid & 15;
    const int rl = tid >> 4, kl = tid & 15;

    float acc[4][4];
#pragma unroll
    for (int i = 0; i < 4; i++)
#pragma unroll
        for (int j = 0; j < 4; j++) acc[i][j] = 0.f;

    for (int k0 = 0; k0 < HH; k0 += 16) {
#pragma unroll
        for (int i = 0; i < 4; i++)
            As[rl + 16 * i][kl] = g_H1[(mBase + rl + 16 * i) * HH + k0 + kl];
#pragma unroll
        for (int i = 0; i < 4; i++) {
            int e = tid + i * 256;
            int kk = e >> 6, n = e & 63;
            int col = nBase + n;
            Bs[kk][n] = (col < VV) ? Wout[(k0 + kk) * VV + col] : 0.f;
        }
        __syncthreads();
#pragma unroll
        for (int kk = 0; kk < 16; kk++) {
            float a0 = As[r0][kk], a1 = As[r0 + 16][kk], a2 = As[r0 + 32][kk], a3 = As[r0 + 48][kk];
            float b0 = Bs[kk][c0], b1 = Bs[kk][c0 + 16], b2 = Bs[kk][c0 + 32], b3 = Bs[kk][c0 + 48];
            acc[0][0] += a0 * b0; acc[0][1] += a0 * b1; acc[0][2] += a0 * b2; acc[0][3] += a0 * b3;
            acc[1][0] += a1 * b0; acc[1][1] += a1 * b1; acc[1][2] += a1 * b2; acc[1][3] += a1 * b3;
            acc[2][0] += a2 * b0; acc[2][1] += a2 * b1; acc[2][2] += a2 * b2; acc[2][3] += a2 * b3;
            acc[3][0] += a3 * b0; acc[3][1] += a3 * b1; acc[3][2] += a3 * b2; acc[3][3] += a3 * b3;
        }
        __syncthreads();
    }
#pragma unroll
    for (int i = 0; i < 4; i++) {
        int m = mBase + r0 + 16 * i;
        int tIdx = m >> 7, b = m & 127;
        size_t rowOff = ((size_t)b * TT + tIdx) * VV;
#pragma unroll
        for (int j = 0; j < 4; j++) {
            int col = nBase + c0 + 16 * j;
            if (col < VV) out[rowOff + col] = acc[i][j] + bout[col];
        }
    }
}

__global__ void k_hidden(float* __restrict__ outh) {
    int i = blockIdx.x * blockDim.x + threadIdx.x;
    if (i < BB * HH) {
        outh[i]           = g_h0[1][i];
        outh[BB * HH + i] = g_h1[1][i];
    }
}

// ---------------- launch ----------------
extern "C" void kernel_launch(void* const* d_in, const int* in_sizes, int n_in,
                              void* d_out, int out_size) {
    const int*   tokens = (const int*)d_in[0];     // int32 (JAX x64 disabled)
    const float* cnn  = (const float*)d_in[1];
    const float* emb  = (const float*)d_in[2];
    const float* Win  = (const float*)d_in[3];
    const float* bin  = (const float*)d_in[4];
    const float* Wout = (const float*)d_in[5];
    const float* bout = (const float*)d_in[6];
    const float* Wu0  = (const float*)d_in[7];
    const float* bu0  = (const float*)d_in[8];
    const float* Wr0  = (const float*)d_in[9];
    const float* br0  = (const float*)d_in[10];
    const float* Wc0  = (const float*)d_in[11];
    const float* bc0  = (const float*)d_in[12];
    const float* Wu1  = (const float*)d_in[13];
    const float* bu1  = (const float*)d_in[14];
    const float* Wr1  = (const float*)d_in[15];
    const float* br1  = (const float*)d_in[16];
    const float* Wc1  = (const float*)d_in[17];
    const float* bc1  = (const float*)d_in[18];
    float* out = (float*)d_out;

    long long packN = 512LL * 1024 + 1024LL * 1024 + 1024;
    k_pack<<<(int)((packN + 255) / 256), 256>>>(Wu0, Wr0, Wu1, Wr1, bu1, br1);

    small_gemm<NFE, OpP><<<dim3(MAPS / 32, BB / 32), 256>>>(OpP{cnn, Win, bin});

    k_precompute<<<dim3(1536 / 64, (TT * BB) / 64), 256>>>(tokens, emb, Wu0, Wr0, Wc0, bu0, br0, bc0);

    k_recurrence<<<NBLK, 512>>>(Wc0, Wc1, bc1);

    k_logits<<<dim3((VV + 63) / 64, (TT * BB) / 64), 256>>>(Wout, bout, out);

    k_hidden<<<(BB * HH + 255) / 256, 256>>>(out + (size_t)BB * TT * VV);
}

// round 10
// speedup vs baseline: 1.5973x; 1.2412x over previous
#include <cuda_runtime.h>
#include <cuda_bf16.h>
#include <math.h>

#define BB   128
#define TT   25
#define VV   10000
#define EE   512
#define NFE  2048
#define HH   512
#define MAPS 512
#define IN0  1024   // EE + MAPS
#define NBLK 128    // 4 row-groups x 32 col-tiles

#define NPAD 10240  // VV padded to 128
#define KEFF 1536   // 3 x 512 (split-K concat)
#define KCM  48     // K chunks of 32

// ---------------- scratch ----------------
__device__ float g_p[BB * MAPS];
__device__ float g_X0[TT * BB * 1536];
__device__ float g_h0[2][BB * HH];
__device__ float g_h1[2][BB * HH];
__device__ float g_ur0[BB * 1024];
__device__ float g_ur1[BB * 1024];
__device__ float g_H1[TT * BB * HH];
__device__ float g_bur1[1024];

// packed gate weights, ORIGINAL [k][n] layout (coalesced B staging)
__device__ float g_WA[512 * 1024];     // rows k<512 (h-part), cols [u|r] of layer0
__device__ float g_WC[1024 * 1024];    // rows k<1024 ([h0',h1]), cols [u|r] of layer1

// bf16 split operands for HMMA logits (row-major, k contiguous)
__device__ __nv_bfloat16 g_A2[TT * BB * KEFF];    // [Ah | Ah | Al]
__device__ __nv_bfloat16 g_B2[NPAD * KEFF];       // [Bh | Bl | Bh], n-major

// group-local store/load barriers (4 groups x 32 blocks)
__device__ volatile int g_gflags[4][32];
__device__ volatile int g_gepoch[4];

__device__ __forceinline__ float sigmoidf(float x) { return 1.f / (1.f + expf(-x)); }
__device__ __forceinline__ float4 ldcg4(const float* p) {
    return __ldcg(reinterpret_cast<const float4*>(p));
}
__device__ __forceinline__ float4 ldg4(const float* p) {
    return __ldg(reinterpret_cast<const float4*>(p));
}
__device__ __forceinline__ unsigned smem_u32(const void* p) {
    unsigned a;
    asm("{ .reg .u64 t; cvta.to.shared.u64 t, %1; cvt.u32.u64 %0, t; }" : "=r"(a) : "l"(p));
    return a;
}

__device__ __forceinline__ void gbarg(int grp, int ct, int e) {
    __syncthreads();
    if (ct == 0) {
        if (threadIdx.x > 0 && threadIdx.x < 32) {
            while (g_gflags[grp][threadIdx.x] < e) { }
        }
        __syncthreads();
        if (threadIdx.x == 0) {
            __threadfence();
            g_gepoch[grp] = e;
        }
    } else {
        if (threadIdx.x == 0) {
            __threadfence();
            g_gflags[grp][ct] = e;
            while (g_gepoch[grp] < e) { }
            __threadfence();
        }
    }
    __syncthreads();
}

// ---------------- pack ----------------
__global__ void k_pack(const float* __restrict__ Wu0, const float* __restrict__ Wr0,
                       const float* __restrict__ Wu1, const float* __restrict__ Wr1,
                       const float* __restrict__ bu1, const float* __restrict__ br1) {
    long long i = (long long)blockIdx.x * blockDim.x + threadIdx.x;
    if (i < 128) { g_gflags[i >> 5][i & 31] = 0; if ((i & 31) == 0) g_gepoch[i >> 5] = 0; }
    if (i < 512LL * 1024) {
        int k = (int)(i >> 10), n = (int)(i & 1023);
        g_WA[i] = (n < 512) ? Wu0[(IN0 + k) * HH + n] : Wr0[(IN0 + k) * HH + (n - 512)];
        return;
    }
    i -= 512LL * 1024;
    if (i < 1024LL * 1024) {
        int k = (int)(i >> 10), n = (int)(i & 1023);
        g_WC[i] = (n < 512) ? Wu1[k * HH + n] : Wr1[k * HH + (n - 512)];
        return;
    }
    i -= 1024LL * 1024;
    if (i < 1024) g_bur1[i] = (i < 512) ? bu1[i] : br1[i - 512];
}

// ---------------- input layer GEMM ----------------
template <int K, typename Op>
__global__ void __launch_bounds__(256) small_gemm(Op op) {
    __shared__ float As[32][33];
    __shared__ float Bs[32][33];
    const int tid = threadIdx.x;
    const int r0 = tid >> 4;
    const int c0 = tid & 15;
    const int mBase = blockIdx.y * 32;
    const int nBase = blockIdx.x * 32;

    float a00 = 0.f, a01 = 0.f, a10 = 0.f, a11 = 0.f;

    for (int k0 = 0; k0 < K; k0 += 32) {
#pragma unroll
        for (int i = 0; i < 4; i++) {
            int e = tid + i * 256;
            int r = e >> 5, kk = e & 31;
            As[r][kk] = op.loadA(mBase + r, k0 + kk);
        }
#pragma unroll
        for (int i = 0; i < 4; i++) {
            int e = tid + i * 256;
            int kk = e >> 5, n = e & 31;
            Bs[kk][n] = op.loadB(k0 + kk, nBase + n);
        }
        __syncthreads();
#pragma unroll
        for (int kk = 0; kk < 32; kk++) {
            float x0 = As[r0][kk],      x1 = As[r0 + 16][kk];
            float y0 = Bs[kk][c0],      y1 = Bs[kk][c0 + 16];
            a00 += x0 * y0; a01 += x0 * y1;
            a10 += x1 * y0; a11 += x1 * y1;
        }
        __syncthreads();
    }
    op.store(mBase + r0,      nBase + c0,      a00);
    op.store(mBase + r0,      nBase + c0 + 16, a01);
    op.store(mBase + r0 + 16, nBase + c0,      a10);
    op.store(mBase + r0 + 16, nBase + c0 + 16, a11);
}

struct OpP {
    const float* A; const float* Bw; const float* bias;
    __device__ float loadA(int r, int k) const { return A[r * NFE + k]; }
    __device__ float loadB(int k, int n) const { return Bw[k * MAPS + n]; }
    __device__ void store(int r, int n, float acc) const {
        float v = acc + bias[n];
        g_p[r * MAPS + n] = v > 0.f ? v : 0.01f * v;
    }
};

// ---------------- persistent recurrence (unchanged from R8) ----------------
template <int PH, int COLS, int KTOT>
__device__ __forceinline__ void run_phase(
    float As[32][68], float Bs[64][36], int t, int grp, int ct,
    const float* h0c, float* h0n, const float* h1c, float* h1n,
    const float* __restrict__ Wg, int Wstride,
    const float* __restrict__ bc1)
{
    const int tid = threadIdx.x;
    const int r = tid >> 4, c2 = tid & 15;
    const int R0 = grp * 32;
    const int cb = ct * COLS;

    const int sr = tid >> 4;
    const int sk4 = (tid & 15) << 2;
    int bk, bn; bool bAct;
    if (COLS == 32) { bk = tid >> 3; bn = (tid & 7) << 2; bAct = true; }
    else            { bk = tid >> 2; bn = (tid & 3) << 2; bAct = (tid < 256); }

    float acc0 = 0.f, acc1 = 0.f;

    auto loadA4 = [&](int ka) -> float4 {
        int rr = R0 + sr;
        if (PH == 0) {
            return ldcg4(h0c + rr * HH + ka);
        } else if (PH == 1) {
            float4 u = ldcg4(g_ur0 + rr * 1024 + 512 + ka);
            float4 h = ldcg4(h0c + rr * HH + ka);
            return make_float4(u.x * h.x, u.y * h.y, u.z * h.z, u.w * h.w);
        } else if (PH == 2) {
            return (ka < 512) ? ldcg4(h0n + rr * HH + ka)
                              : ldcg4(h1c + rr * HH + (ka - 512));
        } else {
            if (ka < 512) {
                float4 u = ldcg4(g_ur1 + rr * 1024 + 512 + ka);
                float4 h = ldcg4(h1c + rr * HH + ka);
                return make_float4(u.x * h.x, u.y * h.y, u.z * h.z, u.w * h.w);
            }
            return ldcg4(h0n + rr * HH + (ka - 512));
        }
    };

    float4 va = loadA4(sk4);
    float4 vb;
    if (bAct) vb = ldg4(Wg + bk * Wstride + cb + bn);

    for (int k0 = 0; k0 < KTOT; k0 += 64) {
        *reinterpret_cast<float4*>(&As[sr][sk4]) = va;
        if (bAct) *reinterpret_cast<float4*>(&Bs[bk][bn]) = vb;
        __syncthreads();

        if (k0 + 64 < KTOT) {
            va = loadA4(k0 + 64 + sk4);
            if (bAct) vb = ldg4(Wg + (k0 + 64 + bk) * Wstride + cb + bn);
        }

#pragma unroll
        for (int kk = 0; kk < 64; kk += 4) {
            float4 a = *reinterpret_cast<const float4*>(&As[r][kk]);
            if (COLS == 32) {
                float2 b0 = *reinterpret_cast<const float2*>(&Bs[kk][2 * c2]);
                float2 b1 = *reinterpret_cast<const float2*>(&Bs[kk + 1][2 * c2]);
                float2 b2 = *reinterpret_cast<const float2*>(&Bs[kk + 2][2 * c2]);
                float2 b3 = *reinterpret_cast<const float2*>(&Bs[kk + 3][2 * c2]);
                acc0 = fmaf(a.x, b0.x, acc0); acc1 = fmaf(a.x, b0.y, acc1);
                acc0 = fmaf(a.y, b1.x, acc0); acc1 = fmaf(a.y, b1.y, acc1);
                acc0 = fmaf(a.z, b2.x, acc0); acc1 = fmaf(a.z, b2.y, acc1);
                acc0 = fmaf(a.w, b3.x, acc0); acc1 = fmaf(a.w, b3.y, acc1);
            } else {
                acc0 = fmaf(a.x, Bs[kk][c2],     acc0);
                acc1 = fmaf(a.y, Bs[kk + 1][c2], acc1);
                acc0 = fmaf(a.z, Bs[kk + 2][c2], acc0);
                acc1 = fmaf(a.w, Bs[kk + 3][c2], acc1);
            }
        }
        __syncthreads();
    }
    if (COLS == 16) acc0 += acc1;

    const int R = R0 + r;

    if (PH == 0) {
        int cgl = cb + 2 * c2;
        const float* x = g_X0 + (t * BB + R) * 1536 + cgl;
        float2 o;
        o.x = sigmoidf(acc0 + x[0]);
        o.y = sigmoidf(acc1 + x[1]);
        *reinterpret_cast<float2*>(g_ur0 + R * 1024 + cgl) = o;
    } else if (PH == 1) {
        int cgl = cb + c2;
        float x = g_X0[(t * BB + R) * 1536 + 1024 + cgl];
        float u = __ldcg(g_ur0 + R * 1024 + cgl);
        float p = __ldcg(h0c + R * HH + cgl);
        float hh = tanhf(acc0 + x);
        h0n[R * HH + cgl] = u * p + (1.f - u) * hh;
    } else if (PH == 2) {
        int cgl = cb + 2 * c2;
        float2 o;
        o.x = sigmoidf(acc0 + g_bur1[cgl]);
        o.y = sigmoidf(acc1 + g_bur1[cgl + 1]);
        *reinterpret_cast<float2*>(g_ur1 + R * 1024 + cgl) = o;
    } else {
        int cgl = cb + c2;
        float u = __ldcg(g_ur1 + R * 1024 + cgl);
        float p = __ldcg(h1c + R * HH + cgl);
        float hh = tanhf(acc0 + bc1[cgl]);
        float v = u * p + (1.f - u) * hh;
        h1n[R * HH + cgl] = v;
        g_H1[(t * BB + R) * HH + cgl] = v;
    }
}

__global__ void __launch_bounds__(512, 1) k_recurrence(
    const float* __restrict__ Wc0, const float* __restrict__ Wc1,
    const float* __restrict__ bc1)
{
    __shared__ float As[32][68];
    __shared__ float Bs[64][36];
    const int tid = threadIdx.x, blk = blockIdx.x;
    const int grp = blk >> 5, ct = blk & 31;
    int ep = 0;

    {
        int off = grp * 16384 + ct * 512 + tid;
        g_h0[0][off] = 0.f;
        g_h1[0][off] = 0.f;
    }
    gbarg(grp, ct, ++ep);

    for (int t = 0; t < TT; t++) {
        const int cur = t & 1;
        const float* h0c = g_h0[cur];
        float*       h0n = g_h0[cur ^ 1];
        const float* h1c = g_h1[cur];
        float*       h1n = g_h1[cur ^ 1];

        run_phase<0, 32,  512>(As, Bs, t, grp, ct, h0c, h0n, h1c, h1n, g_WA, 1024, bc1);
        gbarg(grp, ct, ++ep);
        run_phase<1, 16,  512>(As, Bs, t, grp, ct, h0c, h0n, h1c, h1n, Wc0, 512, bc1);
        gbarg(grp, ct, ++ep);
        run_phase<2, 32, 1024>(As, Bs, t, grp, ct, h0c, h0n, h1c, h1n, g_WC, 1024, bc1);
        gbarg(grp, ct, ++ep);
        run_phase<3, 16, 1024>(As, Bs, t, grp, ct, h0c, h0n, h1c, h1n, Wc1, 512, bc1);
        if (t != TT - 1) gbarg(grp, ct, ++ep);
    }
}

// ---------------- precompute X0 ----------------
__global__ void __launch_bounds__(256) k_precompute(
    const int* __restrict__ tokens, const float* __restrict__ emb,
    const float* __restrict__ Wu0, const float* __restrict__ Wr0, const float* __restrict__ Wc0,
    const float* __restrict__ bu0, const float* __restrict__ br0, const float* __restrict__ bc0)
{
    __shared__ float As[64][17];
    __shared__ float Bs[16][64];
    const int tid = threadIdx.x;
    const int mBase = blockIdx.y * 64;
    const int nBase = blockIdx.x * 64;
    const int region = nBase >> 9;
    const float* Bw   = (region == 0) ? Wu0 : (region == 1) ? Wr0 : Wc0;
    const float* bias = (region == 0) ? bu0 : (region == 1) ? br0 : bc0;
    const int row0 = (region == 2) ? 512 : 0;
    const int nOff = nBase - region * 512;

    const int r0 = tid >> 4, c0 = tid & 15;
    const int rl = tid >> 4, kl = tid & 15;
    int tok[4]; int bidx[4];
#pragma unroll
    for (int i = 0; i < 4; i++) {
        int m = mBase + rl + 16 * i;
        bidx[i] = m & 127;
        tok[i] = tokens[bidx[i] * TT + (m >> 7)];
    }

    float acc[4][4];
#pragma unroll
    for (int i = 0; i < 4; i++)
#pragma unroll
        for (int j = 0; j < 4; j++) acc[i][j] = 0.f;

    for (int k0 = 0; k0 < IN0; k0 += 16) {
        int kabs = k0 + kl;
#pragma unroll
        for (int i = 0; i < 4; i++) {
            float v = (kabs < 512) ? emb[(size_t)tok[i] * EE + kabs]
                                   : g_p[bidx[i] * MAPS + (kabs - 512)];
            As[rl + 16 * i][kl] = v;
        }
#pragma unroll
        for (int i = 0; i < 4; i++) {
            int e = tid + i * 256;
            int kk = e >> 6, n = e & 63;
            Bs[kk][n] = Bw[(row0 + k0 + kk) * HH + nOff + n];
        }
        __syncthreads();
#pragma unroll
        for (int kk = 0; kk < 16; kk++) {
            float a0 = As[r0][kk], a1 = As[r0 + 16][kk], a2 = As[r0 + 32][kk], a3 = As[r0 + 48][kk];
            float b0 = Bs[kk][c0], b1 = Bs[kk][c0 + 16], b2 = Bs[kk][c0 + 32], b3 = Bs[kk][c0 + 48];
            acc[0][0] += a0 * b0; acc[0][1] += a0 * b1; acc[0][2] += a0 * b2; acc[0][3] += a0 * b3;
            acc[1][0] += a1 * b0; acc[1][1] += a1 * b1; acc[1][2] += a1 * b2; acc[1][3] += a1 * b3;
            acc[2][0] += a2 * b0; acc[2][1] += a2 * b1; acc[2][2] += a2 * b2; acc[2][3] += a2 * b3;
            acc[3][0] += a3 * b0; acc[3][1] += a3 * b1; acc[3][2] += a3 * b2; acc[3][3] += a3 * b3;
        }
        __syncthreads();
    }
#pragma unroll
    for (int i = 0; i < 4; i++) {
        int m = mBase + r0 + 16 * i;
#pragma unroll
        for (int j = 0; j < 4; j++) {
            int nl = nOff + c0 + 16 * j;
            g_X0[m * 1536 + nBase + c0 + 16 * j] = acc[i][j] + bias[nl];
        }
    }
}

// ---------------- bf16 split preps ----------------
// A2[m][0:512]=Ah, [512:1024]=Ah, [1024:1536]=Al  (row-major, k contiguous)
__global__ void __launch_bounds__(256) k_cvtA() {
    const int m = blockIdx.x;
    const int tid = threadIdx.x;
    __nv_bfloat16* dst = g_A2 + (size_t)m * KEFF;
#pragma unroll
    for (int i = 0; i < 2; i++) {
        int k = tid + i * 256;
        float a = g_H1[m * HH + k];
        __nv_bfloat16 ah = __float2bfloat16(a);
        __nv_bfloat16 al = __float2bfloat16(a - __bfloat162float(ah));
        dst[k]        = ah;
        dst[512 + k]  = ah;
        dst[1024 + k] = al;
    }
}

// B2[n][0:512]=Bh, [512:1024]=Bl, [1024:1536]=Bh  (n-major; transposes Wout [k][n])
__global__ void __launch_bounds__(256) k_cvtB(const float* __restrict__ Wout) {
    __shared__ float f[32][33];
    const int ntile = blockIdx.x;      // 0..319
    const int ktile = blockIdx.y;      // 0..15
    const int tid = threadIdx.x;
    const int tr = tid >> 5, tc = tid & 31;
#pragma unroll
    for (int i = 0; i < 4; i++) {
        int kk = ktile * 32 + tr + i * 8;
        int n = ntile * 32 + tc;
        f[tr + i * 8][tc] = (n < VV) ? Wout[kk * VV + n] : 0.f;
    }
    __syncthreads();
#pragma unroll
    for (int i = 0; i < 4; i++) {
        int n = ntile * 32 + tr + i * 8;
        int kk = ktile * 32 + tc;
        float w = f[tc][tr + i * 8];
        __nv_bfloat16 bh = __float2bfloat16(w);
        __nv_bfloat16 bl = __float2bfloat16(w - __bfloat162float(bh));
        __nv_bfloat16* dst = g_B2 + (size_t)n * KEFF;
        dst[kk]        = bh;
        dst[512 + kk]  = bl;
        dst[1024 + kk] = bh;
    }
}

// ---------------- HMMA logits: D = A2 @ B2^T via mma.sync bf16 ----------------
// CTA 128x128, 8 warps as 2(m) x 4(n); warp tile 64x32 (4 m-frags x 4 n-frags).
// K chunks of 32, double-buffered smem (row stride 40 bf16 = 80B -> conflict-free ldmatrix).
__global__ void __launch_bounds__(256) k_logits_mma(const float* __restrict__ bout,
                                                    float* __restrict__ out)
{
    __shared__ __align__(16) __nv_bfloat16 sA[2][128 * 40];
    __shared__ __align__(16) __nv_bfloat16 sB[2][128 * 40];
    const int tid = threadIdx.x;
    const int nt = blockIdx.x, mt = blockIdx.y;
    const int warp = tid >> 5, lane = tid & 31;
    const int wm = warp >> 2, wn = warp & 3;

    float acc[4][4][4];
#pragma unroll
    for (int a = 0; a < 4; a++)
#pragma unroll
        for (int b = 0; b < 4; b++)
#pragma unroll
            for (int c = 0; c < 4; c++) acc[a][b][c] = 0.f;

    const __nv_bfloat16* gA = g_A2 + (size_t)(mt * 128) * KEFF;
    const __nv_bfloat16* gB = g_B2 + (size_t)(nt * 128) * KEFF;

    // staging: 512 x 16B segments each for A and B; thread handles 2 of each
    uint4 pa[2], pb[2];
#pragma unroll
    for (int i = 0; i < 2; i++) {
        int s = tid + i * 256, r = s >> 2, sg = s & 3;
        pa[i] = *reinterpret_cast<const uint4*>(gA + (size_t)r * KEFF + sg * 8);
        pb[i] = *reinterpret_cast<const uint4*>(gB + (size_t)r * KEFF + sg * 8);
    }

    for (int kc = 0; kc < KCM; kc++) {
        int buf = kc & 1;
#pragma unroll
        for (int i = 0; i < 2; i++) {
            int s = tid + i * 256, r = s >> 2, sg = s & 3;
            *reinterpret_cast<uint4*>(&sA[buf][r * 40 + sg * 8]) = pa[i];
            *reinterpret_cast<uint4*>(&sB[buf][r * 40 + sg * 8]) = pb[i];
        }
        __syncthreads();

        if (kc + 1 < KCM) {
            int k0 = (kc + 1) * 32;
#pragma unroll
            for (int i = 0; i < 2; i++) {
                int s = tid + i * 256, r = s >> 2, sg = s & 3;
                pa[i] = *reinterpret_cast<const uint4*>(gA + (size_t)r * KEFF + k0 + sg * 8);
                pb[i] = *reinterpret_cast<const uint4*>(gB + (size_t)r * KEFF + k0 + sg * 8);
            }
        }

        unsigned sAb = smem_u32(sA[buf]);
        unsigned sBb = smem_u32(sB[buf]);
#pragma unroll
        for (int kf = 0; kf < 2; kf++) {
            unsigned a[4][4], b[4][2];
#pragma unroll
            for (int mf = 0; mf < 4; mf++) {
                int r = wm * 64 + mf * 16 + (lane & 15);
                unsigned addr = sAb + r * 80 + kf * 32 + (lane >> 4) * 16;
                asm volatile("ldmatrix.sync.aligned.m8n8.x4.shared.b16 {%0,%1,%2,%3}, [%4];"
                             : "=r"(a[mf][0]), "=r"(a[mf][1]), "=r"(a[mf][2]), "=r"(a[mf][3])
                             : "r"(addr));
            }
#pragma unroll
            for (int nf = 0; nf < 4; nf++) {
                int n = wn * 32 + nf * 8 + (lane & 7);
                unsigned addr = sBb + n * 80 + kf * 32 + ((lane >> 3) & 1) * 16;
                asm volatile("ldmatrix.sync.aligned.m8n8.x2.shared.b16 {%0,%1}, [%2];"
                             : "=r"(b[nf][0]), "=r"(b[nf][1])
                             : "r"(addr));
            }
#pragma unroll
            for (int mf = 0; mf < 4; mf++)
#pragma unroll
                for (int nf = 0; nf < 4; nf++) {
                    asm volatile(
                        "mma.sync.aligned.m16n8k16.row.col.f32.bf16.bf16.f32 "
                        "{%0,%1,%2,%3}, {%4,%5,%6,%7}, {%8,%9}, {%0,%1,%2,%3};"
                        : "+f"(acc[mf][nf][0]), "+f"(acc[mf][nf][1]),
                          "+f"(acc[mf][nf][2]), "+f"(acc[mf][nf][3])
                        : "r"(a[mf][0]), "r"(a[mf][1]), "r"(a[mf][2]), "r"(a[mf][3]),
                          "r"(b[nf][0]), "r"(b[nf][1]));
                }
        }
        __syncthreads();
    }

    // epilogue: c frag (m16n8): thread(gID=lane>>2, tig=lane&3):
    //   {c0,c1} -> row gID,   cols 2*tig, 2*tig+1
    //   {c2,c3} -> row gID+8, same cols
    const int gID = lane >> 2, tig = lane & 3;
#pragma unroll
    for (int mf = 0; mf < 4; mf++) {
#pragma unroll
        for (int half = 0; half < 2; half++) {
            int gm = mt * 128 + wm * 64 + mf * 16 + gID + half * 8;
            int tt = gm >> 7, bb = gm & 127;
            float* orow = out + ((size_t)bb * TT + tt) * VV;
#pragma unroll
            for (int nf = 0; nf < 4; nf++) {
                int n = nt * 128 + wn * 32 + nf * 8 + tig * 2;
                float v0 = acc[mf][nf][half * 2 + 0];
                float v1 = acc[mf][nf][half * 2 + 1];
                if (n + 1 < VV) {
                    float2 o = make_float2(v0 + bout[n], v1 + bout[n + 1]);
                    *reinterpret_cast<float2*>(orow + n) = o;
                } else if (n < VV) {
                    orow[n] = v0 + bout[n];
                }
            }
        }
    }
}

__global__ void k_hidden(float* __restrict__ outh) {
    int i = blockIdx.x * blockDim.x + threadIdx.x;
    if (i < BB * HH) {
        outh[i]           = g_h0[1][i];
        outh[BB * HH + i] = g_h1[1][i];
    }
}

// ---------------- launch ----------------
extern "C" void kernel_launch(void* const* d_in, const int* in_sizes, int n_in,
                              void* d_out, int out_size) {
    const int*   tokens = (const int*)d_in[0];     // int32 (JAX x64 disabled)
    const float* cnn  = (const float*)d_in[1];
    const float* emb  = (const float*)d_in[2];
    const float* Win  = (const float*)d_in[3];
    const float* bin  = (const float*)d_in[4];
    const float* Wout = (const float*)d_in[5];
    const float* bout = (const float*)d_in[6];
    const float* Wu0  = (const float*)d_in[7];
    const float* bu0  = (const float*)d_in[8];
    const float* Wr0  = (const float*)d_in[9];
    const float* br0  = (const float*)d_in[10];
    const float* Wc0  = (const float*)d_in[11];
    const float* bc0  = (const float*)d_in[12];
    const float* Wu1  = (const float*)d_in[13];
    const float* bu1  = (const float*)d_in[14];
    const float* Wr1  = (const float*)d_in[15];
    const float* br1  = (const float*)d_in[16];
    const float* Wc1  = (const float*)d_in[17];
    const float* bc1  = (const float*)d_in[18];
    float* out = (float*)d_out;

    long long packN = 512LL * 1024 + 1024LL * 1024 + 1024;
    k_pack<<<(int)((packN + 255) / 256), 256>>>(Wu0, Wr0, Wu1, Wr1, bu1, br1);

    small_gemm<NFE, OpP><<<dim3(MAPS / 32, BB / 32), 256>>>(OpP{cnn, Win, bin});

    k_precompute<<<dim3(1536 / 64, (TT * BB) / 64), 256>>>(tokens, emb, Wu0, Wr0, Wc0, bu0, br0, bc0);

    // convert Wout while recurrence runs ahead in the stream
    k_cvtB<<<dim3(NPAD / 32, 512 / 32), 256>>>(Wout);

    k_recurrence<<<NBLK, 512>>>(Wc0, Wc1, bc1);

    // H1 -> bf16 split, then HMMA logits
    k_cvtA<<<TT * BB, 256>>>();
    k_logits_mma<<<dim3(NPAD / 128, (TT * BB) / 128), 256>>>(bout, out);

    k_hidden<<<(BB * HH + 255) / 256, 256>>>(out + (size_t)BB * TT * VV);
}

// round 11
// speedup vs baseline: 2.2983x; 1.4389x over previous
#include <cuda_runtime.h>
#include <cuda_bf16.h>
#include <math.h>

#define BB   128
#define TT   25
#define VV   10000
#define EE   512
#define NFE  2048
#define HH   512
#define MAPS 512
#define IN0  1024   // EE + MAPS
#define NBLK 128    // 4 row-groups x 32 col-tiles

#define NPAD 10240  // VV padded to 128
#define KEFF 1536   // 3 x 512 (split-K concat) for logits
#define KCM  48     // logits K chunks of 32

// ---------------- scratch ----------------
__device__ float g_p[BB * MAPS];
__device__ float g_X0[TT * BB * 1536];
__device__ float g_h0[2][BB * HH];
__device__ float g_h1[2][BB * HH];
__device__ float g_ur0[BB * 1024];
__device__ float g_ur1[BB * 1024];
__device__ float g_H1[TT * BB * HH];
__device__ float g_bur1[1024];

// bf16 split recurrent weights, n-major [n][K]
__device__ __nv_bfloat16 g_W0h[1024 * 512],  g_W0l[1024 * 512];   // [Wu0_h|Wr0_h]
__device__ __nv_bfloat16 g_W1h[512 * 512],   g_W1l[512 * 512];    // Wc0 h-part
__device__ __nv_bfloat16 g_W2h[1024 * 1024], g_W2l[1024 * 1024];  // [Wu1|Wr1]
__device__ __nv_bfloat16 g_W3h[512 * 1024],  g_W3l[512 * 1024];   // Wc1

// bf16 split operands for HMMA logits (row-major, k contiguous)
__device__ __nv_bfloat16 g_A2[TT * BB * KEFF];    // [Ah | Ah | Al]
__device__ __nv_bfloat16 g_B2[NPAD * KEFF];       // [Bh | Bl | Bh], n-major

// group-local store/load barriers (4 groups x 32 blocks)
__device__ volatile int g_gflags[4][32];
__device__ volatile int g_gepoch[4];

__device__ __forceinline__ float sigmoidf(float x) { return 1.f / (1.f + expf(-x)); }
__device__ __forceinline__ float4 ldcg4(const float* p) {
    return __ldcg(reinterpret_cast<const float4*>(p));
}
__device__ __forceinline__ unsigned smem_u32(const void* p) {
    unsigned a;
    asm("{ .reg .u64 t; cvta.to.shared.u64 t, %1; cvt.u32.u64 %0, t; }" : "=r"(a) : "l"(p));
    return a;
}
__device__ __forceinline__ void ldmx4(unsigned* r, unsigned addr) {
    asm volatile("ldmatrix.sync.aligned.m8n8.x4.shared.b16 {%0,%1,%2,%3}, [%4];"
                 : "=r"(r[0]), "=r"(r[1]), "=r"(r[2]), "=r"(r[3]) : "r"(addr));
}
__device__ __forceinline__ void ldmx2(unsigned* r, unsigned addr) {
    asm volatile("ldmatrix.sync.aligned.m8n8.x2.shared.b16 {%0,%1}, [%2];"
                 : "=r"(r[0]), "=r"(r[1]) : "r"(addr));
}
__device__ __forceinline__ void mma16816(float* acc, const unsigned* a, const unsigned* b) {
    asm volatile(
        "mma.sync.aligned.m16n8k16.row.col.f32.bf16.bf16.f32 "
        "{%0,%1,%2,%3}, {%4,%5,%6,%7}, {%8,%9}, {%0,%1,%2,%3};"
        : "+f"(acc[0]), "+f"(acc[1]), "+f"(acc[2]), "+f"(acc[3])
        : "r"(a[0]), "r"(a[1]), "r"(a[2]), "r"(a[3]), "r"(b[0]), "r"(b[1]));
}

__device__ __forceinline__ void gbarg(int grp, int ct, int e) {
    __syncthreads();
    if (ct == 0) {
        if (threadIdx.x > 0 && threadIdx.x < 32) {
            while (g_gflags[grp][threadIdx.x] < e) { }
        }
        __syncthreads();
        if (threadIdx.x == 0) {
            __threadfence();
            g_gepoch[grp] = e;
        }
    } else {
        if (threadIdx.x == 0) {
            __threadfence();
            g_gflags[grp][ct] = e;
            while (g_gepoch[grp] < e) { }
            __threadfence();
        }
    }
    __syncthreads();
}

// ---------------- pack: barrier reset + bias pack ----------------
__global__ void k_pack(const float* __restrict__ bu1, const float* __restrict__ br1) {
    int i = blockIdx.x * blockDim.x + threadIdx.x;
    if (i < 128) { g_gflags[i >> 5][i & 31] = 0; if ((i & 31) == 0) g_gepoch[i >> 5] = 0; }
    if (i < 1024) g_bur1[i] = (i < 512) ? bu1[i] : br1[i - 512];
}

// ---------------- weight split + transpose (one-time) ----------------
__global__ void __launch_bounds__(256) k_cvtW(
    const float* __restrict__ Wu0, const float* __restrict__ Wr0,
    const float* __restrict__ Wc0, const float* __restrict__ Wu1,
    const float* __restrict__ Wr1, const float* __restrict__ Wc1)
{
    __shared__ float f[32][33];
    const int ph = blockIdx.z;
    const int NN = (ph == 0 || ph == 2) ? 1024 : 512;
    const int KK = (ph >= 2) ? 1024 : 512;
    if ((int)blockIdx.x * 32 >= NN || (int)blockIdx.y * 32 >= KK) return;
    const int tid = threadIdx.x, tr = tid >> 5, tc = tid & 31;
    __nv_bfloat16* Wh = (ph == 0) ? g_W0h : (ph == 1) ? g_W1h : (ph == 2) ? g_W2h : g_W3h;
    __nv_bfloat16* Wl = (ph == 0) ? g_W0l : (ph == 1) ? g_W1l : (ph == 2) ? g_W2l : g_W3l;
#pragma unroll
    for (int i = 0; i < 4; i++) {
        int kk = blockIdx.y * 32 + tr + i * 8;
        int n  = blockIdx.x * 32 + tc;
        float v;
        if (ph == 0)      v = (n < 512) ? Wu0[(IN0 + kk) * HH + n] : Wr0[(IN0 + kk) * HH + (n - 512)];
        else if (ph == 1) v = Wc0[kk * HH + n];
        else if (ph == 2) v = (n < 512) ? Wu1[kk * HH + n] : Wr1[kk * HH + (n - 512)];
        else              v = Wc1[kk * HH + n];
        f[tr + i * 8][tc] = v;
    }
    __syncthreads();
#pragma unroll
    for (int i = 0; i < 4; i++) {
        int n  = blockIdx.x * 32 + tr + i * 8;
        int kk = blockIdx.y * 32 + tc;
        float wv = f[tc][tr + i * 8];
        __nv_bfloat16 bh = __float2bfloat16(wv);
        __nv_bfloat16 bl = __float2bfloat16(wv - __bfloat162float(bh));
        Wh[(size_t)n * KK + kk] = bh;
        Wl[(size_t)n * KK + kk] = bl;
    }
}

// ---------------- input layer GEMM ----------------
template <int K, typename Op>
__global__ void __launch_bounds__(256) small_gemm(Op op) {
    __shared__ float As[32][33];
    __shared__ float Bs[32][33];
    const int tid = threadIdx.x;
    const int r0 = tid >> 4;
    const int c0 = tid & 15;
    const int mBase = blockIdx.y * 32;
    const int nBase = blockIdx.x * 32;

    float a00 = 0.f, a01 = 0.f, a10 = 0.f, a11 = 0.f;

    for (int k0 = 0; k0 < K; k0 += 32) {
#pragma unroll
        for (int i = 0; i < 4; i++) {
            int e = tid + i * 256;
            int r = e >> 5, kk = e & 31;
            As[r][kk] = op.loadA(mBase + r, k0 + kk);
        }
#pragma unroll
        for (int i = 0; i < 4; i++) {
            int e = tid + i * 256;
            int kk = e >> 5, n = e & 31;
            Bs[kk][n] = op.loadB(k0 + kk, nBase + n);
        }
        __syncthreads();
#pragma unroll
        for (int kk = 0; kk < 32; kk++) {
            float x0 = As[r0][kk],      x1 = As[r0 + 16][kk];
            float y0 = Bs[kk][c0],      y1 = Bs[kk][c0 + 16];
            a00 += x0 * y0; a01 += x0 * y1;
            a10 += x1 * y0; a11 += x1 * y1;
        }
        __syncthreads();
    }
    op.store(mBase + r0,      nBase + c0,      a00);
    op.store(mBase + r0,      nBase + c0 + 16, a01);
    op.store(mBase + r0 + 16, nBase + c0,      a10);
    op.store(mBase + r0 + 16, nBase + c0 + 16, a11);
}

struct OpP {
    const float* A; const float* Bw; const float* bias;
    __device__ float loadA(int r, int k) const { return A[r * NFE + k]; }
    __device__ float loadB(int k, int n) const { return Bw[k * MAPS + n]; }
    __device__ void store(int r, int n, float acc) const {
        float v = acc + bias[n];
        g_p[r * MAPS + n] = v > 0.f ? v : 0.01f * v;
    }
};

// ---------------- persistent recurrence via HMMA ----------------
// Block (grp, ct): rows grp*32..+31, cols ct*COLS..+COLS-1 of phase output.
// K chunks of 64; A converted to bf16 hi/lo on the fly; B pre-split in global.
// 16 warps = frag slots (2m x NF n of m16n8) x k-parity within chunk; smem reduce.
template <int PH, int COLS, int KTOT>
__device__ __forceinline__ void run_phase_mma(
    __nv_bfloat16 (*sAh)[72], __nv_bfloat16 (*sAl)[72],
    __nv_bfloat16 (*sBh)[72], __nv_bfloat16 (*sBl)[72],
    float (*red)[32][4],
    int t, int grp, int ct,
    const float* h0c, float* h0n, const float* h1c, float* h1n,
    const __nv_bfloat16* __restrict__ Wh, const __nv_bfloat16* __restrict__ Wl,
    const float* __restrict__ bc1)
{
    const int tid = threadIdx.x;
    const int w = tid >> 5, lane = tid & 31;
    constexpr int F  = COLS / 4;            // frag slots: 8 or 4
    constexpr int KW = 16 / F;              // k-parities: 2 or 4
    constexpr int CH = KTOT / 64;           // chunks
    const int slot = w & (F - 1);
    const int par  = w / F;
    const int mf = (COLS == 32) ? (slot >> 2) : (slot >> 1);
    const int nf = (COLS == 32) ? (slot & 3) : (slot & 1);
    const int R0 = grp * 32;
    const int cb = ct * COLS;

    // staging roles
    const int arow = tid >> 4;              // 0..31
    const int ak4  = (tid & 15) << 2;       // 0..60
    constexpr int HB = COLS * 8;            // uint4 count per B half
    const bool bhAct = tid < HB;
    const bool blAct = (tid >= 256) && (tid < 256 + HB);
    const int bn  = bhAct ? (tid >> 3) : ((tid - 256) >> 3);
    const int bsg = bhAct ? (tid & 7)  : ((tid - 256) & 7);

    float acc[4] = {0.f, 0.f, 0.f, 0.f};

    auto loadA4 = [&](int ka) -> float4 {
        int rr = R0 + arow;
        if (PH == 0) {
            return ldcg4(h0c + rr * HH + ka);
        } else if (PH == 1) {
            float4 u = ldcg4(g_ur0 + rr * 1024 + 512 + ka);
            float4 h = ldcg4(h0c + rr * HH + ka);
            return make_float4(u.x * h.x, u.y * h.y, u.z * h.z, u.w * h.w);
        } else if (PH == 2) {
            return (ka < 512) ? ldcg4(h0n + rr * HH + ka)
                              : ldcg4(h1c + rr * HH + (ka - 512));
        } else {
            if (ka < 512) {
                float4 u = ldcg4(g_ur1 + rr * 1024 + 512 + ka);
                float4 h = ldcg4(h1c + rr * HH + ka);
                return make_float4(u.x * h.x, u.y * h.y, u.z * h.z, u.w * h.w);
            }
            return ldcg4(h0n + rr * HH + (ka - 512));
        }
    };

    float4 va = loadA4(ak4);
    uint4 vb;
    if (bhAct)      vb = *reinterpret_cast<const uint4*>(Wh + (size_t)(cb + bn) * KTOT + bsg * 8);
    else if (blAct) vb = *reinterpret_cast<const uint4*>(Wl + (size_t)(cb + bn) * KTOT + bsg * 8);

    const unsigned baseAh = smem_u32(sAh), baseAl = smem_u32(sAl);
    const unsigned baseBh = smem_u32(sBh), baseBl = smem_u32(sBl);

    for (int c = 0; c < CH; c++) {
        // A: split to hi (fp32 truncation) / lo (rn of residual), store to smem
        {
            unsigned bx = __float_as_uint(va.x), by = __float_as_uint(va.y);
            unsigned bz = __float_as_uint(va.z), bw2 = __float_as_uint(va.w);
            unsigned h01 = __byte_perm(bx, by, 0x7632);
            unsigned h23 = __byte_perm(bz, bw2, 0x7632);
            float lx = va.x - __uint_as_float(bx & 0xFFFF0000u);
            float ly = va.y - __uint_as_float(by & 0xFFFF0000u);
            float lz = va.z - __uint_as_float(bz & 0xFFFF0000u);
            float lw = va.w - __uint_as_float(bw2 & 0xFFFF0000u);
            unsigned l01, l23;
            asm("cvt.rn.bf16x2.f32 %0, %1, %2;" : "=r"(l01) : "f"(ly), "f"(lx));
            asm("cvt.rn.bf16x2.f32 %0, %1, %2;" : "=r"(l23) : "f"(lw), "f"(lz));
            *reinterpret_cast<uint2*>(&sAh[arow][ak4]) = make_uint2(h01, h23);
            *reinterpret_cast<uint2*>(&sAl[arow][ak4]) = make_uint2(l01, l23);
        }
        if (bhAct)      *reinterpret_cast<uint4*>(&sBh[bn][bsg * 8]) = vb;
        else if (blAct) *reinterpret_cast<uint4*>(&sBl[bn][bsg * 8]) = vb;
        __syncthreads();

        if (c + 1 < CH) {
            va = loadA4((c + 1) * 64 + ak4);
            if (bhAct)      vb = *reinterpret_cast<const uint4*>(Wh + (size_t)(cb + bn) * KTOT + (c + 1) * 64 + bsg * 8);
            else if (blAct) vb = *reinterpret_cast<const uint4*>(Wl + (size_t)(cb + bn) * KTOT + (c + 1) * 64 + bsg * 8);
        }

#pragma unroll
        for (int si = 0; si < 4 / KW; si++) {
            int s = par + si * KW;
            unsigned ah[4], al[4], bh[2], bl[2];
            unsigned aoff = (mf * 16 + (lane & 15)) * 144 + s * 32 + (lane >> 4) * 16;
            ldmx4(ah, baseAh + aoff);
            ldmx4(al, baseAl + aoff);
            unsigned boff = (nf * 8 + (lane & 7)) * 144 + s * 32 + ((lane >> 3) & 1) * 16;
            ldmx2(bh, baseBh + boff);
            ldmx2(bl, baseBl + boff);
            mma16816(acc, ah, bh);
            mma16816(acc, ah, bl);
            mma16816(acc, al, bh);
        }
        __syncthreads();
    }

    // cross-parity reduction
    if (par > 0) {
        float* d = red[(par - 1) * F + slot][lane];
        d[0] = acc[0]; d[1] = acc[1]; d[2] = acc[2]; d[3] = acc[3];
    }
    __syncthreads();
    if (par == 0) {
#pragma unroll
        for (int p = 1; p < KW; p++) {
            float* s = red[(p - 1) * F + slot][lane];
            acc[0] += s[0]; acc[1] += s[1]; acc[2] += s[2]; acc[3] += s[3];
        }
        const int gID = lane >> 2, tig = lane & 3;
#pragma unroll
        for (int half = 0; half < 2; half++) {
            int R   = R0 + mf * 16 + gID + half * 8;
            int cgl = cb + nf * 8 + tig * 2;
            float v0 = acc[half * 2], v1 = acc[half * 2 + 1];
            if (PH == 0) {
                const float* x = g_X0 + (t * BB + R) * 1536 + cgl;
                float2 o = make_float2(sigmoidf(v0 + x[0]), sigmoidf(v1 + x[1]));
                *reinterpret_cast<float2*>(g_ur0 + R * 1024 + cgl) = o;
            } else if (PH == 1) {
                const float* x = g_X0 + (t * BB + R) * 1536 + 1024 + cgl;
                float u0 = __ldcg(g_ur0 + R * 1024 + cgl);
                float u1 = __ldcg(g_ur0 + R * 1024 + cgl + 1);
                float p0 = __ldcg(h0c + R * HH + cgl);
                float p1 = __ldcg(h0c + R * HH + cgl + 1);
                float2 o = make_float2(u0 * p0 + (1.f - u0) * tanhf(v0 + x[0]),
                                       u1 * p1 + (1.f - u1) * tanhf(v1 + x[1]));
                *reinterpret_cast<float2*>(h0n + R * HH + cgl) = o;
            } else if (PH == 2) {
                float2 o = make_float2(sigmoidf(v0 + g_bur1[cgl]),
                                       sigmoidf(v1 + g_bur1[cgl + 1]));
                *reinterpret_cast<float2*>(g_ur1 + R * 1024 + cgl) = o;
            } else {
                float u0 = __ldcg(g_ur1 + R * 1024 + cgl);
                float u1 = __ldcg(g_ur1 + R * 1024 + cgl + 1);
                float p0 = __ldcg(h1c + R * HH + cgl);
                float p1 = __ldcg(h1c + R * HH + cgl + 1);
                float2 o = make_float2(u0 * p0 + (1.f - u0) * tanhf(v0 + bc1[cgl]),
                                       u1 * p1 + (1.f - u1) * tanhf(v1 + bc1[cgl + 1]));
                *reinterpret_cast<float2*>(h1n + R * HH + cgl) = o;
                *reinterpret_cast<float2*>(g_H1 + (t * BB + R) * HH + cgl) = o;
            }
        }
    }
}

__global__ void __launch_bounds__(512, 1) k_recurrence(const float* __restrict__ bc1) {
    __shared__ __align__(16) __nv_bfloat16 sAh[32][72];
    __shared__ __align__(16) __nv_bfloat16 sAl[32][72];
    __shared__ __align__(16) __nv_bfloat16 sBh[32][72];
    __shared__ __align__(16) __nv_bfloat16 sBl[32][72];
    __shared__ float red[12][32][4];
    const int tid = threadIdx.x, blk = blockIdx.x;
    const int grp = blk >> 5, ct = blk & 31;
    int ep = 0;

    {
        int off = grp * 16384 + ct * 512 + tid;
        g_h0[0][off] = 0.f;
        g_h1[0][off] = 0.f;
    }
    gbarg(grp, ct, ++ep);

    for (int t = 0; t < TT; t++) {
        const int cur = t & 1;
        const float* h0c = g_h0[cur];
        float*       h0n = g_h0[cur ^ 1];
        const float* h1c = g_h1[cur];
        float*       h1n = g_h1[cur ^ 1];

        run_phase_mma<0, 32,  512>(sAh, sAl, sBh, sBl, red, t, grp, ct,
                                   h0c, h0n, h1c, h1n, g_W0h, g_W0l, bc1);
        gbarg(grp, ct, ++ep);
        run_phase_mma<1, 16,  512>(sAh, sAl, sBh, sBl, red, t, grp, ct,
                                   h0c, h0n, h1c, h1n, g_W1h, g_W1l, bc1);
        gbarg(grp, ct, ++ep);
        run_phase_mma<2, 32, 1024>(sAh, sAl, sBh, sBl, red, t, grp, ct,
                                   h0c, h0n, h1c, h1n, g_W2h, g_W2l, bc1);
        gbarg(grp, ct, ++ep);
        run_phase_mma<3, 16, 1024>(sAh, sAl, sBh, sBl, red, t, grp, ct,
                                   h0c, h0n, h1c, h1n, g_W3h, g_W3l, bc1);
        if (t != TT - 1) gbarg(grp, ct, ++ep);
    }
}

// ---------------- precompute X0 ----------------
__global__ void __launch_bounds__(256) k_precompute(
    const int* __restrict__ tokens, const float* __restrict__ emb,
    const float* __restrict__ Wu0, const float* __restrict__ Wr0, const float* __restrict__ Wc0,
    const float* __restrict__ bu0, const float* __restrict__ br0, const float* __restrict__ bc0)
{
    __shared__ float As[64][17];
    __shared__ float Bs[16][64];
    const int tid = threadIdx.x;
    const int mBase = blockIdx.y * 64;
    const int nBase = blockIdx.x * 64;
    const int region = nBase >> 9;
    const float* Bw   = (region == 0) ? Wu0 : (region == 1) ? Wr0 : Wc0;
    const float* bias = (region == 0) ? bu0 : (region == 1) ? br0 : bc0;
    const int row0 = (region == 2) ? 512 : 0;
    const int nOff = nBase - region * 512;

    const int r0 = tid >> 4, c0 = tid & 15;
    const int rl = tid >> 4, kl = tid & 15;
    int tok[4]; int bidx[4];
#pragma unroll
    for (int i = 0; i < 4; i++) {
        int m = mBase + rl + 16 * i;
        bidx[i] = m & 127;
        tok[i] = tokens[bidx[i] * TT + (m >> 7)];
    }

    float acc[4][4];
#pragma unroll
    for (int i = 0; i < 4; i++)
#pragma unroll
        for (int j = 0; j < 4; j++) acc[i][j] = 0.f;

    for (int k0 = 0; k0 < IN0; k0 += 16) {
        int kabs = k0 + kl;
#pragma unroll
        for (int i = 0; i < 4; i++) {
            float v = (kabs < 512) ? emb[(size_t)tok[i] * EE + kabs]
                                   : g_p[bidx[i] * MAPS + (kabs - 512)];
            As[rl + 16 * i][kl] = v;
        }
#pragma unroll
        for (int i = 0; i < 4; i++) {
            int e = tid + i * 256;
            int kk = e >> 6, n = e & 63;
            Bs[kk][n] = Bw[(row0 + k0 + kk) * HH + nOff + n];
        }
        __syncthreads();
#pragma unroll
        for (int kk = 0; kk < 16; kk++) {
            float a0 = As[r0][kk], a1 = As[r0 + 16][kk], a2 = As[r0 + 32][kk], a3 = As[r0 + 48][kk];
            float b0 = Bs[kk][c0], b1 = Bs[kk][c0 + 16], b2 = Bs[kk][c0 + 32], b3 = Bs[kk][c0 + 48];
            acc[0][0] += a0 * b0; acc[0][1] += a0 * b1; acc[0][2] += a0 * b2; acc[0][3] += a0 * b3;
            acc[1][0] += a1 * b0; acc[1][1] += a1 * b1; acc[1][2] += a1 * b2; acc[1][3] += a1 * b3;
            acc[2][0] += a2 * b0; acc[2][1] += a2 * b1; acc[2][2] += a2 * b2; acc[2][3] += a2 * b3;
            acc[3][0] += a3 * b0; acc[3][1] += a3 * b1; acc[3][2] += a3 * b2; acc[3][3] += a3 * b3;
        }
        __syncthreads();
    }
#pragma unroll
    for (int i = 0; i < 4; i++) {
        int m = mBase + r0 + 16 * i;
#pragma unroll
        for (int j = 0; j < 4; j++) {
            int nl = nOff + c0 + 16 * j;
            g_X0[m * 1536 + nBase + c0 + 16 * j] = acc[i][j] + bias[nl];
        }
    }
}

// ---------------- bf16 split preps for logits ----------------
__global__ void __launch_bounds__(256) k_cvtA() {
    const int m = blockIdx.x;
    const int tid = threadIdx.x;
    __nv_bfloat16* dst = g_A2 + (size_t)m * KEFF;
#pragma unroll
    for (int i = 0; i < 2; i++) {
        int k = tid + i * 256;
        float a = g_H1[m * HH + k];
        __nv_bfloat16 ah = __float2bfloat16(a);
        __nv_bfloat16 al = __float2bfloat16(a - __bfloat162float(ah));
        dst[k]        = ah;
        dst[512 + k]  = ah;
        dst[1024 + k] = al;
    }
}

__global__ void __launch_bounds__(256) k_cvtB(const float* __restrict__ Wout) {
    __shared__ float f[32][33];
    const int ntile = blockIdx.x;
    const int ktile = blockIdx.y;
    const int tid = threadIdx.x;
    const int tr = tid >> 5, tc = tid & 31;
#pragma unroll
    for (int i = 0; i < 4; i++) {
        int kk = ktile * 32 + tr + i * 8;
        int n = ntile * 32 + tc;
        f[tr + i * 8][tc] = (n < VV) ? Wout[kk * VV + n] : 0.f;
    }
    __syncthreads();
#pragma unroll
    for (int i = 0; i < 4; i++) {
        int n = ntile * 32 + tr + i * 8;
        int kk = ktile * 32 + tc;
        float w = f[tc][tr + i * 8];
        __nv_bfloat16 bh = __float2bfloat16(w);
        __nv_bfloat16 bl = __float2bfloat16(w - __bfloat162float(bh));
        __nv_bfloat16* dst = g_B2 + (size_t)n * KEFF;
        dst[kk]        = bh;
        dst[512 + kk]  = bl;
        dst[1024 + kk] = bh;
    }
}

// ---------------- HMMA logits ----------------
__global__ void __launch_bounds__(256) k_logits_mma(const float* __restrict__ bout,
                                                    float* __restrict__ out)
{
    __shared__ __align__(16) __nv_bfloat16 sA[2][128 * 40];
    __shared__ __align__(16) __nv_bfloat16 sB[2][128 * 40];
    const int tid = threadIdx.x;
    const int nt = blockIdx.x, mt = blockIdx.y;
    const int warp = tid >> 5, lane = tid & 31;
    const int wm = warp >> 2, wn = warp & 3;

    float acc[4][4][4];
#pragma unroll
    for (int a = 0; a < 4; a++)
#pragma unroll
        for (int b = 0; b < 4; b++)
#pragma unroll
            for (int c = 0; c < 4; c++) acc[a][b][c] = 0.f;

    const __nv_bfloat16* gA = g_A2 + (size_t)(mt * 128) * KEFF;
    const __nv_bfloat16* gB = g_B2 + (size_t)(nt * 128) * KEFF;

    uint4 pa[2], pb[2];
#pragma unroll
    for (int i = 0; i < 2; i++) {
        int s = tid + i * 256, r = s >> 2, sg = s & 3;
        pa[i] = *reinterpret_cast<const uint4*>(gA + (size_t)r * KEFF + sg * 8);
        pb[i] = *reinterpret_cast<const uint4*>(gB + (size_t)r * KEFF + sg * 8);
    }

    for (int kc = 0; kc < KCM; kc++) {
        int buf = kc & 1;
#pragma unroll
        for (int i = 0; i < 2; i++) {
            int s = tid + i * 256, r = s >> 2, sg = s & 3;
            *reinterpret_cast<uint4*>(&sA[buf][r * 40 + sg * 8]) = pa[i];
            *reinterpret_cast<uint4*>(&sB[buf][r * 40 + sg * 8]) = pb[i];
        }
        __syncthreads();

        if (kc + 1 < KCM) {
            int k0 = (kc + 1) * 32;
#pragma unroll
            for (int i = 0; i < 2; i++) {
                int s = tid + i * 256, r = s >> 2, sg = s & 3;
                pa[i] = *reinterpret_cast<const uint4*>(gA + (size_t)r * KEFF + k0 + sg * 8);
                pb[i] = *reinterpret_cast<const uint4*>(gB + (size_t)r * KEFF + k0 + sg * 8);
            }
        }

        unsigned sAb = smem_u32(sA[buf]);
        unsigned sBb = smem_u32(sB[buf]);
#pragma unroll
        for (int kf = 0; kf < 2; kf++) {
            unsigned a[4][4], b[4][2];
#pragma unroll
            for (int mf = 0; mf < 4; mf++) {
                int r = wm * 64 + mf * 16 + (lane & 15);
                ldmx4(a[mf], sAb + r * 80 + kf * 32 + (lane >> 4) * 16);
            }
#pragma unroll
            for (int nf = 0; nf < 4; nf++) {
                int n = wn * 32 + nf * 8 + (lane & 7);
                ldmx2(b[nf], sBb + n * 80 + kf * 32 + ((lane >> 3) & 1) * 16);
            }
#pragma unroll
            for (int mf = 0; mf < 4; mf++)
#pragma unroll
                for (int nf = 0; nf < 4; nf++)
                    mma16816(acc[mf][nf], a[mf], b[nf]);
        }
        __syncthreads();
    }

    const int gID = lane >> 2, tig = lane & 3;
#pragma unroll
    for (int mf = 0; mf < 4; mf++) {
#pragma unroll
        for (int half = 0; half < 2; half++) {
            int gm = mt * 128 + wm * 64 + mf * 16 + gID + half * 8;
            int tt = gm >> 7, bb = gm & 127;
            float* orow = out + ((size_t)bb * TT + tt) * VV;
#pragma unroll
            for (int nf = 0; nf < 4; nf++) {
                int n = nt * 128 + wn * 32 + nf * 8 + tig * 2;
                float v0 = acc[mf][nf][half * 2 + 0];
                float v1 = acc[mf][nf][half * 2 + 1];
                if (n + 1 < VV) {
                    float2 o = make_float2(v0 + bout[n], v1 + bout[n + 1]);
                    *reinterpret_cast<float2*>(orow + n) = o;
                } else if (n < VV) {
                    orow[n] = v0 + bout[n];
                }
            }
        }
    }
}

__global__ void k_hidden(float* __restrict__ outh) {
    int i = blockIdx.x * blockDim.x + threadIdx.x;
    if (i < BB * HH) {
        outh[i]           = g_h0[1][i];
        outh[BB * HH + i] = g_h1[1][i];
    }
}

// ---------------- launch ----------------
extern "C" void kernel_launch(void* const* d_in, const int* in_sizes, int n_in,
                              void* d_out, int out_size) {
    const int*   tokens = (const int*)d_in[0];     // int32 (JAX x64 disabled)
    const float* cnn  = (const float*)d_in[1];
    const float* emb  = (const float*)d_in[2];
    const float* Win  = (const float*)d_in[3];
    const float* bin  = (const float*)d_in[4];
    const float* Wout = (const float*)d_in[5];
    const float* bout = (const float*)d_in[6];
    const float* Wu0  = (const float*)d_in[7];
    const float* bu0  = (const float*)d_in[8];
    const float* Wr0  = (const float*)d_in[9];
    const float* br0  = (const float*)d_in[10];
    const float* Wc0  = (const float*)d_in[11];
    const float* bc0  = (const float*)d_in[12];
    const float* Wu1  = (const float*)d_in[13];
    const float* bu1  = (const float*)d_in[14];
    const float* Wr1  = (const float*)d_in[15];
    const float* br1  = (const float*)d_in[16];
    const float* Wc1  = (const float*)d_in[17];
    const float* bc1  = (const float*)d_in[18];
    float* out = (float*)d_out;

    k_pack<<<4, 256>>>(bu1, br1);

    // one-time weight split+transpose for the recurrence
    k_cvtW<<<dim3(32, 32, 4), 256>>>(Wu0, Wr0, Wc0, Wu1, Wr1, Wc1);

    small_gemm<NFE, OpP><<<dim3(MAPS / 32, BB / 32), 256>>>(OpP{cnn, Win, bin});

    k_precompute<<<dim3(1536 / 64, (TT * BB) / 64), 256>>>(tokens, emb, Wu0, Wr0, Wc0, bu0, br0, bc0);

    // convert Wout (logits B) while earlier kernels run in the stream
    k_cvtB<<<dim3(NPAD / 32, 512 / 32), 256>>>(Wout);

    k_recurrence<<<NBLK, 512>>>(bc1);

    // H1 -> bf16 split, then HMMA logits
    k_cvtA<<<TT * BB, 256>>>();
    k_logits_mma<<<dim3(NPAD / 128, (TT * BB) / 128), 256>>>(bout, out);

    k_hidden<<<(BB * HH + 255) / 256, 256>>>(out + (size_t)BB * TT * VV);
}

// round 12
// speedup vs baseline: 2.7370x; 1.1909x over previous
#include <cuda_runtime.h>
#include <cuda_bf16.h>
#include <math.h>

#define BB   128
#define TT   25
#define VV   10000
#define EE   512
#define NFE  2048
#define HH   512
#define MAPS 512
#define IN0  1024   // EE + MAPS
#define NBLK 128    // 4 row-groups x 32 col-tiles

#define NPAD 10240  // VV padded to 128
#define KEFF 1536   // 3 x 512 (split-K concat) for logits
#define KCM  48     // logits K chunks of 32

#define KEFF2 3072  // 3 x 1024 for precompute
#define KCM2  96    // precompute K chunks of 32

// ---------------- scratch ----------------
__device__ float g_p[BB * MAPS];
__device__ float g_X0[TT * BB * 1536];
__device__ float g_h0[2][BB * HH];
__device__ float g_h1[2][BB * HH];
__device__ float g_ur0[BB * 1024];
__device__ float g_ur1[BB * 1024];
__device__ float g_H1[TT * BB * HH];
__device__ float g_bur1[1024];
__device__ float g_bx0[1536];                     // packed [bu0|br0|bc0]

// bf16 split recurrent weights, n-major [n][K]
__device__ __nv_bfloat16 g_W0h[1024 * 512],  g_W0l[1024 * 512];   // [Wu0_h|Wr0_h]
__device__ __nv_bfloat16 g_W1h[512 * 512],   g_W1l[512 * 512];    // Wc0 h-part
__device__ __nv_bfloat16 g_W2h[1024 * 1024], g_W2l[1024 * 1024];  // [Wu1|Wr1]
__device__ __nv_bfloat16 g_W3h[512 * 1024],  g_W3l[512 * 1024];   // Wc1

// bf16 split operands for HMMA logits (row-major, k contiguous)
__device__ __nv_bfloat16 g_A2[TT * BB * KEFF];    // [Ah | Ah | Al]
__device__ __nv_bfloat16 g_B2[NPAD * KEFF];       // [Bh | Bl | Bh], n-major

// bf16 split operands for HMMA precompute
__device__ __nv_bfloat16 g_A2x[TT * BB * KEFF2];  // gathered [emb|p]: [Ah|Ah|Al]
__device__ __nv_bfloat16 g_B2x[1536 * KEFF2];     // x-part weights: [Bh|Bl|Bh], n-major

// group-local store/load barriers (4 groups x 32 blocks)
__device__ volatile int g_gflags[4][32];
__device__ volatile int g_gepoch[4];

__device__ __forceinline__ float sigmoidf(float x) { return 1.f / (1.f + expf(-x)); }
__device__ __forceinline__ float4 ldcg4(const float* p) {
    return __ldcg(reinterpret_cast<const float4*>(p));
}
__device__ __forceinline__ unsigned smem_u32(const void* p) {
    unsigned a;
    asm("{ .reg .u64 t; cvta.to.shared.u64 t, %1; cvt.u32.u64 %0, t; }" : "=r"(a) : "l"(p));
    return a;
}
__device__ __forceinline__ void ldmx4(unsigned* r, unsigned addr) {
    asm volatile("ldmatrix.sync.aligned.m8n8.x4.shared.b16 {%0,%1,%2,%3}, [%4];"
                 : "=r"(r[0]), "=r"(r[1]), "=r"(r[2]), "=r"(r[3]) : "r"(addr));
}
__device__ __forceinline__ void ldmx2(unsigned* r, unsigned addr) {
    asm volatile("ldmatrix.sync.aligned.m8n8.x2.shared.b16 {%0,%1}, [%2];"
                 : "=r"(r[0]), "=r"(r[1]) : "r"(addr));
}
__device__ __forceinline__ void mma16816(float* acc, const unsigned* a, const unsigned* b) {
    asm volatile(
        "mma.sync.aligned.m16n8k16.row.col.f32.bf16.bf16.f32 "
        "{%0,%1,%2,%3}, {%4,%5,%6,%7}, {%8,%9}, {%0,%1,%2,%3};"
        : "+f"(acc[0]), "+f"(acc[1]), "+f"(acc[2]), "+f"(acc[3])
        : "r"(a[0]), "r"(a[1]), "r"(a[2]), "r"(a[3]), "r"(b[0]), "r"(b[1]));
}

__device__ __forceinline__ void gbarg(int grp, int ct, int e) {
    __syncthreads();
    if (ct == 0) {
        if (threadIdx.x > 0 && threadIdx.x < 32) {
            while (g_gflags[grp][threadIdx.x] < e) { }
        }
        __syncthreads();
        if (threadIdx.x == 0) {
            __threadfence();
            g_gepoch[grp] = e;
        }
    } else {
        if (threadIdx.x == 0) {
            __threadfence();
            g_gflags[grp][ct] = e;
            while (g_gepoch[grp] < e) { }
            __threadfence();
        }
    }
    __syncthreads();
}

// ---------------- pack: barrier reset + bias packs ----------------
__global__ void k_pack(const float* __restrict__ bu1, const float* __restrict__ br1,
                       const float* __restrict__ bu0, const float* __restrict__ br0,
                       const float* __restrict__ bc0) {
    int i = blockIdx.x * blockDim.x + threadIdx.x;
    if (i < 128) { g_gflags[i >> 5][i & 31] = 0; if ((i & 31) == 0) g_gepoch[i >> 5] = 0; }
    if (i < 1024) g_bur1[i] = (i < 512) ? bu1[i] : br1[i - 512];
    if (i < 1536) g_bx0[i] = (i < 512) ? bu0[i] : (i < 1024) ? br0[i - 512] : bc0[i - 1024];
}

// ---------------- weight split + transpose for recurrence (one-time) ----------------
__global__ void __launch_bounds__(256) k_cvtW(
    const float* __restrict__ Wu0, const float* __restrict__ Wr0,
    const float* __restrict__ Wc0, const float* __restrict__ Wu1,
    const float* __restrict__ Wr1, const float* __restrict__ Wc1)
{
    __shared__ float f[32][33];
    const int ph = blockIdx.z;
    const int NN = (ph == 0 || ph == 2) ? 1024 : 512;
    const int KK = (ph >= 2) ? 1024 : 512;
    if ((int)blockIdx.x * 32 >= NN || (int)blockIdx.y * 32 >= KK) return;
    const int tid = threadIdx.x, tr = tid >> 5, tc = tid & 31;
    __nv_bfloat16* Wh = (ph == 0) ? g_W0h : (ph == 1) ? g_W1h : (ph == 2) ? g_W2h : g_W3h;
    __nv_bfloat16* Wl = (ph == 0) ? g_W0l : (ph == 1) ? g_W1l : (ph == 2) ? g_W2l : g_W3l;
#pragma unroll
    for (int i = 0; i < 4; i++) {
        int kk = blockIdx.y * 32 + tr + i * 8;
        int n  = blockIdx.x * 32 + tc;
        float v;
        if (ph == 0)      v = (n < 512) ? Wu0[(IN0 + kk) * HH + n] : Wr0[(IN0 + kk) * HH + (n - 512)];
        else if (ph == 1) v = Wc0[kk * HH + n];
        else if (ph == 2) v = (n < 512) ? Wu1[kk * HH + n] : Wr1[kk * HH + (n - 512)];
        else              v = Wc1[kk * HH + n];
        f[tr + i * 8][tc] = v;
    }
    __syncthreads();
#pragma unroll
    for (int i = 0; i < 4; i++) {
        int n  = blockIdx.x * 32 + tr + i * 8;
        int kk = blockIdx.y * 32 + tc;
        float wv = f[tc][tr + i * 8];
        __nv_bfloat16 bh = __float2bfloat16(wv);
        __nv_bfloat16 bl = __float2bfloat16(wv - __bfloat162float(bh));
        Wh[(size_t)n * KK + kk] = bh;
        Wl[(size_t)n * KK + kk] = bl;
    }
}

// ---------------- precompute weight split + transpose (x-parts) ----------------
// B2x[n][0:1024]=Bh, [1024:2048]=Bl, [2048:3072]=Bh; n<512: Wu0_x, n<1024: Wr0_x, else Wc0_x
__global__ void __launch_bounds__(256) k_cvtBx(
    const float* __restrict__ Wu0, const float* __restrict__ Wr0,
    const float* __restrict__ Wc0)
{
    __shared__ float f[32][33];
    const int ntile = blockIdx.x;      // 0..47  (1536/32)
    const int ktile = blockIdx.y;      // 0..31  (1024/32)
    const int tid = threadIdx.x;
    const int tr = tid >> 5, tc = tid & 31;
#pragma unroll
    for (int i = 0; i < 4; i++) {
        int kk = ktile * 32 + tr + i * 8;
        int n  = ntile * 32 + tc;
        float v;
        if (n < 512)       v = Wu0[kk * HH + n];
        else if (n < 1024) v = Wr0[kk * HH + (n - 512)];
        else               v = Wc0[(512 + kk) * HH + (n - 1024)];  // x-part of Wc0
        f[tr + i * 8][tc] = v;
    }
    __syncthreads();
#pragma unroll
    for (int i = 0; i < 4; i++) {
        int n  = ntile * 32 + tr + i * 8;
        int kk = ktile * 32 + tc;
        float wv = f[tc][tr + i * 8];
        __nv_bfloat16 bh = __float2bfloat16(wv);
        __nv_bfloat16 bl = __float2bfloat16(wv - __bfloat162float(bh));
        __nv_bfloat16* dst = g_B2x + (size_t)n * KEFF2;
        dst[kk]         = bh;
        dst[1024 + kk]  = bl;
        dst[2048 + kk]  = bh;
    }
}

// ---------------- precompute A gather + split ----------------
// Row m (= t*BB + b): x = [emb[tokens[b][t]] | p[b]]; A2x[m] = [Ah(1024)|Ah|Al]
__global__ void __launch_bounds__(256) k_cvtAx(const int* __restrict__ tokens,
                                               const float* __restrict__ emb) {
    const int m = blockIdx.x;
    const int b = m & 127, t = m >> 7;
    const int tok = tokens[b * TT + t];
    const int tid = threadIdx.x;
    __nv_bfloat16* dst = g_A2x + (size_t)m * KEFF2;
#pragma unroll
    for (int i = 0; i < 4; i++) {
        int k = tid + i * 256;
        float a = (k < 512) ? emb[(size_t)tok * EE + k] : g_p[b * MAPS + (k - 512)];
        __nv_bfloat16 ah = __float2bfloat16(a);
        __nv_bfloat16 al = __float2bfloat16(a - __bfloat162float(ah));
        dst[k]         = ah;
        dst[1024 + k]  = ah;
        dst[2048 + k]  = al;
    }
}

// ---------------- input layer GEMM ----------------
template <int K, typename Op>
__global__ void __launch_bounds__(256) small_gemm(Op op) {
    __shared__ float As[32][33];
    __shared__ float Bs[32][33];
    const int tid = threadIdx.x;
    const int r0 = tid >> 4;
    const int c0 = tid & 15;
    const int mBase = blockIdx.y * 32;
    const int nBase = blockIdx.x * 32;

    float a00 = 0.f, a01 = 0.f, a10 = 0.f, a11 = 0.f;

    for (int k0 = 0; k0 < K; k0 += 32) {
#pragma unroll
        for (int i = 0; i < 4; i++) {
            int e = tid + i * 256;
            int r = e >> 5, kk = e & 31;
            As[r][kk] = op.loadA(mBase + r, k0 + kk);
        }
#pragma unroll
        for (int i = 0; i < 4; i++) {
            int e = tid + i * 256;
            int kk = e >> 5, n = e & 31;
            Bs[kk][n] = op.loadB(k0 + kk, nBase + n);
        }
        __syncthreads();
#pragma unroll
        for (int kk = 0; kk < 32; kk++) {
            float x0 = As[r0][kk],      x1 = As[r0 + 16][kk];
            float y0 = Bs[kk][c0],      y1 = Bs[kk][c0 + 16];
            a00 += x0 * y0; a01 += x0 * y1;
            a10 += x1 * y0; a11 += x1 * y1;
        }
        __syncthreads();
    }
    op.store(mBase + r0,      nBase + c0,      a00);
    op.store(mBase + r0,      nBase + c0 + 16, a01);
    op.store(mBase + r0 + 16, nBase + c0,      a10);
    op.store(mBase + r0 + 16, nBase + c0 + 16, a11);
}

struct OpP {
    const float* A; const float* Bw; const float* bias;
    __device__ float loadA(int r, int k) const { return A[r * NFE + k]; }
    __device__ float loadB(int k, int n) const { return Bw[k * MAPS + n]; }
    __device__ void store(int r, int n, float acc) const {
        float v = acc + bias[n];
        g_p[r * MAPS + n] = v > 0.f ? v : 0.01f * v;
    }
};

// ---------------- persistent recurrence via HMMA ----------------
template <int PH, int COLS, int KTOT>
__device__ __forceinline__ void run_phase_mma(
    __nv_bfloat16 (*sAh)[72], __nv_bfloat16 (*sAl)[72],
    __nv_bfloat16 (*sBh)[72], __nv_bfloat16 (*sBl)[72],
    float (*red)[32][4],
    int t, int grp, int ct,
    const float* h0c, float* h0n, const float* h1c, float* h1n,
    const __nv_bfloat16* __restrict__ Wh, const __nv_bfloat16* __restrict__ Wl,
    const float* __restrict__ bc1)
{
    const int tid = threadIdx.x;
    const int w = tid >> 5, lane = tid & 31;
    constexpr int F  = COLS / 4;            // frag slots: 8 or 4
    constexpr int KW = 16 / F;              // k-parities: 2 or 4
    constexpr int CH = KTOT / 64;           // chunks
    const int slot = w & (F - 1);
    const int par  = w / F;
    const int mf = (COLS == 32) ? (slot >> 2) : (slot >> 1);
    const int nf = (COLS == 32) ? (slot & 3) : (slot & 1);
    const int R0 = grp * 32;
    const int cb = ct * COLS;

    const int arow = tid >> 4;
    const int ak4  = (tid & 15) << 2;
    constexpr int HB = COLS * 8;
    const bool bhAct = tid < HB;
    const bool blAct = (tid >= 256) && (tid < 256 + HB);
    const int bn  = bhAct ? (tid >> 3) : ((tid - 256) >> 3);
    const int bsg = bhAct ? (tid & 7)  : ((tid - 256) & 7);

    float acc[4] = {0.f, 0.f, 0.f, 0.f};

    auto loadA4 = [&](int ka) -> float4 {
        int rr = R0 + arow;
        if (PH == 0) {
            return ldcg4(h0c + rr * HH + ka);
        } else if (PH == 1) {
            float4 u = ldcg4(g_ur0 + rr * 1024 + 512 + ka);
            float4 h = ldcg4(h0c + rr * HH + ka);
            return make_float4(u.x * h.x, u.y * h.y, u.z * h.z, u.w * h.w);
        } else if (PH == 2) {
            return (ka < 512) ? ldcg4(h0n + rr * HH + ka)
                              : ldcg4(h1c + rr * HH + (ka - 512));
        } else {
            if (ka < 512) {
                float4 u = ldcg4(g_ur1 + rr * 1024 + 512 + ka);
                float4 h = ldcg4(h1c + rr * HH + ka);
                return make_float4(u.x * h.x, u.y * h.y, u.z * h.z, u.w * h.w);
            }
            return ldcg4(h0n + rr * HH + (ka - 512));
        }
    };

    float4 va = loadA4(ak4);
    uint4 vb;
    if (bhAct)      vb = *reinterpret_cast<const uint4*>(Wh + (size_t)(cb + bn) * KTOT + bsg * 8);
    else if (blAct) vb = *reinterpret_cast<const uint4*>(Wl + (size_t)(cb + bn) * KTOT + bsg * 8);

    const unsigned baseAh = smem_u32(sAh), baseAl = smem_u32(sAl);
    const unsigned baseBh = smem_u32(sBh), baseBl = smem_u32(sBl);

    for (int c = 0; c < CH; c++) {
        {
            unsigned bx = __float_as_uint(va.x), by = __float_as_uint(va.y);
            unsigned bz = __float_as_uint(va.z), bw2 = __float_as_uint(va.w);
            unsigned h01 = __byte_perm(bx, by, 0x7632);
            unsigned h23 = __byte_perm(bz, bw2, 0x7632);
            float lx = va.x - __uint_as_float(bx & 0xFFFF0000u);
            float ly = va.y - __uint_as_float(by & 0xFFFF0000u);
            float lz = va.z - __uint_as_float(bz & 0xFFFF0000u);
            float lw = va.w - __uint_as_float(bw2 & 0xFFFF0000u);
            unsigned l01, l23;
            asm("cvt.rn.bf16x2.f32 %0, %1, %2;" : "=r"(l01) : "f"(ly), "f"(lx));
            asm("cvt.rn.bf16x2.f32 %0, %1, %2;" : "=r"(l23) : "f"(lw), "f"(lz));
            *reinterpret_cast<uint2*>(&sAh[arow][ak4]) = make_uint2(h01, h23);
            *reinterpret_cast<uint2*>(&sAl[arow][ak4]) = make_uint2(l01, l23);
        }
        if (bhAct)      *reinterpret_cast<uint4*>(&sBh[bn][bsg * 8]) = vb;
        else if (blAct) *reinterpret_cast<uint4*>(&sBl[bn][bsg * 8]) = vb;
        __syncthreads();

        if (c + 1 < CH) {
            va = loadA4((c + 1) * 64 + ak4);
            if (bhAct)      vb = *reinterpret_cast<const uint4*>(Wh + (size_t)(cb + bn) * KTOT + (c + 1) * 64 + bsg * 8);
            else if (blAct) vb = *reinterpret_cast<const uint4*>(Wl + (size_t)(cb + bn) * KTOT + (c + 1) * 64 + bsg * 8);
        }

#pragma unroll
        for (int si = 0; si < 4 / KW; si++) {
            int s = par + si * KW;
            unsigned ah[4], al[4], bh[2], bl[2];
            unsigned aoff = (mf * 16 + (lane & 15)) * 144 + s * 32 + (lane >> 4) * 16;
            ldmx4(ah, baseAh + aoff);
            ldmx4(al, baseAl + aoff);
            unsigned boff = (nf * 8 + (lane & 7)) * 144 + s * 32 + ((lane >> 3) & 1) * 16;
            ldmx2(bh, baseBh + boff);
            ldmx2(bl, baseBl + boff);
            mma16816(acc, ah, bh);
            mma16816(acc, ah, bl);
            mma16816(acc, al, bh);
        }
        __syncthreads();
    }

    if (par > 0) {
        float* d = red[(par - 1) * F + slot][lane];
        d[0] = acc[0]; d[1] = acc[1]; d[2] = acc[2]; d[3] = acc[3];
    }
    __syncthreads();
    if (par == 0) {
#pragma unroll
        for (int p = 1; p < KW; p++) {
            float* s = red[(p - 1) * F + slot][lane];
            acc[0] += s[0]; acc[1] += s[1]; acc[2] += s[2]; acc[3] += s[3];
        }
        const int gID = lane >> 2, tig = lane & 3;
#pragma unroll
        for (int half = 0; half < 2; half++) {
            int R   = R0 + mf * 16 + gID + half * 8;
            int cgl = cb + nf * 8 + tig * 2;
            float v0 = acc[half * 2], v1 = acc[half * 2 + 1];
            if (PH == 0) {
                const float* x = g_X0 + (t * BB + R) * 1536 + cgl;
                float2 o = make_float2(sigmoidf(v0 + x[0]), sigmoidf(v1 + x[1]));
                *reinterpret_cast<float2*>(g_ur0 + R * 1024 + cgl) = o;
            } else if (PH == 1) {
                const float* x = g_X0 + (t * BB + R) * 1536 + 1024 + cgl;
                float u0 = __ldcg(g_ur0 + R * 1024 + cgl);
                float u1 = __ldcg(g_ur0 + R * 1024 + cgl + 1);
                float p0 = __ldcg(h0c + R * HH + cgl);
                float p1 = __ldcg(h0c + R * HH + cgl + 1);
                float2 o = make_float2(u0 * p0 + (1.f - u0) * tanhf(v0 + x[0]),
                                       u1 * p1 + (1.f - u1) * tanhf(v1 + x[1]));
                *reinterpret_cast<float2*>(h0n + R * HH + cgl) = o;
            } else if (PH == 2) {
                float2 o = make_float2(sigmoidf(v0 + g_bur1[cgl]),
                                       sigmoidf(v1 + g_bur1[cgl + 1]));
                *reinterpret_cast<float2*>(g_ur1 + R * 1024 + cgl) = o;
            } else {
                float u0 = __ldcg(g_ur1 + R * 1024 + cgl);
                float u1 = __ldcg(g_ur1 + R * 1024 + cgl + 1);
                float p0 = __ldcg(h1c + R * HH + cgl);
                float p1 = __ldcg(h1c + R * HH + cgl + 1);
                float2 o = make_float2(u0 * p0 + (1.f - u0) * tanhf(v0 + bc1[cgl]),
                                       u1 * p1 + (1.f - u1) * tanhf(v1 + bc1[cgl + 1]));
                *reinterpret_cast<float2*>(h1n + R * HH + cgl) = o;
                *reinterpret_cast<float2*>(g_H1 + (t * BB + R) * HH + cgl) = o;
            }
        }
    }
}

__global__ void __launch_bounds__(512, 1) k_recurrence(const float* __restrict__ bc1) {
    __shared__ __align__(16) __nv_bfloat16 sAh[32][72];
    __shared__ __align__(16) __nv_bfloat16 sAl[32][72];
    __shared__ __align__(16) __nv_bfloat16 sBh[32][72];
    __shared__ __align__(16) __nv_bfloat16 sBl[32][72];
    __shared__ float red[12][32][4];
    const int tid = threadIdx.x, blk = blockIdx.x;
    const int grp = blk >> 5, ct = blk & 31;
    int ep = 0;

    {
        int off = grp * 16384 + ct * 512 + tid;
        g_h0[0][off] = 0.f;
        g_h1[0][off] = 0.f;
    }
    gbarg(grp, ct, ++ep);

    for (int t = 0; t < TT; t++) {
        const int cur = t & 1;
        const float* h0c = g_h0[cur];
        float*       h0n = g_h0[cur ^ 1];
        const float* h1c = g_h1[cur];
        float*       h1n = g_h1[cur ^ 1];

        run_phase_mma<0, 32,  512>(sAh, sAl, sBh, sBl, red, t, grp, ct,
                                   h0c, h0n, h1c, h1n, g_W0h, g_W0l, bc1);
        gbarg(grp, ct, ++ep);
        run_phase_mma<1, 16,  512>(sAh, sAl, sBh, sBl, red, t, grp, ct,
                                   h0c, h0n, h1c, h1n, g_W1h, g_W1l, bc1);
        gbarg(grp, ct, ++ep);
        run_phase_mma<2, 32, 1024>(sAh, sAl, sBh, sBl, red, t, grp, ct,
                                   h0c, h0n, h1c, h1n, g_W2h, g_W2l, bc1);
        gbarg(grp, ct, ++ep);
        run_phase_mma<3, 16, 1024>(sAh, sAl, sBh, sBl, red, t, grp, ct,
                                   h0c, h0n, h1c, h1n, g_W3h, g_W3l, bc1);
        if (t != TT - 1) gbarg(grp, ct, ++ep);
    }
}

// ---------------- bf16 split preps for logits ----------------
__global__ void __launch_bounds__(256) k_cvtA() {
    const int m = blockIdx.x;
    const int tid = threadIdx.x;
    __nv_bfloat16* dst = g_A2 + (size_t)m * KEFF;
#pragma unroll
    for (int i = 0; i < 2; i++) {
        int k = tid + i * 256;
        float a = g_H1[m * HH + k];
        __nv_bfloat16 ah = __float2bfloat16(a);
        __nv_bfloat16 al = __float2bfloat16(a - __bfloat162float(ah));
        dst[k]        = ah;
        dst[512 + k]  = ah;
        dst[1024 + k] = al;
    }
}

__global__ void __launch_bounds__(256) k_cvtB(const float* __restrict__ Wout) {
    __shared__ float f[32][33];
    const int ntile = blockIdx.x;
    const int ktile = blockIdx.y;
    const int tid = threadIdx.x;
    const int tr = tid >> 5, tc = tid & 31;
#pragma unroll
    for (int i = 0; i < 4; i++) {
        int kk = ktile * 32 + tr + i * 8;
        int n = ntile * 32 + tc;
        f[tr + i * 8][tc] = (n < VV) ? Wout[kk * VV + n] : 0.f;
    }
    __syncthreads();
#pragma unroll
    for (int i = 0; i < 4; i++) {
        int n = ntile * 32 + tr + i * 8;
        int kk = ktile * 32 + tc;
        float w = f[tc][tr + i * 8];
        __nv_bfloat16 bh = __float2bfloat16(w);
        __nv_bfloat16 bl = __float2bfloat16(w - __bfloat162float(bh));
        __nv_bfloat16* dst = g_B2 + (size_t)n * KEFF;
        dst[kk]        = bh;
        dst[512 + kk]  = bl;
        dst[1024 + kk] = bh;
    }
}

// ---------------- generic HMMA GEMM core (CTA 128x128, double-buffered) ----------------
template <int KEFFT, int KCMT, bool LOGITS>
__device__ __forceinline__ void hmma_gemm_body(
    const __nv_bfloat16* __restrict__ gA, const __nv_bfloat16* __restrict__ gB,
    const float* __restrict__ bias, float* __restrict__ out, int nt, int mt,
    __nv_bfloat16 (*sA)[128 * 40], __nv_bfloat16 (*sB)[128 * 40])
{
    const int tid = threadIdx.x;
    const int warp = tid >> 5, lane = tid & 31;
    const int wm = warp >> 2, wn = warp & 3;

    float acc[4][4][4];
#pragma unroll
    for (int a = 0; a < 4; a++)
#pragma unroll
        for (int b = 0; b < 4; b++)
#pragma unroll
            for (int c = 0; c < 4; c++) acc[a][b][c] = 0.f;

    uint4 pa[2], pb[2];
#pragma unroll
    for (int i = 0; i < 2; i++) {
        int s = tid + i * 256, r = s >> 2, sg = s & 3;
        pa[i] = *reinterpret_cast<const uint4*>(gA + (size_t)r * KEFFT + sg * 8);
        pb[i] = *reinterpret_cast<const uint4*>(gB + (size_t)r * KEFFT + sg * 8);
    }

    for (int kc = 0; kc < KCMT; kc++) {
        int buf = kc & 1;
#pragma unroll
        for (int i = 0; i < 2; i++) {
            int s = tid + i * 256, r = s >> 2, sg = s & 3;
            *reinterpret_cast<uint4*>(&sA[buf][r * 40 + sg * 8]) = pa[i];
            *reinterpret_cast<uint4*>(&sB[buf][r * 40 + sg * 8]) = pb[i];
        }
        __syncthreads();

        if (kc + 1 < KCMT) {
            int k0 = (kc + 1) * 32;
#pragma unroll
            for (int i = 0; i < 2; i++) {
                int s = tid + i * 256, r = s >> 2, sg = s & 3;
                pa[i] = *reinterpret_cast<const uint4*>(gA + (size_t)r * KEFFT + k0 + sg * 8);
                pb[i] = *reinterpret_cast<const uint4*>(gB + (size_t)r * KEFFT + k0 + sg * 8);
            }
        }

        unsigned sAb = smem_u32(sA[buf]);
        unsigned sBb = smem_u32(sB[buf]);
#pragma unroll
        for (int kf = 0; kf < 2; kf++) {
            unsigned a[4][4], b[4][2];
#pragma unroll
            for (int mf = 0; mf < 4; mf++) {
                int r = wm * 64 + mf * 16 + (lane & 15);
                ldmx4(a[mf], sAb + r * 80 + kf * 32 + (lane >> 4) * 16);
            }
#pragma unroll
            for (int nf = 0; nf < 4; nf++) {
                int n = wn * 32 + nf * 8 + (lane & 7);
                ldmx2(b[nf], sBb + n * 80 + kf * 32 + ((lane >> 3) & 1) * 16);
            }
#pragma unroll
            for (int mf = 0; mf < 4; mf++)
#pragma unroll
                for (int nf = 0; nf < 4; nf++)
                    mma16816(acc[mf][nf], a[mf], b[nf]);
        }
        __syncthreads();
    }

    const int gID = lane >> 2, tig = lane & 3;
#pragma unroll
    for (int mf = 0; mf < 4; mf++) {
#pragma unroll
        for (int half = 0; half < 2; half++) {
            int gm = mt * 128 + wm * 64 + mf * 16 + gID + half * 8;
            float* orow;
            if (LOGITS) {
                int tt = gm >> 7, bb = gm & 127;
                orow = out + ((size_t)bb * TT + tt) * VV;
            } else {
                orow = out + (size_t)gm * 1536;
            }
#pragma unroll
            for (int nf = 0; nf < 4; nf++) {
                int n = nt * 128 + wn * 32 + nf * 8 + tig * 2;
                float v0 = acc[mf][nf][half * 2 + 0];
                float v1 = acc[mf][nf][half * 2 + 1];
                if (LOGITS) {
                    if (n + 1 < VV) {
                        float2 o = make_float2(v0 + bias[n], v1 + bias[n + 1]);
                        *reinterpret_cast<float2*>(orow + n) = o;
                    } else if (n < VV) {
                        orow[n] = v0 + bias[n];
                    }
                } else {
                    float2 o = make_float2(v0 + bias[n], v1 + bias[n + 1]);
                    *reinterpret_cast<float2*>(orow + n) = o;
                }
            }
        }
    }
}

__global__ void __launch_bounds__(256) k_logits_mma(const float* __restrict__ bout,
                                                    float* __restrict__ out)
{
    __shared__ __align__(16) __nv_bfloat16 sA[2][128 * 40];
    __shared__ __align__(16) __nv_bfloat16 sB[2][128 * 40];
    const int nt = blockIdx.x, mt = blockIdx.y;
    hmma_gemm_body<KEFF, KCM, true>(
        g_A2 + (size_t)(mt * 128) * KEFF, g_B2 + (size_t)(nt * 128) * KEFF,
        bout, out, nt, mt, sA, sB);
}

// precompute: X0 = A2x @ B2x^T + bias  (M=3200, N=1536)
__global__ void __launch_bounds__(256) k_precompute_mma(float* __restrict__ dummy)
{
    __shared__ __align__(16) __nv_bfloat16 sA[2][128 * 40];
    __shared__ __align__(16) __nv_bfloat16 sB[2][128 * 40];
    const int nt = blockIdx.x, mt = blockIdx.y;
    hmma_gemm_body<KEFF2, KCM2, false>(
        g_A2x + (size_t)(mt * 128) * KEFF2, g_B2x + (size_t)(nt * 128) * KEFF2,
        g_bx0, g_X0, nt, mt, sA, sB);
}

__global__ void k_hidden(float* __restrict__ outh) {
    int i = blockIdx.x * blockDim.x + threadIdx.x;
    if (i < BB * HH) {
        outh[i]           = g_h0[1][i];
        outh[BB * HH + i] = g_h1[1][i];
    }
}

// ---------------- launch ----------------
extern "C" void kernel_launch(void* const* d_in, const int* in_sizes, int n_in,
                              void* d_out, int out_size) {
    const int*   tokens = (const int*)d_in[0];     // int32 (JAX x64 disabled)
    const float* cnn  = (const float*)d_in[1];
    const float* emb  = (const float*)d_in[2];
    const float* Win  = (const float*)d_in[3];
    const float* bin  = (const float*)d_in[4];
    const float* Wout = (const float*)d_in[5];
    const float* bout = (const float*)d_in[6];
    const float* Wu0  = (const float*)d_in[7];
    const float* bu0  = (const float*)d_in[8];
    const float* Wr0  = (const float*)d_in[9];
    const float* br0  = (const float*)d_in[10];
    const float* Wc0  = (const float*)d_in[11];
    const float* bc0  = (const float*)d_in[12];
    const float* Wu1  = (const float*)d_in[13];
    const float* bu1  = (const float*)d_in[14];
    const float* Wr1  = (const float*)d_in[15];
    const float* br1  = (const float*)d_in[16];
    const float* Wc1  = (const float*)d_in[17];
    const float* bc1  = (const float*)d_in[18];
    float* out = (float*)d_out;

    k_pack<<<8, 256>>>(bu1, br1, bu0, br0, bc0);

    // one-time weight splits
    k_cvtW<<<dim3(32, 32, 4), 256>>>(Wu0, Wr0, Wc0, Wu1, Wr1, Wc1);
    k_cvtBx<<<dim3(48, 32), 256>>>(Wu0, Wr0, Wc0);
    k_cvtB<<<dim3(NPAD / 32, 512 / 32), 256>>>(Wout);

    // input layer: p = leaky_relu(cnn @ Win + bin)
    small_gemm<NFE, OpP><<<dim3(MAPS / 32, BB / 32), 256>>>(OpP{cnn, Win, bin});

    // precompute X0 via HMMA
    k_cvtAx<<<TT * BB, 256>>>(tokens, emb);
    k_precompute_mma<<<dim3(1536 / 128, (TT * BB) / 128), 256>>>(nullptr);

    // 25-step recurrence (HMMA persistent)
    k_recurrence<<<NBLK, 512>>>(bc1);

    // H1 -> bf16 split, then HMMA logits
    k_cvtA<<<TT * BB, 256>>>();
    k_logits_mma<<<dim3(NPAD / 128, (TT * BB) / 128), 256>>>(bout, out);

    k_hidden<<<(BB * HH + 255) / 256, 256>>>(out + (size_t)BB * TT * VV);
}

// round 13
// speedup vs baseline: 3.1146x; 1.1380x over previous
#include <cuda_runtime.h>
#include <cuda_bf16.h>
#include <math.h>

#define BB   128
#define TT   25
#define VV   10000
#define EE   512
#define NFE  2048
#define HH   512
#define MAPS 512
#define IN0  1024   // EE + MAPS
#define NBLK 128    // 4 row-groups x 32 col-tiles

#define NPAD 10240  // VV padded to 128
#define KEFF 1536   // 3 x 512 (split-K concat) for logits
#define KCM  48     // logits K chunks of 32

#define KEFF2 3072  // 3 x 1024 for precompute
#define KCM2  96    // precompute K chunks of 32

// ---------------- scratch ----------------
__device__ float g_p[BB * MAPS];
__device__ float g_X0[TT * BB * 1536];
__device__ float g_h0[2][BB * HH];
__device__ float g_h1[2][BB * HH];
__device__ float g_ur0[BB * 1024];
__device__ float g_ur1[BB * 1024];
__device__ float g_bur1[1024];
__device__ float g_bx0[1536];                     // packed [bu0|br0|bc0]

// bf16 split recurrent weights, n-major [n][K]
__device__ __nv_bfloat16 g_W0h[1024 * 512],  g_W0l[1024 * 512];   // [Wu0_h|Wr0_h]
__device__ __nv_bfloat16 g_W1h[512 * 512],   g_W1l[512 * 512];    // Wc0 h-part
__device__ __nv_bfloat16 g_W2h[1024 * 1024], g_W2l[1024 * 1024];  // [Wu1|Wr1]
__device__ __nv_bfloat16 g_W3h[512 * 1024],  g_W3l[512 * 1024];   // Wc1

// bf16 split operands for HMMA logits (row-major, k contiguous)
__device__ __nv_bfloat16 g_A2[TT * BB * KEFF];    // [Ah | Ah | Al] (written by PH3 epilogue)
__device__ __nv_bfloat16 g_B2[NPAD * KEFF];       // [Bh | Bl | Bh], n-major

// bf16 split operands for HMMA precompute
__device__ __nv_bfloat16 g_A2x[TT * BB * KEFF2];  // gathered [emb|p]: [Ah|Ah|Al]
__device__ __nv_bfloat16 g_B2x[1536 * KEFF2];     // x-part weights: [Bh|Bl|Bh], n-major

// group-local store/load barriers (4 groups x 32 blocks)
__device__ volatile int g_gflags[4][32];
__device__ volatile int g_gepoch[4];

__device__ __forceinline__ float sigmoidf(float x) { return 1.f / (1.f + expf(-x)); }
__device__ __forceinline__ float4 ldcg4(const float* p) {
    return __ldcg(reinterpret_cast<const float4*>(p));
}
__device__ __forceinline__ unsigned smem_u32(const void* p) {
    unsigned a;
    asm("{ .reg .u64 t; cvta.to.shared.u64 t, %1; cvt.u32.u64 %0, t; }" : "=r"(a) : "l"(p));
    return a;
}
__device__ __forceinline__ void ldmx4(unsigned* r, unsigned addr) {
    asm volatile("ldmatrix.sync.aligned.m8n8.x4.shared.b16 {%0,%1,%2,%3}, [%4];"
                 : "=r"(r[0]), "=r"(r[1]), "=r"(r[2]), "=r"(r[3]) : "r"(addr));
}
__device__ __forceinline__ void ldmx2(unsigned* r, unsigned addr) {
    asm volatile("ldmatrix.sync.aligned.m8n8.x2.shared.b16 {%0,%1}, [%2];"
                 : "=r"(r[0]), "=r"(r[1]) : "r"(addr));
}
__device__ __forceinline__ void mma16816(float* acc, const unsigned* a, const unsigned* b) {
    asm volatile(
        "mma.sync.aligned.m16n8k16.row.col.f32.bf16.bf16.f32 "
        "{%0,%1,%2,%3}, {%4,%5,%6,%7}, {%8,%9}, {%0,%1,%2,%3};"
        : "+f"(acc[0]), "+f"(acc[1]), "+f"(acc[2]), "+f"(acc[3])
        : "r"(a[0]), "r"(a[1]), "r"(a[2]), "r"(a[3]), "r"(b[0]), "r"(b[1]));
}
// split a float4 into bf16 hi(trunc)/lo(rn residual) pairs
__device__ __forceinline__ void split4(float4 v, uint2& hi, uint2& lo) {
    unsigned bx = __float_as_uint(v.x), by = __float_as_uint(v.y);
    unsigned bz = __float_as_uint(v.z), bw = __float_as_uint(v.w);
    hi.x = __byte_perm(bx, by, 0x7632);
    hi.y = __byte_perm(bz, bw, 0x7632);
    float lx = v.x - __uint_as_float(bx & 0xFFFF0000u);
    float ly = v.y - __uint_as_float(by & 0xFFFF0000u);
    float lz = v.z - __uint_as_float(bz & 0xFFFF0000u);
    float lw = v.w - __uint_as_float(bw & 0xFFFF0000u);
    asm("cvt.rn.bf16x2.f32 %0, %1, %2;" : "=r"(lo.x) : "f"(ly), "f"(lx));
    asm("cvt.rn.bf16x2.f32 %0, %1, %2;" : "=r"(lo.y) : "f"(lw), "f"(lz));
}

__device__ __forceinline__ void gbarg(int grp, int ct, int e) {
    __syncthreads();
    if (ct == 0) {
        if (threadIdx.x > 0 && threadIdx.x < 32) {
            while (g_gflags[grp][threadIdx.x] < e) { }
        }
        __syncthreads();
        if (threadIdx.x == 0) {
            __threadfence();
            g_gepoch[grp] = e;
        }
    } else {
        if (threadIdx.x == 0) {
            __threadfence();
            g_gflags[grp][ct] = e;
            while (g_gepoch[grp] < e) { }
            __threadfence();
        }
    }
    __syncthreads();
}

// ---------------- pack ----------------
__global__ void k_pack(const float* __restrict__ bu1, const float* __restrict__ br1,
                       const float* __restrict__ bu0, const float* __restrict__ br0,
                       const float* __restrict__ bc0) {
    int i = blockIdx.x * blockDim.x + threadIdx.x;
    if (i < 128) { g_gflags[i >> 5][i & 31] = 0; if ((i & 31) == 0) g_gepoch[i >> 5] = 0; }
    if (i < 1024) g_bur1[i] = (i < 512) ? bu1[i] : br1[i - 512];
    if (i < 1536) g_bx0[i] = (i < 512) ? bu0[i] : (i < 1024) ? br0[i - 512] : bc0[i - 1024];
}

// ---------------- weight split + transpose for recurrence ----------------
__global__ void __launch_bounds__(256) k_cvtW(
    const float* __restrict__ Wu0, const float* __restrict__ Wr0,
    const float* __restrict__ Wc0, const float* __restrict__ Wu1,
    const float* __restrict__ Wr1, const float* __restrict__ Wc1)
{
    __shared__ float f[32][33];
    const int ph = blockIdx.z;
    const int NN = (ph == 0 || ph == 2) ? 1024 : 512;
    const int KK = (ph >= 2) ? 1024 : 512;
    if ((int)blockIdx.x * 32 >= NN || (int)blockIdx.y * 32 >= KK) return;
    const int tid = threadIdx.x, tr = tid >> 5, tc = tid & 31;
    __nv_bfloat16* Wh = (ph == 0) ? g_W0h : (ph == 1) ? g_W1h : (ph == 2) ? g_W2h : g_W3h;
    __nv_bfloat16* Wl = (ph == 0) ? g_W0l : (ph == 1) ? g_W1l : (ph == 2) ? g_W2l : g_W3l;
#pragma unroll
    for (int i = 0; i < 4; i++) {
        int kk = blockIdx.y * 32 + tr + i * 8;
        int n  = blockIdx.x * 32 + tc;
        float v;
        if (ph == 0)      v = (n < 512) ? Wu0[(IN0 + kk) * HH + n] : Wr0[(IN0 + kk) * HH + (n - 512)];
        else if (ph == 1) v = Wc0[kk * HH + n];
        else if (ph == 2) v = (n < 512) ? Wu1[kk * HH + n] : Wr1[kk * HH + (n - 512)];
        else              v = Wc1[kk * HH + n];
        f[tr + i * 8][tc] = v;
    }
    __syncthreads();
#pragma unroll
    for (int i = 0; i < 4; i++) {
        int n  = blockIdx.x * 32 + tr + i * 8;
        int kk = blockIdx.y * 32 + tc;
        float wv = f[tc][tr + i * 8];
        __nv_bfloat16 bh = __float2bfloat16(wv);
        __nv_bfloat16 bl = __float2bfloat16(wv - __bfloat162float(bh));
        Wh[(size_t)n * KK + kk] = bh;
        Wl[(size_t)n * KK + kk] = bl;
    }
}

// ---------------- precompute weight split + transpose (x-parts) ----------------
__global__ void __launch_bounds__(256) k_cvtBx(
    const float* __restrict__ Wu0, const float* __restrict__ Wr0,
    const float* __restrict__ Wc0)
{
    __shared__ float f[32][33];
    const int ntile = blockIdx.x;
    const int ktile = blockIdx.y;
    const int tid = threadIdx.x;
    const int tr = tid >> 5, tc = tid & 31;
#pragma unroll
    for (int i = 0; i < 4; i++) {
        int kk = ktile * 32 + tr + i * 8;
        int n  = ntile * 32 + tc;
        float v;
        if (n < 512)       v = Wu0[kk * HH + n];
        else if (n < 1024) v = Wr0[kk * HH + (n - 512)];
        else               v = Wc0[(512 + kk) * HH + (n - 1024)];
        f[tr + i * 8][tc] = v;
    }
    __syncthreads();
#pragma unroll
    for (int i = 0; i < 4; i++) {
        int n  = ntile * 32 + tr + i * 8;
        int kk = ktile * 32 + tc;
        float wv = f[tc][tr + i * 8];
        __nv_bfloat16 bh = __float2bfloat16(wv);
        __nv_bfloat16 bl = __float2bfloat16(wv - __bfloat162float(bh));
        __nv_bfloat16* dst = g_B2x + (size_t)n * KEFF2;
        dst[kk]         = bh;
        dst[1024 + kk]  = bl;
        dst[2048 + kk]  = bh;
    }
}

// ---------------- precompute A gather + split ----------------
__global__ void __launch_bounds__(256) k_cvtAx(const int* __restrict__ tokens,
                                               const float* __restrict__ emb) {
    const int m = blockIdx.x;
    const int b = m & 127, t = m >> 7;
    const int tok = tokens[b * TT + t];
    const int tid = threadIdx.x;
    __nv_bfloat16* dst = g_A2x + (size_t)m * KEFF2;
#pragma unroll
    for (int i = 0; i < 4; i++) {
        int k = tid + i * 256;
        float a = (k < 512) ? emb[(size_t)tok * EE + k] : g_p[b * MAPS + (k - 512)];
        __nv_bfloat16 ah = __float2bfloat16(a);
        __nv_bfloat16 al = __float2bfloat16(a - __bfloat162float(ah));
        dst[k]         = ah;
        dst[1024 + k]  = ah;
        dst[2048 + k]  = al;
    }
}

// ---------------- input layer GEMM ----------------
template <int K, typename Op>
__global__ void __launch_bounds__(256) small_gemm(Op op) {
    __shared__ float As[32][33];
    __shared__ float Bs[32][33];
    const int tid = threadIdx.x;
    const int r0 = tid >> 4;
    const int c0 = tid & 15;
    const int mBase = blockIdx.y * 32;
    const int nBase = blockIdx.x * 32;

    float a00 = 0.f, a01 = 0.f, a10 = 0.f, a11 = 0.f;

    for (int k0 = 0; k0 < K; k0 += 32) {
#pragma unroll
        for (int i = 0; i < 4; i++) {
            int e = tid + i * 256;
            int r = e >> 5, kk = e & 31;
            As[r][kk] = op.loadA(mBase + r, k0 + kk);
        }
#pragma unroll
        for (int i = 0; i < 4; i++) {
            int e = tid + i * 256;
            int kk = e >> 5, n = e & 31;
            Bs[kk][n] = op.loadB(k0 + kk, nBase + n);
        }
        __syncthreads();
#pragma unroll
        for (int kk = 0; kk < 32; kk++) {
            float x0 = As[r0][kk],      x1 = As[r0 + 16][kk];
            float y0 = Bs[kk][c0],      y1 = Bs[kk][c0 + 16];
            a00 += x0 * y0; a01 += x0 * y1;
            a10 += x1 * y0; a11 += x1 * y1;
        }
        __syncthreads();
    }
    op.store(mBase + r0,      nBase + c0,      a00);
    op.store(mBase + r0,      nBase + c0 + 16, a01);
    op.store(mBase + r0 + 16, nBase + c0,      a10);
    op.store(mBase + r0 + 16, nBase + c0 + 16, a11);
}

struct OpP {
    const float* A; const float* Bw; const float* bias;
    __device__ float loadA(int r, int k) const { return A[r * NFE + k]; }
    __device__ float loadB(int k, int n) const { return Bw[k * MAPS + n]; }
    __device__ void store(int r, int n, float acc) const {
        float v = acc + bias[n];
        g_p[r * MAPS + n] = v > 0.f ? v : 0.01f * v;
    }
};

// ---------------- persistent recurrence via HMMA, K-chunk 128 ----------------
// Block (grp, ct): rows grp*32..+31, cols ct*COLS..+COLS-1 of phase output.
template <int PH, int COLS, int KTOT>
__device__ __forceinline__ void run_phase_mma(
    __nv_bfloat16 (*sAh)[136], __nv_bfloat16 (*sAl)[136],
    __nv_bfloat16 (*sBh)[136], __nv_bfloat16 (*sBl)[136],
    float (*red)[32][4],
    int t, int grp, int ct,
    const float* h0c, float* h0n, const float* h1c, float* h1n,
    const __nv_bfloat16* __restrict__ Wh, const __nv_bfloat16* __restrict__ Wl,
    const float* __restrict__ bc1)
{
    const int tid = threadIdx.x;
    const int w = tid >> 5, lane = tid & 31;
    constexpr int F  = COLS / 4;            // frag slots: 8 or 4
    constexpr int KW = 16 / F;              // k-parities: 2 or 4
    constexpr int CH = KTOT / 128;          // chunks: 4 or 8
    const int slot = w & (F - 1);
    const int par  = w / F;
    const int mf = (COLS == 32) ? (slot >> 2) : (slot >> 1);
    const int nf = (COLS == 32) ? (slot & 3) : (slot & 1);
    const int R0 = grp * 32;
    const int cb = ct * COLS;

    // A staging: thread -> (row arow, 8 k-floats at ak)
    const int arow = tid >> 4;
    const int ak   = (tid & 15) << 3;
    // B staging: uint4 units (8 bf16); per half COLS*16 uint4
    bool bhAct, blAct; int bn, bsg;
    if (COLS == 32) {
        bhAct = true; blAct = true; bn = tid >> 4; bsg = tid & 15;
    } else {
        bhAct = tid < 256; blAct = !bhAct;
        int q = bhAct ? tid : tid - 256; bn = q >> 4; bsg = q & 15;
    }

    float acc[4] = {0.f, 0.f, 0.f, 0.f};

    auto loadA4 = [&](int ka) -> float4 {
        int rr = R0 + arow;
        if (PH == 0) {
            return ldcg4(h0c + rr * HH + ka);
        } else if (PH == 1) {
            float4 u = ldcg4(g_ur0 + rr * 1024 + 512 + ka);
            float4 h = ldcg4(h0c + rr * HH + ka);
            return make_float4(u.x * h.x, u.y * h.y, u.z * h.z, u.w * h.w);
        } else if (PH == 2) {
            return (ka < 512) ? ldcg4(h0n + rr * HH + ka)
                              : ldcg4(h1c + rr * HH + (ka - 512));
        } else {
            if (ka < 512) {
                float4 u = ldcg4(g_ur1 + rr * 1024 + 512 + ka);
                float4 h = ldcg4(h1c + rr * HH + ka);
                return make_float4(u.x * h.x, u.y * h.y, u.z * h.z, u.w * h.w);
            }
            return ldcg4(h0n + rr * HH + (ka - 512));
        }
    };

    float4 va0 = loadA4(ak), va1 = loadA4(ak + 4);
    uint4 vbh, vbl;
    if (bhAct) vbh = *reinterpret_cast<const uint4*>(Wh + (size_t)(cb + bn) * KTOT + bsg * 8);
    if (blAct) vbl = *reinterpret_cast<const uint4*>(Wl + (size_t)(cb + bn) * KTOT + bsg * 8);

    const unsigned baseAh = smem_u32(sAh), baseAl = smem_u32(sAl);
    const unsigned baseBh = smem_u32(sBh), baseBl = smem_u32(sBl);

    for (int c = 0; c < CH; c++) {
        {
            uint2 h0p, l0p, h1p, l1p;
            split4(va0, h0p, l0p);
            split4(va1, h1p, l1p);
            *reinterpret_cast<uint2*>(&sAh[arow][ak])     = h0p;
            *reinterpret_cast<uint2*>(&sAl[arow][ak])     = l0p;
            *reinterpret_cast<uint2*>(&sAh[arow][ak + 4]) = h1p;
            *reinterpret_cast<uint2*>(&sAl[arow][ak + 4]) = l1p;
        }
        if (bhAct) *reinterpret_cast<uint4*>(&sBh[bn][bsg * 8]) = vbh;
        if (blAct) *reinterpret_cast<uint4*>(&sBl[bn][bsg * 8]) = vbl;
        __syncthreads();

        if (c + 1 < CH) {
            va0 = loadA4((c + 1) * 128 + ak);
            va1 = loadA4((c + 1) * 128 + ak + 4);
            if (bhAct) vbh = *reinterpret_cast<const uint4*>(Wh + (size_t)(cb + bn) * KTOT + (c + 1) * 128 + bsg * 8);
            if (blAct) vbl = *reinterpret_cast<const uint4*>(Wl + (size_t)(cb + bn) * KTOT + (c + 1) * 128 + bsg * 8);
        }

#pragma unroll
        for (int si = 0; si < 8 / KW; si++) {
            int s = par + si * KW;
            unsigned ah[4], al[4], bh[2], bl[2];
            unsigned aoff = (mf * 16 + (lane & 15)) * 272 + s * 32 + (lane >> 4) * 16;
            ldmx4(ah, baseAh + aoff);
            ldmx4(al, baseAl + aoff);
            unsigned boff = (nf * 8 + (lane & 7)) * 272 + s * 32 + ((lane >> 3) & 1) * 16;
            ldmx2(bh, baseBh + boff);
            ldmx2(bl, baseBl + boff);
            mma16816(acc, ah, bh);
            mma16816(acc, ah, bl);
            mma16816(acc, al, bh);
        }
        __syncthreads();
    }

    // cross-parity reduction
    if (par > 0) {
        float* d = red[(par - 1) * F + slot][lane];
        d[0] = acc[0]; d[1] = acc[1]; d[2] = acc[2]; d[3] = acc[3];
    }
    __syncthreads();
    if (par == 0) {
#pragma unroll
        for (int p = 1; p < KW; p++) {
            float* s = red[(p - 1) * F + slot][lane];
            acc[0] += s[0]; acc[1] += s[1]; acc[2] += s[2]; acc[3] += s[3];
        }
        const int gID = lane >> 2, tig = lane & 3;
#pragma unroll
        for (int half = 0; half < 2; half++) {
            int R   = R0 + mf * 16 + gID + half * 8;
            int cgl = cb + nf * 8 + tig * 2;
            float v0 = acc[half * 2], v1 = acc[half * 2 + 1];
            if (PH == 0) {
                const float* x = g_X0 + (t * BB + R) * 1536 + cgl;
                float2 o = make_float2(sigmoidf(v0 + x[0]), sigmoidf(v1 + x[1]));
                *reinterpret_cast<float2*>(g_ur0 + R * 1024 + cgl) = o;
            } else if (PH == 1) {
                const float* x = g_X0 + (t * BB + R) * 1536 + 1024 + cgl;
                float u0 = __ldcg(g_ur0 + R * 1024 + cgl);
                float u1 = __ldcg(g_ur0 + R * 1024 + cgl + 1);
                float p0 = __ldcg(h0c + R * HH + cgl);
                float p1 = __ldcg(h0c + R * HH + cgl + 1);
                float2 o = make_float2(u0 * p0 + (1.f - u0) * tanhf(v0 + x[0]),
                                       u1 * p1 + (1.f - u1) * tanhf(v1 + x[1]));
                *reinterpret_cast<float2*>(h0n + R * HH + cgl) = o;
            } else if (PH == 2) {
                float2 o = make_float2(sigmoidf(v0 + g_bur1[cgl]),
                                       sigmoidf(v1 + g_bur1[cgl + 1]));
                *reinterpret_cast<float2*>(g_ur1 + R * 1024 + cgl) = o;
            } else {
                float u0 = __ldcg(g_ur1 + R * 1024 + cgl);
                float u1 = __ldcg(g_ur1 + R * 1024 + cgl + 1);
                float p0 = __ldcg(h1c + R * HH + cgl);
                float p1 = __ldcg(h1c + R * HH + cgl + 1);
                float2 o = make_float2(u0 * p0 + (1.f - u0) * tanhf(v0 + bc1[cgl]),
                                       u1 * p1 + (1.f - u1) * tanhf(v1 + bc1[cgl + 1]));
                *reinterpret_cast<float2*>(h1n + R * HH + cgl) = o;
                // fused logits-A split write: A2[m] = [Ah | Ah | Al]
                unsigned b0 = __float_as_uint(o.x), b1 = __float_as_uint(o.y);
                unsigned ahp = __byte_perm(b0, b1, 0x7632);
                float l0 = o.x - __uint_as_float(b0 & 0xFFFF0000u);
                float l1 = o.y - __uint_as_float(b1 & 0xFFFF0000u);
                unsigned alp;
                asm("cvt.rn.bf16x2.f32 %0, %1, %2;" : "=r"(alp) : "f"(l1), "f"(l0));
                __nv_bfloat16* dst = g_A2 + (size_t)(t * BB + R) * KEFF + cgl;
                *reinterpret_cast<unsigned*>(dst)        = ahp;
                *reinterpret_cast<unsigned*>(dst + 512)  = ahp;
                *reinterpret_cast<unsigned*>(dst + 1024) = alp;
            }
        }
    }
}

__global__ void __launch_bounds__(512, 1) k_recurrence(const float* __restrict__ bc1) {
    __shared__ __align__(16) __nv_bfloat16 sAh[32][136];
    __shared__ __align__(16) __nv_bfloat16 sAl[32][136];
    __shared__ __align__(16) __nv_bfloat16 sBh[32][136];
    __shared__ __align__(16) __nv_bfloat16 sBl[32][136];
    __shared__ float red[12][32][4];
    const int tid = threadIdx.x, blk = blockIdx.x;
    const int grp = blk >> 5, ct = blk & 31;
    int ep = 0;

    {
        int off = grp * 16384 + ct * 512 + tid;
        g_h0[0][off] = 0.f;
        g_h1[0][off] = 0.f;
    }
    gbarg(grp, ct, ++ep);

    for (int t = 0; t < TT; t++) {
        const int cur = t & 1;
        const float* h0c = g_h0[cur];
        float*       h0n = g_h0[cur ^ 1];
        const float* h1c = g_h1[cur];
        float*       h1n = g_h1[cur ^ 1];

        run_phase_mma<0, 32,  512>(sAh, sAl, sBh, sBl, red, t, grp, ct,
                                   h0c, h0n, h1c, h1n, g_W0h, g_W0l, bc1);
        gbarg(grp, ct, ++ep);
        run_phase_mma<1, 16,  512>(sAh, sAl, sBh, sBl, red, t, grp, ct,
                                   h0c, h0n, h1c, h1n, g_W1h, g_W1l, bc1);
        gbarg(grp, ct, ++ep);
        run_phase_mma<2, 32, 1024>(sAh, sAl, sBh, sBl, red, t, grp, ct,
                                   h0c, h0n, h1c, h1n, g_W2h, g_W2l, bc1);
        gbarg(grp, ct, ++ep);
        run_phase_mma<3, 16, 1024>(sAh, sAl, sBh, sBl, red, t, grp, ct,
                                   h0c, h0n, h1c, h1n, g_W3h, g_W3l, bc1);
        // NO barrier after PH3: h1' first read at PH2(t+1), behind 2 later barriers;
        // g_ur0 WAR from PH0(t+1) covered by post-PH1/post-PH2(t).
    }
}

// ---------------- bf16 split prep for logits B ----------------
__global__ void __launch_bounds__(256) k_cvtB(const float* __restrict__ Wout) {
    __shared__ float f[32][33];
    const int ntile = blockIdx.x;
    const int ktile = blockIdx.y;
    const int tid = threadIdx.x;
    const int tr = tid >> 5, tc = tid & 31;
#pragma unroll
    for (int i = 0; i < 4; i++) {
        int kk = ktile * 32 + tr + i * 8;
        int n = ntile * 32 + tc;
        f[tr + i * 8][tc] = (n < VV) ? Wout[kk * VV + n] : 0.f;
    }
    __syncthreads();
#pragma unroll
    for (int i = 0; i < 4; i++) {
        int n = ntile * 32 + tr + i * 8;
        int kk = ktile * 32 + tc;
        float w = f[tc][tr + i * 8];
        __nv_bfloat16 bh = __float2bfloat16(w);
        __nv_bfloat16 bl = __float2bfloat16(w - __bfloat162float(bh));
        __nv_bfloat16* dst = g_B2 + (size_t)n * KEFF;
        dst[kk]        = bh;
        dst[512 + kk]  = bl;
        dst[1024 + kk] = bh;
    }
}

// ---------------- generic HMMA GEMM core (CTA 128x128, double-buffered) ----------------
template <int KEFFT, int KCMT, bool LOGITS>
__device__ __forceinline__ void hmma_gemm_body(
    const __nv_bfloat16* __restrict__ gA, const __nv_bfloat16* __restrict__ gB,
    const float* __restrict__ bias, float* __restrict__ out, int nt, int mt,
    __nv_bfloat16 (*sA)[128 * 40], __nv_bfloat16 (*sB)[128 * 40])
{
    const int tid = threadIdx.x;
    const int warp = tid >> 5, lane = tid & 31;
    const int wm = warp >> 2, wn = warp & 3;

    float acc[4][4][4];
#pragma unroll
    for (int a = 0; a < 4; a++)
#pragma unroll
        for (int b = 0; b < 4; b++)
#pragma unroll
            for (int c = 0; c < 4; c++) acc[a][b][c] = 0.f;

    uint4 pa[2], pb[2];
#pragma unroll
    for (int i = 0; i < 2; i++) {
        int s = tid + i * 256, r = s >> 2, sg = s & 3;
        pa[i] = *reinterpret_cast<const uint4*>(gA + (size_t)r * KEFFT + sg * 8);
        pb[i] = *reinterpret_cast<const uint4*>(gB + (size_t)r * KEFFT + sg * 8);
    }

    for (int kc = 0; kc < KCMT; kc++) {
        int buf = kc & 1;
#pragma unroll
        for (int i = 0; i < 2; i++) {
            int s = tid + i * 256, r = s >> 2, sg = s & 3;
            *reinterpret_cast<uint4*>(&sA[buf][r * 40 + sg * 8]) = pa[i];
            *reinterpret_cast<uint4*>(&sB[buf][r * 40 + sg * 8]) = pb[i];
        }
        __syncthreads();

        if (kc + 1 < KCMT) {
            int k0 = (kc + 1) * 32;
#pragma unroll
            for (int i = 0; i < 2; i++) {
                int s = tid + i * 256, r = s >> 2, sg = s & 3;
                pa[i] = *reinterpret_cast<const uint4*>(gA + (size_t)r * KEFFT + k0 + sg * 8);
                pb[i] = *reinterpret_cast<const uint4*>(gB + (size_t)r * KEFFT + k0 + sg * 8);
            }
        }

        unsigned sAb = smem_u32(sA[buf]);
        unsigned sBb = smem_u32(sB[buf]);
#pragma unroll
        for (int kf = 0; kf < 2; kf++) {
            unsigned a[4][4], b[4][2];
#pragma unroll
            for (int mf = 0; mf < 4; mf++) {
                int r = wm * 64 + mf * 16 + (lane & 15);
                ldmx4(a[mf], sAb + r * 80 + kf * 32 + (lane >> 4) * 16);
            }
#pragma unroll
            for (int nf = 0; nf < 4; nf++) {
                int n = wn * 32 + nf * 8 + (lane & 7);
                ldmx2(b[nf], sBb + n * 80 + kf * 32 + ((lane >> 3) & 1) * 16);
            }
#pragma unroll
            for (int mf = 0; mf < 4; mf++)
#pragma unroll
                for (int nf = 0; nf < 4; nf++)
                    mma16816(acc[mf][nf], a[mf], b[nf]);
        }
        __syncthreads();
    }

    const int gID = lane >> 2, tig = lane & 3;
#pragma unroll
    for (int mf = 0; mf < 4; mf++) {
#pragma unroll
        for (int half = 0; half < 2; half++) {
            int gm = mt * 128 + wm * 64 + mf * 16 + gID + half * 8;
            float* orow;
            if (LOGITS) {
                int tt = gm >> 7, bb = gm & 127;
                orow = out + ((size_t)bb * TT + tt) * VV;
            } else {
                orow = out + (size_t)gm * 1536;
            }
#pragma unroll
            for (int nf = 0; nf < 4; nf++) {
                int n = nt * 128 + wn * 32 + nf * 8 + tig * 2;
                float v0 = acc[mf][nf][half * 2 + 0];
                float v1 = acc[mf][nf][half * 2 + 1];
                if (LOGITS) {
                    if (n + 1 < VV) {
                        float2 o = make_float2(v0 + bias[n], v1 + bias[n + 1]);
                        *reinterpret_cast<float2*>(orow + n) = o;
                    } else if (n < VV) {
                        orow[n] = v0 + bias[n];
                    }
                } else {
                    float2 o = make_float2(v0 + bias[n], v1 + bias[n + 1]);
                    *reinterpret_cast<float2*>(orow + n) = o;
                }
            }
        }
    }
}

__global__ void __launch_bounds__(256) k_logits_mma(const float* __restrict__ bout,
                                                    float* __restrict__ out)
{
    __shared__ __align__(16) __nv_bfloat16 sA[2][128 * 40];
    __shared__ __align__(16) __nv_bfloat16 sB[2][128 * 40];
    const int nt = blockIdx.x, mt = blockIdx.y;
    hmma_gemm_body<KEFF, KCM, true>(
        g_A2 + (size_t)(mt * 128) * KEFF, g_B2 + (size_t)(nt * 128) * KEFF,
        bout, out, nt, mt, sA, sB);
}

__global__ void __launch_bounds__(256) k_precompute_mma(float* __restrict__ dummy)
{
    __shared__ __align__(16) __nv_bfloat16 sA[2][128 * 40];
    __shared__ __align__(16) __nv_bfloat16 sB[2][128 * 40];
    const int nt = blockIdx.x, mt = blockIdx.y;
    hmma_gemm_body<KEFF2, KCM2, false>(
        g_A2x + (size_t)(mt * 128) * KEFF2, g_B2x + (size_t)(nt * 128) * KEFF2,
        g_bx0, g_X0, nt, mt, sA, sB);
}

__global__ void k_hidden(float* __restrict__ outh) {
    int i = blockIdx.x * blockDim.x + threadIdx.x;
    if (i < BB * HH) {
        outh[i]           = g_h0[1][i];
        outh[BB * HH + i] = g_h1[1][i];
    }
}

// ---------------- launch ----------------
extern "C" void kernel_launch(void* const* d_in, const int* in_sizes, int n_in,
                              void* d_out, int out_size) {
    const int*   tokens = (const int*)d_in[0];     // int32 (JAX x64 disabled)
    const float* cnn  = (const float*)d_in[1];
    const float* emb  = (const float*)d_in[2];
    const float* Win  = (const float*)d_in[3];
    const float* bin  = (const float*)d_in[4];
    const float* Wout = (const float*)d_in[5];
    const float* bout = (const float*)d_in[6];
    const float* Wu0  = (const float*)d_in[7];
    const float* bu0  = (const float*)d_in[8];
    const float* Wr0  = (const float*)d_in[9];
    const float* br0  = (const float*)d_in[10];
    const float* Wc0  = (const float*)d_in[11];
    const float* bc0  = (const float*)d_in[12];
    const float* Wu1  = (const float*)d_in[13];
    const float* bu1  = (const float*)d_in[14];
    const float* Wr1  = (const float*)d_in[15];
    const float* br1  = (const float*)d_in[16];
    const float* Wc1  = (const float*)d_in[17];
    const float* bc1  = (const float*)d_in[18];
    float* out = (float*)d_out;

    k_pack<<<8, 256>>>(bu1, br1, bu0, br0, bc0);

    // one-time weight splits
    k_cvtW<<<dim3(32, 32, 4), 256>>>(Wu0, Wr0, Wc0, Wu1, Wr1, Wc1);
    k_cvtBx<<<dim3(48, 32), 256>>>(Wu0, Wr0, Wc0);
    k_cvtB<<<dim3(NPAD / 32, 512 / 32), 256>>>(Wout);

    // input layer: p = leaky_relu(cnn @ Win + bin)
    small_gemm<NFE, OpP><<<dim3(MAPS / 32, BB / 32), 256>>>(OpP{cnn, Win, bin});

    // precompute X0 via HMMA
    k_cvtAx<<<TT * BB, 256>>>(tokens, emb);
    k_precompute_mma<<<dim3(1536 / 128, (TT * BB) / 128), 256>>>(nullptr);

    // 25-step recurrence (HMMA persistent; writes logits A2 directly)
    k_recurrence<<<NBLK, 512>>>(bc1);

    // HMMA logits
    k_logits_mma<<<dim3(NPAD / 128, (TT * BB) / 128), 256>>>(bout, out);

    k_hidden<<<(BB * HH + 255) / 256, 256>>>(out + (size_t)BB * TT * VV);
}